// round 5
// baseline (speedup 1.0000x reference)
#include <cuda_runtime.h>
#include <cuda_fp16.h>
#include <math.h>
#include <stdint.h>

#define B_  32
#define N_  512
#define DIN 768
#define DOUT 256
#define H_  8
#define M_  (B_ * N_)

// ---------------- device scratch ----------------
__device__ __half g_xh [(size_t)M_ * DIN];
__device__ __half g_xl [(size_t)M_ * DIN];
__device__ __half g_w0h[(size_t)H_ * DOUT * DIN];  // [h][n][k]
__device__ __half g_w0l[(size_t)H_ * DOUT * DIN];
__device__ __half g_Whh[(size_t)H_ * M_ * DOUT];
__device__ __half g_Whl[(size_t)H_ * M_ * DOUT];
__device__ float  g_f1 [H_ * M_];
__device__ float  g_eu [H_ * M_];   // exp(f2)
__device__ float  g_ev [H_ * M_];   // exp(0.2 f2)
__device__ __half g_Ph [(size_t)H_ * B_ * N_ * N_];   // P hi (134MB)
__device__ __half g_Pl [(size_t)H_ * B_ * N_ * N_];   // P lo (134MB)
__device__ __half g_hmh[(size_t)M_ * DOUT];
__device__ __half g_hml[(size_t)M_ * DOUT];
__device__ __half g_woh[(size_t)DOUT * DOUT];
__device__ __half g_wol[(size_t)DOUT * DOUT];
__device__ __half g_W2h[(size_t)M_ * DOUT];
__device__ __half g_W2l[(size_t)M_ * DOUT];
__device__ float  g_f1b[M_];
__device__ float  g_eub[M_];
__device__ float  g_evb[M_];
__device__ __half g_P2h[(size_t)B_ * N_ * N_];
__device__ __half g_P2l[(size_t)B_ * N_ * N_];

// ---------------- PTX helpers ----------------
__device__ __forceinline__ uint32_t smem_u32(const void* p) {
    uint32_t a;
    asm("{ .reg .u64 t; cvta.to.shared.u64 t, %1; cvt.u32.u64 %0, t; }" : "=r"(a) : "l"(p));
    return a;
}
__device__ __forceinline__ void cp16(uint32_t d, const void* s) {
    asm volatile("cp.async.cg.shared.global [%0], [%1], 16;" :: "r"(d), "l"(s));
}
#define CP_COMMIT() asm volatile("cp.async.commit_group;")
#define CP_WAIT(n)  asm volatile("cp.async.wait_group %0;" :: "n"(n))

#define LDM_X4(r, addr) \
    asm volatile("ldmatrix.sync.aligned.m8n8.x4.shared.b16 {%0,%1,%2,%3}, [%4];" \
        : "=r"((r)[0]), "=r"((r)[1]), "=r"((r)[2]), "=r"((r)[3]) : "r"(addr))
#define LDM_X2(r, addr) \
    asm volatile("ldmatrix.sync.aligned.m8n8.x2.shared.b16 {%0,%1}, [%2];" \
        : "=r"((r)[0]), "=r"((r)[1]) : "r"(addr))
#define LDM_X2T(r, addr) \
    asm volatile("ldmatrix.sync.aligned.m8n8.x2.trans.shared.b16 {%0,%1}, [%2];" \
        : "=r"((r)[0]), "=r"((r)[1]) : "r"(addr))

__device__ __forceinline__ void mma_f16(float* c, const uint32_t* a, const uint32_t* b) {
    asm volatile("mma.sync.aligned.m16n8k16.row.col.f32.f16.f16.f32 "
        "{%0,%1,%2,%3}, {%4,%5,%6,%7}, {%8,%9}, {%0,%1,%2,%3};"
        : "+f"(c[0]), "+f"(c[1]), "+f"(c[2]), "+f"(c[3])
        : "r"(a[0]), "r"(a[1]), "r"(a[2]), "r"(a[3]), "r"(b[0]), "r"(b[1]));
}

// ---------------- conversion kernels ----------------
__global__ __launch_bounds__(256) void split_kernel(
    const float* __restrict__ src, __half* __restrict__ hi,
    __half* __restrict__ lo, int n4)
{
    int i = blockIdx.x * 256 + threadIdx.x;
    if (i >= n4) return;
    float4 v = ((const float4*)src)[i];
    __half h0 = __float2half(v.x), h1 = __float2half(v.y);
    __half h2 = __float2half(v.z), h3 = __float2half(v.w);
    ((__half2*)hi)[2 * i]     = __halves2half2(h0, h1);
    ((__half2*)hi)[2 * i + 1] = __halves2half2(h2, h3);
    ((__half2*)lo)[2 * i]     = __halves2half2(
        __float2half(v.x - __half2float(h0)), __float2half(v.y - __half2float(h1)));
    ((__half2*)lo)[2 * i + 1] = __halves2half2(
        __float2half(v.z - __half2float(h2)), __float2half(v.w - __half2float(h3)));
}

__global__ __launch_bounds__(256) void wsplit_kernel(
    const float* __restrict__ W, __half* __restrict__ bh,
    __half* __restrict__ bl, int Kd, int Nd)
{
    int z = blockIdx.z;
    int i = blockIdx.x * 256 + threadIdx.x;
    if (i >= Kd * Nd) return;
    int n = i / Kd, k = i % Kd;
    float v = W[(size_t)z * Kd * Nd + (size_t)k * Nd + n];
    __half h = __float2half(v);
    bh[(size_t)z * Kd * Nd + i] = h;
    bl[(size_t)z * Kd * Nd + i] = __float2half(v - __half2float(h));
}

// ================= HMMA split GEMM =================
#define GEMM_SMEM (2 * 40960)

__global__ __launch_bounds__(256, 1) void gemm_mma_kernel(
    const __half* __restrict__ Ah, const __half* __restrict__ Al,
    const __half* __restrict__ Bh, const __half* __restrict__ Bl,
    __half* __restrict__ Chh, __half* __restrict__ Chl, int K, int Nt)
{
    extern __shared__ __align__(128) char sm[];
    const uint32_t sb = smem_u32(sm);
    const int t = threadIdx.x, lane = t & 31, wid = t >> 5;
    const int m0 = blockIdx.x * 128, f0 = blockIdx.y * 128, z = blockIdx.z;
    const int warp_m = wid & 1, warp_n = wid >> 1;

    const __half* As_h = Ah + (size_t)m0 * K;
    const __half* As_l = Al + (size_t)m0 * K;
    const __half* Bs_h = Bh + (size_t)z * Nt * K + (size_t)f0 * K;
    const __half* Bs_l = Bl + (size_t)z * Nt * K + (size_t)f0 * K;
    __half* Ch = Chh + (size_t)z * M_ * Nt;
    __half* Cl = Chl + (size_t)z * M_ * Nt;

    float acc[4][4][4];
    #pragma unroll
    for (int a = 0; a < 4; ++a)
        #pragma unroll
        for (int b = 0; b < 4; ++b)
            #pragma unroll
            for (int c = 0; c < 4; ++c) acc[a][b][c] = 0.0f;

    const int row = t >> 1, half = t & 1;
    auto prefetch = [&](int c, int s) {
        const int kc = c * 32;
        const __half* srcs[4] = { As_h + kc, As_l + kc, Bs_h + kc, Bs_l + kc };
        #pragma unroll
        for (int tile = 0; tile < 4; ++tile) {
            uint32_t dst = sb + s * 40960 + tile * 10240 + row * 80 + half * 32;
            const __half* src = srcs[tile] + (size_t)row * K + half * 16;
            cp16(dst, src);
            cp16(dst + 16, src + 8);
        }
        CP_COMMIT();
    };

    const int NC = K >> 5;
    prefetch(0, 0);
    for (int c = 0; c < NC; ++c) {
        const int s = c & 1;
        if (c + 1 < NC) { prefetch(c + 1, s ^ 1); CP_WAIT(1); }
        else CP_WAIT(0);
        __syncthreads();

        const uint32_t bAh = sb + s * 40960;
        const uint32_t bAl = bAh + 10240;
        const uint32_t bBh = bAh + 20480;
        const uint32_t bBl = bAh + 30720;
        #pragma unroll
        for (int k16 = 0; k16 < 2; ++k16) {
            const int kc = k16 * 16;
            uint32_t ah[4][4], al[4][4];
            #pragma unroll
            for (int mf = 0; mf < 4; ++mf) {
                uint32_t off = (uint32_t)((warp_m * 64 + mf * 16 + (lane & 15)) * 80
                                          + (kc + ((lane >> 4) << 3)) * 2);
                LDM_X4(ah[mf], bAh + off);
                LDM_X4(al[mf], bAl + off);
            }
            #pragma unroll
            for (int nf = 0; nf < 4; ++nf) {
                uint32_t boff = (uint32_t)((warp_n * 32 + nf * 8 + (lane & 7)) * 80
                                           + (kc + (((lane >> 3) & 1) << 3)) * 2);
                uint32_t bh[2], bl[2];
                LDM_X2(bh, bBh + boff);
                LDM_X2(bl, bBl + boff);
                #pragma unroll
                for (int mf = 0; mf < 4; ++mf) {
                    mma_f16(acc[mf][nf], ah[mf], bh);
                    mma_f16(acc[mf][nf], ah[mf], bl);
                    mma_f16(acc[mf][nf], al[mf], bh);
                }
            }
        }
        __syncthreads();
    }

    #pragma unroll
    for (int mf = 0; mf < 4; ++mf)
        #pragma unroll
        for (int nf = 0; nf < 4; ++nf) {
            int r0 = m0 + warp_m * 64 + mf * 16 + (lane >> 2);
            int col = f0 + warp_n * 32 + nf * 8 + (lane & 3) * 2;
            #pragma unroll
            for (int hh = 0; hh < 2; ++hh) {
                float c0 = acc[mf][nf][hh * 2], c1 = acc[mf][nf][hh * 2 + 1];
                int r = r0 + hh * 8;
                __half h0 = __float2half(c0), h1 = __float2half(c1);
                *(__half2*)(Ch + (size_t)r * Nt + col) = __halves2half2(h0, h1);
                *(__half2*)(Cl + (size_t)r * Nt + col) = __halves2half2(
                    __float2half(c0 - __half2float(h0)),
                    __float2half(c1 - __half2float(h1)));
            }
        }
}

// ---------------- f1/f2 + factored exponentials ----------------
__global__ __launch_bounds__(256) void f12_kernel(
    const __half* __restrict__ Whh, const __half* __restrict__ Whl,
    const float* __restrict__ a1, const float* __restrict__ a2,
    float* __restrict__ f1, float* __restrict__ eu, float* __restrict__ ev,
    int rows, int Mper)
{
    int warp = (blockIdx.x * blockDim.x + threadIdx.x) >> 5;
    int lane = threadIdx.x & 31;
    if (warp >= rows) return;
    int h = warp / Mper;
    const __half* rh = Whh + (size_t)warp * DOUT;
    const __half* rl = Whl + (size_t)warp * DOUT;
    const float* a1h = a1 + h * DOUT;
    const float* a2h = a2 + h * DOUT;
    float s1 = 0.0f, s2 = 0.0f;
    #pragma unroll
    for (int f = lane; f < DOUT; f += 32) {
        float v = __half2float(rh[f]) + __half2float(rl[f]);
        s1 = fmaf(v, a1h[f], s1);
        s2 = fmaf(v, a2h[f], s2);
    }
    #pragma unroll
    for (int off = 16; off; off >>= 1) {
        s1 += __shfl_xor_sync(0xffffffffu, s1, off);
        s2 += __shfl_xor_sync(0xffffffffu, s2, off);
    }
    if (lane == 0) {
        f1[warp] = s1;
        eu[warp] = __expf(s2);
        ev[warp] = __expf(0.2f * s2);
    }
}

// ---------------- P builder: P = E / sum(E), hi/lo fp16 ----------------
// warp per (b,n) row; loops over heads; adj read once.
__global__ __launch_bounds__(256) void pbuild_kernel(
    const float* __restrict__ f1, const float* __restrict__ eu,
    const float* __restrict__ ev, const int* __restrict__ adj,
    __half* __restrict__ Ph, __half* __restrict__ Pl, int NH)
{
    int warp = (blockIdx.x * blockDim.x + threadIdx.x) >> 5;
    int lane = threadIdx.x & 31;
    if (warp >= B_ * N_) return;
    int b = warp >> 9;
    const int* adjrow = adj + (size_t)warp * N_;

    int am[16];
    #pragma unroll
    for (int q = 0; q < 16; ++q) am[q] = adjrow[q * 32 + lane];

    for (int h = 0; h < NH; ++h) {
        size_t r = (size_t)(h * B_ + b) * N_ + (warp & (N_ - 1));
        float f1v = f1[r];
        float u1 = __expf(f1v), v1 = __expf(0.2f * f1v);
        const float* euh = eu + (size_t)(h * B_ + b) * N_;
        const float* evh = ev + (size_t)(h * B_ + b) * N_;

        float E[16], s = 0.0f;
        #pragma unroll
        for (int q = 0; q < 16; ++q) {
            int m = q * 32 + lane;
            float t  = u1 * euh[m];
            float t2 = v1 * evh[m];
            float Ev = t >= 1.0f ? t : t2;
            Ev = am[q] > 0 ? Ev : 0.0f;
            E[q] = Ev;
            s += Ev;
        }
        #pragma unroll
        for (int off = 16; off; off >>= 1)
            s += __shfl_xor_sync(0xffffffffu, s, off);
        float inv = s > 0.0f ? 1.0f / s : 0.0f;

        __half* ph = Ph + r * N_;
        __half* pl = Pl + r * N_;
        #pragma unroll
        for (int q = 0; q < 16; ++q) {
            int m = q * 32 + lane;
            float p = E[q] * inv;
            __half hp = __float2half(p);
            ph[m] = hp;
            pl[m] = __float2half(p - __half2float(hp));
        }
    }
}

// ================= HMMA attention aggregation (pure GEMM now) =================
// CTA: 64 n x 256 f, 512 threads, 16 warps (2n x 8f). P and Wh via cp.async.
// smem: P [2 st][2 hl][64][40] = 20480 | Wh [2 st][2 hl][32][264] = 67584
#define ATTN_SMEM (20480 + 67584)

template<int NHEADS, bool FINAL>
__global__ __launch_bounds__(512, 1) void attn_mma_kernel(
    const __half* __restrict__ Ph, const __half* __restrict__ Pl,
    const __half* __restrict__ Whh, const __half* __restrict__ Whl,
    __half* __restrict__ outh, __half* __restrict__ outl,
    float* __restrict__ outf)
{
    extern __shared__ __align__(128) char sm[];
    const uint32_t sb = smem_u32(sm);
    const uint32_t smP = sb;
    const uint32_t smW = sb + 20480;

    const int t = threadIdx.x, lane = t & 31, wid = t >> 5;
    const int n0 = blockIdx.x * 64;
    const int b  = blockIdx.y;
    const int warp_n = wid & 1, warp_f = wid >> 1;

    const int hl   = t >> 8;
    const int idx  = t & 255;
    const int prow = idx >> 2, pseg = idx & 3;
    const int wrow = idx >> 3, wseg = idx & 7;

    auto issue = [&](int g, int st) {
        const int hh = g >> 4, m0 = (g & 15) * 32;
        const size_t hb = (size_t)hh * B_ + b;
        // P tile: 64 rows x 32 halves, hi/lo
        {
            const __half* src = (hl ? Pl : Ph)
                + (hb * N_ + n0 + prow) * N_ + m0 + pseg * 8;
            cp16(smP + st * 10240 + hl * 5120 + prow * 80 + pseg * 16, src);
        }
        // Wh tile: 32 rows x 256 halves, hi/lo
        {
            const __half* src = (hl ? Whl : Whh)
                + (hb * N_ + m0 + wrow) * (size_t)DOUT;
            uint32_t dst = smW + st * 33792 + hl * 16896 + wrow * 528;
            #pragma unroll
            for (int j = 0; j < 4; ++j) {
                int s8 = wseg + j * 8;
                cp16(dst + s8 * 16, src + s8 * 8);
            }
        }
        CP_COMMIT();
    };

    float sum[2][4][4];
    #pragma unroll
    for (int a = 0; a < 2; ++a)
        #pragma unroll
        for (int c = 0; c < 4; ++c)
            #pragma unroll
            for (int d = 0; d < 4; ++d) sum[a][c][d] = 0.0f;

    issue(0, 0);
    for (int h = 0; h < NHEADS; ++h) {
        float acc[2][4][4];
        #pragma unroll
        for (int a = 0; a < 2; ++a)
            #pragma unroll
            for (int c = 0; c < 4; ++c)
                #pragma unroll
                for (int d = 0; d < 4; ++d) acc[a][c][d] = 0.0f;

        for (int c = 0; c < 16; ++c) {
            const int g = h * 16 + c;
            const int st = g & 1;
            if (g + 1 < NHEADS * 16) { issue(g + 1, st ^ 1); CP_WAIT(1); }
            else CP_WAIT(0);
            __syncthreads();

            const uint32_t Phs = smP + st * 10240;
            const uint32_t Pls = Phs + 5120;
            const uint32_t Whs = smW + st * 33792;
            const uint32_t Wls = Whs + 16896;
            #pragma unroll
            for (int k16 = 0; k16 < 2; ++k16) {
                const int kc = k16 * 16;
                uint32_t ah[2][4], al[2][4];
                #pragma unroll
                for (int mf = 0; mf < 2; ++mf) {
                    uint32_t off = (uint32_t)((warp_n * 32 + mf * 16 + (lane & 15)) * 80
                                              + (kc + ((lane >> 4) << 3)) * 2);
                    LDM_X4(ah[mf], Phs + off);
                    LDM_X4(al[mf], Pls + off);
                }
                #pragma unroll
                for (int nf = 0; nf < 4; ++nf) {
                    uint32_t woff = (uint32_t)((kc + (lane & 15)) * 528
                                               + (warp_f * 32 + nf * 8) * 2);
                    uint32_t bh[2], bl[2];
                    LDM_X2T(bh, Whs + woff);
                    LDM_X2T(bl, Wls + woff);
                    #pragma unroll
                    for (int mf = 0; mf < 2; ++mf) {
                        mma_f16(acc[mf][nf], ah[mf], bh);
                        mma_f16(acc[mf][nf], ah[mf], bl);
                        mma_f16(acc[mf][nf], al[mf], bh);
                    }
                }
            }
            __syncthreads();
        }

        if (FINAL) {
            #pragma unroll
            for (int a = 0; a < 2; ++a)
                #pragma unroll
                for (int c = 0; c < 4; ++c)
                    #pragma unroll
                    for (int d = 0; d < 4; ++d) sum[a][c][d] = acc[a][c][d];
        } else {
            #pragma unroll
            for (int a = 0; a < 2; ++a)
                #pragma unroll
                for (int c = 0; c < 4; ++c)
                    #pragma unroll
                    for (int d = 0; d < 4; ++d) {
                        float v = acc[a][c][d];
                        sum[a][c][d] += (v > 0.0f) ? v : expm1f(v);
                    }
        }
    }

    #pragma unroll
    for (int mf = 0; mf < 2; ++mf)
        #pragma unroll
        for (int nf = 0; nf < 4; ++nf) {
            int r0  = n0 + warp_n * 32 + mf * 16 + (lane >> 2);
            int col = warp_f * 32 + nf * 8 + (lane & 3) * 2;
            #pragma unroll
            for (int hh2 = 0; hh2 < 2; ++hh2) {
                int r = r0 + hh2 * 8;
                float c0 = sum[mf][nf][hh2 * 2], c1 = sum[mf][nf][hh2 * 2 + 1];
                if (FINAL) {
                    float2 v = { fmaxf(c0, 0.0f), fmaxf(c1, 0.0f) };
                    *(float2*)(outf + ((size_t)b * N_ + r) * DOUT + col) = v;
                } else {
                    c0 *= 0.125f; c1 *= 0.125f;
                    __half h0 = __float2half(c0), h1 = __float2half(c1);
                    *(__half2*)(outh + ((size_t)b * N_ + r) * DOUT + col) =
                        __halves2half2(h0, h1);
                    *(__half2*)(outl + ((size_t)b * N_ + r) * DOUT + col) =
                        __halves2half2(__float2half(c0 - __half2float(h0)),
                                       __float2half(c1 - __half2float(h1)));
                }
            }
        }
}

// ---------------- launch ----------------
extern "C" void kernel_launch(void* const* d_in, const int* in_sizes, int n_in,
                              void* d_out, int out_size)
{
    const float* x    = (const float*)d_in[0];
    const int*   adj  = (const int*)  d_in[1];
    const float* W0   = (const float*)d_in[2];
    const float* a1_0 = (const float*)d_in[3];
    const float* a2_0 = (const float*)d_in[4];
    const float* Wo   = (const float*)d_in[5];
    const float* a1_o = (const float*)d_in[6];
    const float* a2_o = (const float*)d_in[7];
    float* out = (float*)d_out;

    __half *xh, *xl, *w0h, *w0l, *Whh, *Whl, *hmh, *hml, *woh, *wol, *W2h, *W2l;
    __half *Ph, *Pl, *P2h, *P2l;
    float *f1, *eu, *ev, *f1b, *eub, *evb;
    cudaGetSymbolAddress((void**)&xh,  g_xh);
    cudaGetSymbolAddress((void**)&xl,  g_xl);
    cudaGetSymbolAddress((void**)&w0h, g_w0h);
    cudaGetSymbolAddress((void**)&w0l, g_w0l);
    cudaGetSymbolAddress((void**)&Whh, g_Whh);
    cudaGetSymbolAddress((void**)&Whl, g_Whl);
    cudaGetSymbolAddress((void**)&f1,  g_f1);
    cudaGetSymbolAddress((void**)&eu,  g_eu);
    cudaGetSymbolAddress((void**)&ev,  g_ev);
    cudaGetSymbolAddress((void**)&Ph,  g_Ph);
    cudaGetSymbolAddress((void**)&Pl,  g_Pl);
    cudaGetSymbolAddress((void**)&hmh, g_hmh);
    cudaGetSymbolAddress((void**)&hml, g_hml);
    cudaGetSymbolAddress((void**)&woh, g_woh);
    cudaGetSymbolAddress((void**)&wol, g_wol);
    cudaGetSymbolAddress((void**)&W2h, g_W2h);
    cudaGetSymbolAddress((void**)&W2l, g_W2l);
    cudaGetSymbolAddress((void**)&f1b, g_f1b);
    cudaGetSymbolAddress((void**)&eub, g_eub);
    cudaGetSymbolAddress((void**)&evb, g_evb);
    cudaGetSymbolAddress((void**)&P2h, g_P2h);
    cudaGetSymbolAddress((void**)&P2l, g_P2l);

    cudaFuncSetAttribute(gemm_mma_kernel,
        cudaFuncAttributeMaxDynamicSharedMemorySize, GEMM_SMEM);
    cudaFuncSetAttribute(attn_mma_kernel<H_, false>,
        cudaFuncAttributeMaxDynamicSharedMemorySize, ATTN_SMEM);
    cudaFuncSetAttribute(attn_mma_kernel<1, true>,
        cudaFuncAttributeMaxDynamicSharedMemorySize, ATTN_SMEM);

    // ---- layer 1 ----
    split_kernel<<<(M_ * DIN / 4 + 255) / 256, 256>>>(x, xh, xl, M_ * DIN / 4);
    wsplit_kernel<<<dim3((DIN * DOUT + 255) / 256, 1, H_), 256>>>(W0, w0h, w0l, DIN, DOUT);
    gemm_mma_kernel<<<dim3(M_ / 128, DOUT / 128, H_), 256, GEMM_SMEM>>>(
        xh, xl, w0h, w0l, Whh, Whl, DIN, DOUT);
    f12_kernel<<<(H_ * M_) / 8, 256>>>(Whh, Whl, a1_0, a2_0, f1, eu, ev, H_ * M_, M_);
    pbuild_kernel<<<(B_ * N_) / 8, 256>>>(f1, eu, ev, adj, Ph, Pl, H_);
    attn_mma_kernel<H_, false><<<dim3(N_ / 64, B_), 512, ATTN_SMEM>>>(
        Ph, Pl, Whh, Whl, hmh, hml, nullptr);

    // ---- layer 2 ----
    wsplit_kernel<<<dim3((DOUT * DOUT + 255) / 256, 1, 1), 256>>>(Wo, woh, wol, DOUT, DOUT);
    gemm_mma_kernel<<<dim3(M_ / 128, DOUT / 128, 1), 256, GEMM_SMEM>>>(
        hmh, hml, woh, wol, W2h, W2l, DOUT, DOUT);
    f12_kernel<<<M_ / 8, 256>>>(W2h, W2l, a1_o, a2_o, f1b, eub, evb, M_, M_);
    pbuild_kernel<<<(B_ * N_) / 8, 256>>>(f1b, eub, evb, adj, P2h, P2l, 1);
    attn_mma_kernel<1, true><<<dim3(N_ / 64, B_), 512, ATTN_SMEM>>>(
        P2h, P2l, W2h, W2l, nullptr, nullptr, out);
}

// round 6
// speedup vs baseline: 1.6355x; 1.6355x over previous
#include <cuda_runtime.h>
#include <cuda_fp16.h>
#include <math.h>
#include <stdint.h>

#define B_  32
#define N_  512
#define DIN 768
#define DOUT 256
#define H_  8
#define M_  (B_ * N_)

// ---------------- device scratch ----------------
__device__ __half g_xh [(size_t)M_ * DIN];
__device__ __half g_xl [(size_t)M_ * DIN];
__device__ __half g_w0h[(size_t)H_ * DOUT * DIN];
__device__ __half g_w0l[(size_t)H_ * DOUT * DIN];
__device__ __half g_Whh[(size_t)H_ * M_ * DOUT];
__device__ __half g_Whl[(size_t)H_ * M_ * DOUT];
__device__ uint32_t g_mask[(size_t)B_ * N_ * 16];     // packed adjacency bits
__device__ float  g_eu1[H_ * M_];   // exp(f1)
__device__ float  g_ev1[H_ * M_];   // exp(0.2 f1)
__device__ float  g_eu2[H_ * M_];   // exp(f2)
__device__ float  g_ev2[H_ * M_];   // exp(0.2 f2)
__device__ float  g_din[H_ * M_];   // 1/denom
__device__ __half g_hmh[(size_t)M_ * DOUT];
__device__ __half g_hml[(size_t)M_ * DOUT];
__device__ __half g_woh[(size_t)DOUT * DOUT];
__device__ __half g_wol[(size_t)DOUT * DOUT];
__device__ __half g_W2h[(size_t)M_ * DOUT];
__device__ __half g_W2l[(size_t)M_ * DOUT];
__device__ float  g_eu1b[M_];
__device__ float  g_ev1b[M_];
__device__ float  g_eu2b[M_];
__device__ float  g_ev2b[M_];
__device__ float  g_dinb[M_];

// ---------------- PTX helpers ----------------
__device__ __forceinline__ uint32_t smem_u32(const void* p) {
    uint32_t a;
    asm("{ .reg .u64 t; cvta.to.shared.u64 t, %1; cvt.u32.u64 %0, t; }" : "=r"(a) : "l"(p));
    return a;
}
__device__ __forceinline__ void cp16(uint32_t d, const void* s) {
    asm volatile("cp.async.cg.shared.global [%0], [%1], 16;" :: "r"(d), "l"(s));
}
#define CP_COMMIT() asm volatile("cp.async.commit_group;")
#define CP_WAIT(n)  asm volatile("cp.async.wait_group %0;" :: "n"(n))

#define LDM_X4(r, addr) \
    asm volatile("ldmatrix.sync.aligned.m8n8.x4.shared.b16 {%0,%1,%2,%3}, [%4];" \
        : "=r"((r)[0]), "=r"((r)[1]), "=r"((r)[2]), "=r"((r)[3]) : "r"(addr))
#define LDM_X2(r, addr) \
    asm volatile("ldmatrix.sync.aligned.m8n8.x2.shared.b16 {%0,%1}, [%2];" \
        : "=r"((r)[0]), "=r"((r)[1]) : "r"(addr))
#define LDM_X2T(r, addr) \
    asm volatile("ldmatrix.sync.aligned.m8n8.x2.trans.shared.b16 {%0,%1}, [%2];" \
        : "=r"((r)[0]), "=r"((r)[1]) : "r"(addr))

__device__ __forceinline__ void mma_f16(float* c, const uint32_t* a, const uint32_t* b) {
    asm volatile("mma.sync.aligned.m16n8k16.row.col.f32.f16.f16.f32 "
        "{%0,%1,%2,%3}, {%4,%5,%6,%7}, {%8,%9}, {%0,%1,%2,%3};"
        : "+f"(c[0]), "+f"(c[1]), "+f"(c[2]), "+f"(c[3])
        : "r"(a[0]), "r"(a[1]), "r"(a[2]), "r"(a[3]), "r"(b[0]), "r"(b[1]));
}

// ---------------- conversion kernels ----------------
__global__ __launch_bounds__(256) void split_kernel(
    const float* __restrict__ src, __half* __restrict__ hi,
    __half* __restrict__ lo, int n4)
{
    int i = blockIdx.x * 256 + threadIdx.x;
    if (i >= n4) return;
    float4 v = ((const float4*)src)[i];
    __half h0 = __float2half(v.x), h1 = __float2half(v.y);
    __half h2 = __float2half(v.z), h3 = __float2half(v.w);
    ((__half2*)hi)[2 * i]     = __halves2half2(h0, h1);
    ((__half2*)hi)[2 * i + 1] = __halves2half2(h2, h3);
    ((__half2*)lo)[2 * i]     = __halves2half2(
        __float2half(v.x - __half2float(h0)), __float2half(v.y - __half2float(h1)));
    ((__half2*)lo)[2 * i + 1] = __halves2half2(
        __float2half(v.z - __half2float(h2)), __float2half(v.w - __half2float(h3)));
}

__global__ __launch_bounds__(256) void wsplit_kernel(
    const float* __restrict__ W, __half* __restrict__ bh,
    __half* __restrict__ bl, int Kd, int Nd)
{
    int z = blockIdx.z;
    int i = blockIdx.x * 256 + threadIdx.x;
    if (i >= Kd * Nd) return;
    int n = i / Kd, k = i % Kd;
    float v = W[(size_t)z * Kd * Nd + (size_t)k * Nd + n];
    __half h = __float2half(v);
    bh[(size_t)z * Kd * Nd + i] = h;
    bl[(size_t)z * Kd * Nd + i] = __float2half(v - __half2float(h));
}

// ---------------- pack adjacency into bitmask ----------------
__global__ __launch_bounds__(256) void packadj_kernel(
    const int* __restrict__ adj, uint32_t* __restrict__ mask)
{
    int row  = (blockIdx.x * 256 + threadIdx.x) >> 5;
    int lane = threadIdx.x & 31;
    if (row >= B_ * N_) return;
    const int* ar = adj + (size_t)row * N_;
    #pragma unroll
    for (int q = 0; q < 16; ++q) {
        uint32_t w = __ballot_sync(0xffffffffu, ar[q * 32 + lane] > 0);
        if (lane == q) mask[row * 16 + q] = w;
    }
}

// ================= HMMA split GEMM (unchanged from R4) =================
#define GEMM_SMEM (2 * 40960)

__global__ __launch_bounds__(256, 1) void gemm_mma_kernel(
    const __half* __restrict__ Ah, const __half* __restrict__ Al,
    const __half* __restrict__ Bh, const __half* __restrict__ Bl,
    __half* __restrict__ Chh, __half* __restrict__ Chl, int K, int Nt)
{
    extern __shared__ __align__(128) char sm[];
    const uint32_t sb = smem_u32(sm);
    const int t = threadIdx.x, lane = t & 31, wid = t >> 5;
    const int m0 = blockIdx.x * 128, f0 = blockIdx.y * 128, z = blockIdx.z;
    const int warp_m = wid & 1, warp_n = wid >> 1;

    const __half* As_h = Ah + (size_t)m0 * K;
    const __half* As_l = Al + (size_t)m0 * K;
    const __half* Bs_h = Bh + (size_t)z * Nt * K + (size_t)f0 * K;
    const __half* Bs_l = Bl + (size_t)z * Nt * K + (size_t)f0 * K;
    __half* Ch = Chh + (size_t)z * M_ * Nt;
    __half* Cl = Chl + (size_t)z * M_ * Nt;

    float acc[4][4][4];
    #pragma unroll
    for (int a = 0; a < 4; ++a)
        #pragma unroll
        for (int b = 0; b < 4; ++b)
            #pragma unroll
            for (int c = 0; c < 4; ++c) acc[a][b][c] = 0.0f;

    const int row = t >> 1, half = t & 1;
    auto prefetch = [&](int c, int s) {
        const int kc = c * 32;
        const __half* srcs[4] = { As_h + kc, As_l + kc, Bs_h + kc, Bs_l + kc };
        #pragma unroll
        for (int tile = 0; tile < 4; ++tile) {
            uint32_t dst = sb + s * 40960 + tile * 10240 + row * 80 + half * 32;
            const __half* src = srcs[tile] + (size_t)row * K + half * 16;
            cp16(dst, src);
            cp16(dst + 16, src + 8);
        }
        CP_COMMIT();
    };

    const int NC = K >> 5;
    prefetch(0, 0);
    for (int c = 0; c < NC; ++c) {
        const int s = c & 1;
        if (c + 1 < NC) { prefetch(c + 1, s ^ 1); CP_WAIT(1); }
        else CP_WAIT(0);
        __syncthreads();

        const uint32_t bAh = sb + s * 40960;
        const uint32_t bAl = bAh + 10240;
        const uint32_t bBh = bAh + 20480;
        const uint32_t bBl = bAh + 30720;
        #pragma unroll
        for (int k16 = 0; k16 < 2; ++k16) {
            const int kc = k16 * 16;
            uint32_t ah[4][4], al[4][4];
            #pragma unroll
            for (int mf = 0; mf < 4; ++mf) {
                uint32_t off = (uint32_t)((warp_m * 64 + mf * 16 + (lane & 15)) * 80
                                          + (kc + ((lane >> 4) << 3)) * 2);
                LDM_X4(ah[mf], bAh + off);
                LDM_X4(al[mf], bAl + off);
            }
            #pragma unroll
            for (int nf = 0; nf < 4; ++nf) {
                uint32_t boff = (uint32_t)((warp_n * 32 + nf * 8 + (lane & 7)) * 80
                                           + (kc + (((lane >> 3) & 1) << 3)) * 2);
                uint32_t bh[2], bl[2];
                LDM_X2(bh, bBh + boff);
                LDM_X2(bl, bBl + boff);
                #pragma unroll
                for (int mf = 0; mf < 4; ++mf) {
                    mma_f16(acc[mf][nf], ah[mf], bh);
                    mma_f16(acc[mf][nf], ah[mf], bl);
                    mma_f16(acc[mf][nf], al[mf], bh);
                }
            }
        }
        __syncthreads();
    }

    #pragma unroll
    for (int mf = 0; mf < 4; ++mf)
        #pragma unroll
        for (int nf = 0; nf < 4; ++nf) {
            int r0 = m0 + warp_m * 64 + mf * 16 + (lane >> 2);
            int col = f0 + warp_n * 32 + nf * 8 + (lane & 3) * 2;
            #pragma unroll
            for (int hh = 0; hh < 2; ++hh) {
                float c0 = acc[mf][nf][hh * 2], c1 = acc[mf][nf][hh * 2 + 1];
                int r = r0 + hh * 8;
                __half h0 = __float2half(c0), h1 = __float2half(c1);
                *(__half2*)(Ch + (size_t)r * Nt + col) = __halves2half2(h0, h1);
                *(__half2*)(Cl + (size_t)r * Nt + col) = __halves2half2(
                    __float2half(c0 - __half2float(h0)),
                    __float2half(c1 - __half2float(h1)));
            }
        }
}

// ---------------- f1/f2 -> factored exponentials ----------------
__global__ __launch_bounds__(256) void f12_kernel(
    const __half* __restrict__ Whh, const __half* __restrict__ Whl,
    const float* __restrict__ a1, const float* __restrict__ a2,
    float* __restrict__ eu1, float* __restrict__ ev1,
    float* __restrict__ eu2, float* __restrict__ ev2,
    int rows, int Mper)
{
    int warp = (blockIdx.x * blockDim.x + threadIdx.x) >> 5;
    int lane = threadIdx.x & 31;
    if (warp >= rows) return;
    int h = warp / Mper;
    const __half* rh = Whh + (size_t)warp * DOUT;
    const __half* rl = Whl + (size_t)warp * DOUT;
    const float* a1h = a1 + h * DOUT;
    const float* a2h = a2 + h * DOUT;
    float s1 = 0.0f, s2 = 0.0f;
    #pragma unroll
    for (int f = lane; f < DOUT; f += 32) {
        float v = __half2float(rh[f]) + __half2float(rl[f]);
        s1 = fmaf(v, a1h[f], s1);
        s2 = fmaf(v, a2h[f], s2);
    }
    #pragma unroll
    for (int off = 16; off; off >>= 1) {
        s1 += __shfl_xor_sync(0xffffffffu, s1, off);
        s2 += __shfl_xor_sync(0xffffffffu, s2, off);
    }
    if (lane == 0) {
        eu1[warp] = __expf(s1);
        ev1[warp] = __expf(0.2f * s1);
        eu2[warp] = __expf(s2);
        ev2[warp] = __expf(0.2f * s2);
    }
}

// ---------------- denominator (factored, no per-pair exp) ----------------
__global__ __launch_bounds__(256) void dstats_kernel(
    const float* __restrict__ eu1, const float* __restrict__ ev1,
    const float* __restrict__ eu2, const float* __restrict__ ev2,
    const uint32_t* __restrict__ mask, float* __restrict__ dinv, int NH)
{
    int row  = (blockIdx.x * 256 + threadIdx.x) >> 5;
    int lane = threadIdx.x & 31;
    if (row >= B_ * N_) return;
    int b = row >> 9;
    uint32_t myw = (lane < 16) ? mask[row * 16 + lane] : 0u;

    for (int h = 0; h < NH; ++h) {
        size_t hb = (size_t)h * B_ + b;
        size_t r  = hb * N_ + (row & (N_ - 1));
        float u1 = eu1[r], v1 = ev1[r];
        const float* euh = eu2 + hb * N_;
        const float* evh = ev2 + hb * N_;
        float s = 0.0f;
        #pragma unroll
        for (int q = 0; q < 16; ++q) {
            uint32_t w = __shfl_sync(0xffffffffu, myw, q);
            int m = q * 32 + lane;
            float tt = u1 * euh[m];
            float t2 = v1 * evh[m];
            float E = tt >= 1.0f ? tt : t2;
            s += ((w >> lane) & 1u) ? E : 0.0f;
        }
        #pragma unroll
        for (int off = 16; off; off >>= 1)
            s += __shfl_xor_sync(0xffffffffu, s, off);
        if (lane == 0) dinv[r] = s > 0.0f ? 1.0f / s : 0.0f;
    }
}

// ================= HMMA attention: on-the-fly P (factored exp), 2 MMAs =====
// smem layout (bytes):
//  sadj   @ 0      : 64*16 u32            = 4096
//  seu    @ 4096   : 512 f32              = 2048
//  sev    @ 6144   : 512 f32              = 2048
//  su1    @ 8192   : 64 f32 (pad 256)
//  sv1    @ 8448   : 64 f32 (pad 256)
//  sinv   @ 8704   : 64 f32 (pad 256, +256 pad)
//  Ps     @ 9216   : [2 st][64][40] half  = 10240
//  Whs    @ 19456  : [2 st][2 hl][32][264]= 67584
#define ATTN_SMEM (19456 + 67584)

template<int NHEADS, bool FINAL>
__global__ __launch_bounds__(512, 1) void attn_mma_kernel(
    const __half* __restrict__ Whh, const __half* __restrict__ Whl,
    const float* __restrict__ eu1, const float* __restrict__ ev1,
    const float* __restrict__ eu2, const float* __restrict__ ev2,
    const float* __restrict__ dinv, const uint32_t* __restrict__ gmask,
    __half* __restrict__ outh, __half* __restrict__ outl,
    float* __restrict__ outf)
{
    extern __shared__ __align__(128) char sm[];
    const uint32_t sb = smem_u32(sm);
    uint32_t* sadj = (uint32_t*)sm;
    float* seu  = (float*)(sm + 4096);
    float* sev  = (float*)(sm + 6144);
    float* su1  = (float*)(sm + 8192);
    float* sv1  = (float*)(sm + 8448);
    float* sinv = (float*)(sm + 8704);
    const uint32_t smP = sb + 9216;
    const uint32_t smW = sb + 19456;

    const int t = threadIdx.x, lane = t & 31, wid = t >> 5;
    const int n0 = blockIdx.x * 64;
    const int b  = blockIdx.y;
    const int warp_n = wid & 1, warp_f = wid >> 1;

    // adjacency bitmask for this row tile (once per CTA)
    if (t < 64 * 16 / 2) {
        // 512 threads load 2 words each
    }
    {
        int i0 = t;              // 0..511
        sadj[i0]       = gmask[((size_t)b * N_ + n0 + (i0 >> 4)) * 16 + (i0 & 15)];
        int i1 = t + 512;
        sadj[i1]       = gmask[((size_t)b * N_ + n0 + (i1 >> 4)) * 16 + (i1 & 15)];
    }

    const int pi  = t >> 3;          // 0..63
    const int pk4 = (t & 7) * 4;     // 0,4,...,28
    const int hl   = t >> 8;
    const int idx  = t & 255;
    const int wrow = idx >> 3, wseg = idx & 7;

    float sum[2][4][4];
    #pragma unroll
    for (int a = 0; a < 2; ++a)
        #pragma unroll
        for (int c = 0; c < 4; ++c)
            #pragma unroll
            for (int d = 0; d < 4; ++d) sum[a][c][d] = 0.0f;

    for (int h = 0; h < NHEADS; ++h) {
        const size_t hb = (size_t)h * B_ + b;
        const __half* Wsh = Whh + hb * (size_t)N_ * DOUT;
        const __half* Wsl = Whl + hb * (size_t)N_ * DOUT;

        __syncthreads();
        seu[t & 511] = eu2[hb * N_ + (t & 511)];
        sev[t & 511] = ev2[hb * N_ + (t & 511)];
        if (t < 64) {
            su1[t]  = eu1[hb * N_ + n0 + t];
            sv1[t]  = ev1[hb * N_ + n0 + t];
            sinv[t] = dinv[hb * N_ + n0 + t];
        }
        __syncthreads();

        float acc[2][4][4];
        #pragma unroll
        for (int a = 0; a < 2; ++a)
            #pragma unroll
            for (int c = 0; c < 4; ++c)
                #pragma unroll
                for (int d = 0; d < 4; ++d) acc[a][c][d] = 0.0f;

        auto computeP = [&](int c, int st) {
            const int m0 = c * 32;
            float u1 = su1[pi], v1 = sv1[pi], inv = sinv[pi];
            uint32_t w = sadj[pi * 16 + c];
            __half hs[4];
            #pragma unroll
            for (int kk = 0; kk < 4; ++kk) {
                int mm = m0 + pk4 + kk;
                float tt = u1 * seu[mm];
                float t2 = v1 * sev[mm];
                float E  = tt >= 1.0f ? tt : t2;
                float p  = ((w >> (pk4 + kk)) & 1u) ? E * inv : 0.0f;
                hs[kk] = __float2half(p);
            }
            char* dh = sm + 9216 + st * 5120 + pi * 80 + pk4 * 2;
            ((__half2*)dh)[0] = __halves2half2(hs[0], hs[1]);
            ((__half2*)dh)[1] = __halves2half2(hs[2], hs[3]);
        };
        auto prefetchW = [&](int c, int st) {
            const int m0 = c * 32;
            const __half* src = (hl ? Wsl : Wsh) + (size_t)(m0 + wrow) * DOUT;
            uint32_t dst = smW + st * 33792 + hl * 16896 + wrow * 528;
            #pragma unroll
            for (int j = 0; j < 4; ++j) {
                int s8 = wseg + j * 8;
                cp16(dst + s8 * 16, src + s8 * 8);
            }
            CP_COMMIT();
        };

        computeP(0, 0);
        prefetchW(0, 0);
        for (int c = 0; c < 16; ++c) {
            const int st = c & 1;
            if (c < 15) {
                prefetchW(c + 1, st ^ 1);
                computeP(c + 1, st ^ 1);
                CP_WAIT(1);
            } else CP_WAIT(0);
            __syncthreads();

            const uint32_t Phs = smP + st * 5120;
            const uint32_t Whs = smW + st * 33792;
            const uint32_t Wls = Whs + 16896;
            #pragma unroll
            for (int k16 = 0; k16 < 2; ++k16) {
                const int kc = k16 * 16;
                uint32_t ah[2][4];
                #pragma unroll
                for (int mf = 0; mf < 2; ++mf) {
                    uint32_t off = (uint32_t)((warp_n * 32 + mf * 16 + (lane & 15)) * 80
                                              + (kc + ((lane >> 4) << 3)) * 2);
                    LDM_X4(ah[mf], Phs + off);
                }
                #pragma unroll
                for (int nf = 0; nf < 4; ++nf) {
                    uint32_t woff = (uint32_t)((kc + (lane & 15)) * 528
                                               + (warp_f * 32 + nf * 8) * 2);
                    uint32_t bh[2], bl[2];
                    LDM_X2T(bh, Whs + woff);
                    LDM_X2T(bl, Wls + woff);
                    #pragma unroll
                    for (int mf = 0; mf < 2; ++mf) {
                        mma_f16(acc[mf][nf], ah[mf], bh);
                        mma_f16(acc[mf][nf], ah[mf], bl);
                    }
                }
            }
            __syncthreads();
        }

        if (FINAL) {
            #pragma unroll
            for (int a = 0; a < 2; ++a)
                #pragma unroll
                for (int c = 0; c < 4; ++c)
                    #pragma unroll
                    for (int d = 0; d < 4; ++d) sum[a][c][d] = acc[a][c][d];
        } else {
            #pragma unroll
            for (int a = 0; a < 2; ++a)
                #pragma unroll
                for (int c = 0; c < 4; ++c)
                    #pragma unroll
                    for (int d = 0; d < 4; ++d) {
                        float v = acc[a][c][d];
                        sum[a][c][d] += (v > 0.0f) ? v : expm1f(v);
                    }
        }
    }

    #pragma unroll
    for (int mf = 0; mf < 2; ++mf)
        #pragma unroll
        for (int nf = 0; nf < 4; ++nf) {
            int r0  = n0 + warp_n * 32 + mf * 16 + (lane >> 2);
            int col = warp_f * 32 + nf * 8 + (lane & 3) * 2;
            #pragma unroll
            for (int hh2 = 0; hh2 < 2; ++hh2) {
                int r = r0 + hh2 * 8;
                float c0 = sum[mf][nf][hh2 * 2], c1 = sum[mf][nf][hh2 * 2 + 1];
                if (FINAL) {
                    float2 v = { fmaxf(c0, 0.0f), fmaxf(c1, 0.0f) };
                    *(float2*)(outf + ((size_t)b * N_ + r) * DOUT + col) = v;
                } else {
                    c0 *= 0.125f; c1 *= 0.125f;
                    __half h0 = __float2half(c0), h1 = __float2half(c1);
                    *(__half2*)(outh + ((size_t)b * N_ + r) * DOUT + col) =
                        __halves2half2(h0, h1);
                    *(__half2*)(outl + ((size_t)b * N_ + r) * DOUT + col) =
                        __halves2half2(__float2half(c0 - __half2float(h0)),
                                       __float2half(c1 - __half2float(h1)));
                }
            }
        }
}

// ---------------- launch ----------------
extern "C" void kernel_launch(void* const* d_in, const int* in_sizes, int n_in,
                              void* d_out, int out_size)
{
    const float* x    = (const float*)d_in[0];
    const int*   adj  = (const int*)  d_in[1];
    const float* W0   = (const float*)d_in[2];
    const float* a1_0 = (const float*)d_in[3];
    const float* a2_0 = (const float*)d_in[4];
    const float* Wo   = (const float*)d_in[5];
    const float* a1_o = (const float*)d_in[6];
    const float* a2_o = (const float*)d_in[7];
    float* out = (float*)d_out;

    __half *xh, *xl, *w0h, *w0l, *Whh, *Whl, *hmh, *hml, *woh, *wol, *W2h, *W2l;
    float *eu1, *ev1, *eu2, *ev2, *din, *eu1b, *ev1b, *eu2b, *ev2b, *dinb;
    uint32_t* mask;
    cudaGetSymbolAddress((void**)&xh,  g_xh);
    cudaGetSymbolAddress((void**)&xl,  g_xl);
    cudaGetSymbolAddress((void**)&w0h, g_w0h);
    cudaGetSymbolAddress((void**)&w0l, g_w0l);
    cudaGetSymbolAddress((void**)&Whh, g_Whh);
    cudaGetSymbolAddress((void**)&Whl, g_Whl);
    cudaGetSymbolAddress((void**)&mask, g_mask);
    cudaGetSymbolAddress((void**)&eu1, g_eu1);
    cudaGetSymbolAddress((void**)&ev1, g_ev1);
    cudaGetSymbolAddress((void**)&eu2, g_eu2);
    cudaGetSymbolAddress((void**)&ev2, g_ev2);
    cudaGetSymbolAddress((void**)&din, g_din);
    cudaGetSymbolAddress((void**)&hmh, g_hmh);
    cudaGetSymbolAddress((void**)&hml, g_hml);
    cudaGetSymbolAddress((void**)&woh, g_woh);
    cudaGetSymbolAddress((void**)&wol, g_wol);
    cudaGetSymbolAddress((void**)&W2h, g_W2h);
    cudaGetSymbolAddress((void**)&W2l, g_W2l);
    cudaGetSymbolAddress((void**)&eu1b, g_eu1b);
    cudaGetSymbolAddress((void**)&ev1b, g_ev1b);
    cudaGetSymbolAddress((void**)&eu2b, g_eu2b);
    cudaGetSymbolAddress((void**)&ev2b, g_ev2b);
    cudaGetSymbolAddress((void**)&dinb, g_dinb);

    cudaFuncSetAttribute(gemm_mma_kernel,
        cudaFuncAttributeMaxDynamicSharedMemorySize, GEMM_SMEM);
    cudaFuncSetAttribute(attn_mma_kernel<H_, false>,
        cudaFuncAttributeMaxDynamicSharedMemorySize, ATTN_SMEM);
    cudaFuncSetAttribute(attn_mma_kernel<1, true>,
        cudaFuncAttributeMaxDynamicSharedMemorySize, ATTN_SMEM);

    // ---- layer 1 ----
    packadj_kernel<<<(B_ * N_) / 8, 256>>>(adj, mask);
    split_kernel<<<(M_ * DIN / 4 + 255) / 256, 256>>>(x, xh, xl, M_ * DIN / 4);
    wsplit_kernel<<<dim3((DIN * DOUT + 255) / 256, 1, H_), 256>>>(W0, w0h, w0l, DIN, DOUT);
    gemm_mma_kernel<<<dim3(M_ / 128, DOUT / 128, H_), 256, GEMM_SMEM>>>(
        xh, xl, w0h, w0l, Whh, Whl, DIN, DOUT);
    f12_kernel<<<(H_ * M_) / 8, 256>>>(Whh, Whl, a1_0, a2_0,
                                       eu1, ev1, eu2, ev2, H_ * M_, M_);
    dstats_kernel<<<(B_ * N_) / 8, 256>>>(eu1, ev1, eu2, ev2, mask, din, H_);
    attn_mma_kernel<H_, false><<<dim3(N_ / 64, B_), 512, ATTN_SMEM>>>(
        Whh, Whl, eu1, ev1, eu2, ev2, din, mask, hmh, hml, nullptr);

    // ---- layer 2 ----
    wsplit_kernel<<<dim3((DOUT * DOUT + 255) / 256, 1, 1), 256>>>(Wo, woh, wol, DOUT, DOUT);
    gemm_mma_kernel<<<dim3(M_ / 128, DOUT / 128, 1), 256, GEMM_SMEM>>>(
        hmh, hml, woh, wol, W2h, W2l, DOUT, DOUT);
    f12_kernel<<<M_ / 8, 256>>>(W2h, W2l, a1_o, a2_o,
                                eu1b, ev1b, eu2b, ev2b, M_, M_);
    dstats_kernel<<<(B_ * N_) / 8, 256>>>(eu1b, ev1b, eu2b, ev2b, mask, dinb, 1);
    attn_mma_kernel<1, true><<<dim3(N_ / 64, B_), 512, ATTN_SMEM>>>(
        W2h, W2l, eu1b, ev1b, eu2b, ev2b, dinb, mask, nullptr, nullptr, out);
}

// round 7
// speedup vs baseline: 1.8127x; 1.1083x over previous
#include <cuda_runtime.h>
#include <cuda_fp16.h>
#include <math.h>
#include <stdint.h>

#define B_  32
#define N_  512
#define DIN 768
#define DOUT 256
#define H_  8
#define M_  (B_ * N_)

// ---------------- device scratch ----------------
__device__ __half g_xh [(size_t)M_ * DIN];
__device__ __half g_xl [(size_t)M_ * DIN];
__device__ __half g_w0h[(size_t)H_ * DOUT * DIN];
__device__ __half g_w0l[(size_t)H_ * DOUT * DIN];
__device__ __half g_Whh[(size_t)H_ * M_ * DOUT];
__device__ __half g_Whl[(size_t)H_ * M_ * DOUT];
__device__ uint32_t g_mask[(size_t)B_ * N_ * 16];     // packed adjacency bits
__device__ float  g_eu1[H_ * M_];   // exp(f1)
__device__ float  g_ev1[H_ * M_];   // exp(0.2 f1)
__device__ float  g_eu2[H_ * M_];   // exp(f2)
__device__ float  g_ev2[H_ * M_];   // exp(0.2 f2)
__device__ float  g_din[H_ * M_];   // 1/denom
__device__ __half g_hmh[(size_t)M_ * DOUT];
__device__ __half g_hml[(size_t)M_ * DOUT];
__device__ __half g_woh[(size_t)DOUT * DOUT];
__device__ __half g_wol[(size_t)DOUT * DOUT];
__device__ __half g_W2h[(size_t)M_ * DOUT];
__device__ __half g_W2l[(size_t)M_ * DOUT];
__device__ float  g_eu1b[M_];
__device__ float  g_ev1b[M_];
__device__ float  g_eu2b[M_];
__device__ float  g_ev2b[M_];
__device__ float  g_dinb[M_];

// ---------------- PTX helpers ----------------
__device__ __forceinline__ uint32_t smem_u32(const void* p) {
    uint32_t a;
    asm("{ .reg .u64 t; cvta.to.shared.u64 t, %1; cvt.u32.u64 %0, t; }" : "=r"(a) : "l"(p));
    return a;
}
__device__ __forceinline__ void cp16(uint32_t d, const void* s) {
    asm volatile("cp.async.cg.shared.global [%0], [%1], 16;" :: "r"(d), "l"(s));
}
#define CP_COMMIT() asm volatile("cp.async.commit_group;")
#define CP_WAIT(n)  asm volatile("cp.async.wait_group %0;" :: "n"(n))

#define LDM_X4(r, addr) \
    asm volatile("ldmatrix.sync.aligned.m8n8.x4.shared.b16 {%0,%1,%2,%3}, [%4];" \
        : "=r"((r)[0]), "=r"((r)[1]), "=r"((r)[2]), "=r"((r)[3]) : "r"(addr))
#define LDM_X2(r, addr) \
    asm volatile("ldmatrix.sync.aligned.m8n8.x2.shared.b16 {%0,%1}, [%2];" \
        : "=r"((r)[0]), "=r"((r)[1]) : "r"(addr))
#define LDM_X2T(r, addr) \
    asm volatile("ldmatrix.sync.aligned.m8n8.x2.trans.shared.b16 {%0,%1}, [%2];" \
        : "=r"((r)[0]), "=r"((r)[1]) : "r"(addr))

__device__ __forceinline__ void mma_f16(float* c, const uint32_t* a, const uint32_t* b) {
    asm volatile("mma.sync.aligned.m16n8k16.row.col.f32.f16.f16.f32 "
        "{%0,%1,%2,%3}, {%4,%5,%6,%7}, {%8,%9}, {%0,%1,%2,%3};"
        : "+f"(c[0]), "+f"(c[1]), "+f"(c[2]), "+f"(c[3])
        : "r"(a[0]), "r"(a[1]), "r"(a[2]), "r"(a[3]), "r"(b[0]), "r"(b[1]));
}

// ---------------- conversion kernels ----------------
__global__ __launch_bounds__(256) void split_kernel(
    const float* __restrict__ src, __half* __restrict__ hi,
    __half* __restrict__ lo, int n4)
{
    int i = blockIdx.x * 256 + threadIdx.x;
    if (i >= n4) return;
    float4 v = ((const float4*)src)[i];
    __half h0 = __float2half(v.x), h1 = __float2half(v.y);
    __half h2 = __float2half(v.z), h3 = __float2half(v.w);
    ((__half2*)hi)[2 * i]     = __halves2half2(h0, h1);
    ((__half2*)hi)[2 * i + 1] = __halves2half2(h2, h3);
    ((__half2*)lo)[2 * i]     = __halves2half2(
        __float2half(v.x - __half2float(h0)), __float2half(v.y - __half2float(h1)));
    ((__half2*)lo)[2 * i + 1] = __halves2half2(
        __float2half(v.z - __half2float(h2)), __float2half(v.w - __half2float(h3)));
}

__global__ __launch_bounds__(256) void wsplit_kernel(
    const float* __restrict__ W, __half* __restrict__ bh,
    __half* __restrict__ bl, int Kd, int Nd)
{
    int z = blockIdx.z;
    int i = blockIdx.x * 256 + threadIdx.x;
    if (i >= Kd * Nd) return;
    int n = i / Kd, k = i % Kd;
    float v = W[(size_t)z * Kd * Nd + (size_t)k * Nd + n];
    __half h = __float2half(v);
    bh[(size_t)z * Kd * Nd + i] = h;
    bl[(size_t)z * Kd * Nd + i] = __float2half(v - __half2float(h));
}

// ---------------- pack adjacency into bitmask ----------------
__global__ __launch_bounds__(256) void packadj_kernel(
    const int* __restrict__ adj, uint32_t* __restrict__ mask)
{
    int row  = (blockIdx.x * 256 + threadIdx.x) >> 5;
    int lane = threadIdx.x & 31;
    if (row >= B_ * N_) return;
    const int* ar = adj + (size_t)row * N_;
    #pragma unroll
    for (int q = 0; q < 16; ++q) {
        uint32_t w = __ballot_sync(0xffffffffu, ar[q * 32 + lane] > 0);
        if (lane == q) mask[row * 16 + q] = w;
    }
}

// ================= HMMA split GEMM (2 CTAs/SM) =================
#define GEMM_SMEM (2 * 40960)

__global__ __launch_bounds__(256, 2) void gemm_mma_kernel(
    const __half* __restrict__ Ah, const __half* __restrict__ Al,
    const __half* __restrict__ Bh, const __half* __restrict__ Bl,
    __half* __restrict__ Chh, __half* __restrict__ Chl, int K, int Nt)
{
    extern __shared__ __align__(128) char sm[];
    const uint32_t sb = smem_u32(sm);
    const int t = threadIdx.x, lane = t & 31, wid = t >> 5;
    const int m0 = blockIdx.x * 128, f0 = blockIdx.y * 128, z = blockIdx.z;
    const int warp_m = wid & 1, warp_n = wid >> 1;

    const __half* As_h = Ah + (size_t)m0 * K;
    const __half* As_l = Al + (size_t)m0 * K;
    const __half* Bs_h = Bh + (size_t)z * Nt * K + (size_t)f0 * K;
    const __half* Bs_l = Bl + (size_t)z * Nt * K + (size_t)f0 * K;
    __half* Ch = Chh + (size_t)z * M_ * Nt;
    __half* Cl = Chl + (size_t)z * M_ * Nt;

    float acc[4][4][4];
    #pragma unroll
    for (int a = 0; a < 4; ++a)
        #pragma unroll
        for (int b = 0; b < 4; ++b)
            #pragma unroll
            for (int c = 0; c < 4; ++c) acc[a][b][c] = 0.0f;

    const int row = t >> 1, half = t & 1;
    auto prefetch = [&](int c, int s) {
        const int kc = c * 32;
        const __half* srcs[4] = { As_h + kc, As_l + kc, Bs_h + kc, Bs_l + kc };
        #pragma unroll
        for (int tile = 0; tile < 4; ++tile) {
            uint32_t dst = sb + s * 40960 + tile * 10240 + row * 80 + half * 32;
            const __half* src = srcs[tile] + (size_t)row * K + half * 16;
            cp16(dst, src);
            cp16(dst + 16, src + 8);
        }
        CP_COMMIT();
    };

    const int NC = K >> 5;
    prefetch(0, 0);
    for (int c = 0; c < NC; ++c) {
        const int s = c & 1;
        if (c + 1 < NC) { prefetch(c + 1, s ^ 1); CP_WAIT(1); }
        else CP_WAIT(0);
        __syncthreads();

        const uint32_t bAh = sb + s * 40960;
        const uint32_t bAl = bAh + 10240;
        const uint32_t bBh = bAh + 20480;
        const uint32_t bBl = bAh + 30720;
        #pragma unroll
        for (int k16 = 0; k16 < 2; ++k16) {
            const int kc = k16 * 16;
            uint32_t ah[4][4], al[4][4];
            #pragma unroll
            for (int mf = 0; mf < 4; ++mf) {
                uint32_t off = (uint32_t)((warp_m * 64 + mf * 16 + (lane & 15)) * 80
                                          + (kc + ((lane >> 4) << 3)) * 2);
                LDM_X4(ah[mf], bAh + off);
                LDM_X4(al[mf], bAl + off);
            }
            #pragma unroll
            for (int nf = 0; nf < 4; ++nf) {
                uint32_t boff = (uint32_t)((warp_n * 32 + nf * 8 + (lane & 7)) * 80
                                           + (kc + (((lane >> 3) & 1) << 3)) * 2);
                uint32_t bh[2], bl[2];
                LDM_X2(bh, bBh + boff);
                LDM_X2(bl, bBl + boff);
                #pragma unroll
                for (int mf = 0; mf < 4; ++mf) {
                    mma_f16(acc[mf][nf], ah[mf], bh);
                    mma_f16(acc[mf][nf], ah[mf], bl);
                    mma_f16(acc[mf][nf], al[mf], bh);
                }
            }
        }
        __syncthreads();
    }

    #pragma unroll
    for (int mf = 0; mf < 4; ++mf)
        #pragma unroll
        for (int nf = 0; nf < 4; ++nf) {
            int r0 = m0 + warp_m * 64 + mf * 16 + (lane >> 2);
            int col = f0 + warp_n * 32 + nf * 8 + (lane & 3) * 2;
            #pragma unroll
            for (int hh = 0; hh < 2; ++hh) {
                float c0 = acc[mf][nf][hh * 2], c1 = acc[mf][nf][hh * 2 + 1];
                int r = r0 + hh * 8;
                __half h0 = __float2half(c0), h1 = __float2half(c1);
                *(__half2*)(Ch + (size_t)r * Nt + col) = __halves2half2(h0, h1);
                *(__half2*)(Cl + (size_t)r * Nt + col) = __halves2half2(
                    __float2half(c0 - __half2float(h0)),
                    __float2half(c1 - __half2float(h1)));
            }
        }
}

// ---------------- f1/f2 -> factored exponentials ----------------
__global__ __launch_bounds__(256) void f12_kernel(
    const __half* __restrict__ Whh, const __half* __restrict__ Whl,
    const float* __restrict__ a1, const float* __restrict__ a2,
    float* __restrict__ eu1, float* __restrict__ ev1,
    float* __restrict__ eu2, float* __restrict__ ev2,
    int rows, int Mper)
{
    int warp = (blockIdx.x * blockDim.x + threadIdx.x) >> 5;
    int lane = threadIdx.x & 31;
    if (warp >= rows) return;
    int h = warp / Mper;
    const __half* rh = Whh + (size_t)warp * DOUT;
    const __half* rl = Whl + (size_t)warp * DOUT;
    const float* a1h = a1 + h * DOUT;
    const float* a2h = a2 + h * DOUT;
    float s1 = 0.0f, s2 = 0.0f;
    #pragma unroll
    for (int f = lane; f < DOUT; f += 32) {
        float v = __half2float(rh[f]) + __half2float(rl[f]);
        s1 = fmaf(v, a1h[f], s1);
        s2 = fmaf(v, a2h[f], s2);
    }
    #pragma unroll
    for (int off = 16; off; off >>= 1) {
        s1 += __shfl_xor_sync(0xffffffffu, s1, off);
        s2 += __shfl_xor_sync(0xffffffffu, s2, off);
    }
    if (lane == 0) {
        eu1[warp] = __expf(s1);
        ev1[warp] = __expf(0.2f * s1);
        eu2[warp] = __expf(s2);
        ev2[warp] = __expf(0.2f * s2);
    }
}

// ---------------- denominator (factored, no per-pair exp) ----------------
__global__ __launch_bounds__(256) void dstats_kernel(
    const float* __restrict__ eu1, const float* __restrict__ ev1,
    const float* __restrict__ eu2, const float* __restrict__ ev2,
    const uint32_t* __restrict__ mask, float* __restrict__ dinv, int NH)
{
    int row  = (blockIdx.x * 256 + threadIdx.x) >> 5;
    int lane = threadIdx.x & 31;
    if (row >= B_ * N_) return;
    int b = row >> 9;
    uint32_t myw = (lane < 16) ? mask[row * 16 + lane] : 0u;

    for (int h = 0; h < NH; ++h) {
        size_t hb = (size_t)h * B_ + b;
        size_t r  = hb * N_ + (row & (N_ - 1));
        float u1 = eu1[r], v1 = ev1[r];
        const float* euh = eu2 + hb * N_;
        const float* evh = ev2 + hb * N_;
        float s = 0.0f;
        #pragma unroll
        for (int q = 0; q < 16; ++q) {
            uint32_t w = __shfl_sync(0xffffffffu, myw, q);
            int m = q * 32 + lane;
            float tt = u1 * euh[m];
            float t2 = v1 * evh[m];
            float E = tt >= 1.0f ? tt : t2;
            s += ((w >> lane) & 1u) ? E : 0.0f;
        }
        #pragma unroll
        for (int off = 16; off; off >>= 1)
            s += __shfl_xor_sync(0xffffffffu, s, off);
        if (lane == 0) dinv[r] = s > 0.0f ? 1.0f / s : 0.0f;
    }
}

// ================= HMMA attention: on-the-fly P (factored exp), 2 MMAs =====
#define ATTN_SMEM (19456 + 67584)

template<int NHEADS, bool FINAL>
__global__ __launch_bounds__(512, 1) void attn_mma_kernel(
    const __half* __restrict__ Whh, const __half* __restrict__ Whl,
    const float* __restrict__ eu1, const float* __restrict__ ev1,
    const float* __restrict__ eu2, const float* __restrict__ ev2,
    const float* __restrict__ dinv, const uint32_t* __restrict__ gmask,
    __half* __restrict__ outh, __half* __restrict__ outl,
    float* __restrict__ outf)
{
    extern __shared__ __align__(128) char sm[];
    const uint32_t sb = smem_u32(sm);
    uint32_t* sadj = (uint32_t*)sm;
    float* seu  = (float*)(sm + 4096);
    float* sev  = (float*)(sm + 6144);
    float* su1  = (float*)(sm + 8192);
    float* sv1  = (float*)(sm + 8448);
    float* sinv = (float*)(sm + 8704);
    const uint32_t smP = sb + 9216;
    const uint32_t smW = sb + 19456;

    const int t = threadIdx.x, lane = t & 31, wid = t >> 5;
    const int n0 = blockIdx.x * 64;
    const int b  = blockIdx.y;
    const int warp_n = wid & 1, warp_f = wid >> 1;

    // adjacency bitmask for this row tile (once per CTA)
    {
        int i0 = t;
        sadj[i0] = gmask[((size_t)b * N_ + n0 + (i0 >> 4)) * 16 + (i0 & 15)];
        int i1 = t + 512;
        sadj[i1] = gmask[((size_t)b * N_ + n0 + (i1 >> 4)) * 16 + (i1 & 15)];
    }

    const int pi  = t >> 3;          // 0..63
    const int pk4 = (t & 7) * 4;     // 0,4,...,28
    const int hl   = t >> 8;
    const int idx  = t & 255;
    const int wrow = idx >> 3, wseg = idx & 7;

    float sum[2][4][4];
    #pragma unroll
    for (int a = 0; a < 2; ++a)
        #pragma unroll
        for (int c = 0; c < 4; ++c)
            #pragma unroll
            for (int d = 0; d < 4; ++d) sum[a][c][d] = 0.0f;

    for (int h = 0; h < NHEADS; ++h) {
        const size_t hb = (size_t)h * B_ + b;
        const __half* Wsh = Whh + hb * (size_t)N_ * DOUT;
        const __half* Wsl = Whl + hb * (size_t)N_ * DOUT;

        __syncthreads();
        seu[t & 511] = eu2[hb * N_ + (t & 511)];
        sev[t & 511] = ev2[hb * N_ + (t & 511)];
        if (t < 64) {
            su1[t]  = eu1[hb * N_ + n0 + t];
            sv1[t]  = ev1[hb * N_ + n0 + t];
            sinv[t] = dinv[hb * N_ + n0 + t];
        }
        __syncthreads();

        float acc[2][4][4];
        #pragma unroll
        for (int a = 0; a < 2; ++a)
            #pragma unroll
            for (int c = 0; c < 4; ++c)
                #pragma unroll
                for (int d = 0; d < 4; ++d) acc[a][c][d] = 0.0f;

        auto computeP = [&](int c, int st) {
            const int m0 = c * 32;
            float u1 = su1[pi], v1 = sv1[pi], inv = sinv[pi];
            uint32_t w = sadj[pi * 16 + c];
            __half hs[4];
            #pragma unroll
            for (int kk = 0; kk < 4; ++kk) {
                int mm = m0 + pk4 + kk;
                float tt = u1 * seu[mm];
                float t2 = v1 * sev[mm];
                float E  = tt >= 1.0f ? tt : t2;
                float p  = ((w >> (pk4 + kk)) & 1u) ? E * inv : 0.0f;
                hs[kk] = __float2half(p);
            }
            char* dh = sm + 9216 + st * 5120 + pi * 80 + pk4 * 2;
            ((__half2*)dh)[0] = __halves2half2(hs[0], hs[1]);
            ((__half2*)dh)[1] = __halves2half2(hs[2], hs[3]);
        };
        auto prefetchW = [&](int c, int st) {
            const int m0 = c * 32;
            const __half* src = (hl ? Wsl : Wsh) + (size_t)(m0 + wrow) * DOUT;
            uint32_t dst = smW + st * 33792 + hl * 16896 + wrow * 528;
            #pragma unroll
            for (int j = 0; j < 4; ++j) {
                int s8 = wseg + j * 8;
                cp16(dst + s8 * 16, src + s8 * 8);
            }
            CP_COMMIT();
        };

        computeP(0, 0);
        prefetchW(0, 0);
        for (int c = 0; c < 16; ++c) {
            const int st = c & 1;
            if (c < 15) {
                prefetchW(c + 1, st ^ 1);
                computeP(c + 1, st ^ 1);
                CP_WAIT(1);
            } else CP_WAIT(0);
            __syncthreads();

            const uint32_t Phs = smP + st * 5120;
            const uint32_t Whs = smW + st * 33792;
            const uint32_t Wls = Whs + 16896;
            #pragma unroll
            for (int k16 = 0; k16 < 2; ++k16) {
                const int kc = k16 * 16;
                uint32_t ah[2][4];
                #pragma unroll
                for (int mf = 0; mf < 2; ++mf) {
                    uint32_t off = (uint32_t)((warp_n * 32 + mf * 16 + (lane & 15)) * 80
                                              + (kc + ((lane >> 4) << 3)) * 2);
                    LDM_X4(ah[mf], Phs + off);
                }
                #pragma unroll
                for (int nf = 0; nf < 4; ++nf) {
                    uint32_t woff = (uint32_t)((kc + (lane & 15)) * 528
                                               + (warp_f * 32 + nf * 8) * 2);
                    uint32_t bh[2], bl[2];
                    LDM_X2T(bh, Whs + woff);
                    LDM_X2T(bl, Wls + woff);
                    #pragma unroll
                    for (int mf = 0; mf < 2; ++mf) {
                        mma_f16(acc[mf][nf], ah[mf], bh);
                        mma_f16(acc[mf][nf], ah[mf], bl);
                    }
                }
            }
            __syncthreads();
        }

        if (FINAL) {
            #pragma unroll
            for (int a = 0; a < 2; ++a)
                #pragma unroll
                for (int c = 0; c < 4; ++c)
                    #pragma unroll
                    for (int d = 0; d < 4; ++d) sum[a][c][d] = acc[a][c][d];
        } else {
            #pragma unroll
            for (int a = 0; a < 2; ++a)
                #pragma unroll
                for (int c = 0; c < 4; ++c)
                    #pragma unroll
                    for (int d = 0; d < 4; ++d) {
                        float v = acc[a][c][d];
                        sum[a][c][d] += (v > 0.0f) ? v : expm1f(v);
                    }
        }
    }

    #pragma unroll
    for (int mf = 0; mf < 2; ++mf)
        #pragma unroll
        for (int nf = 0; nf < 4; ++nf) {
            int r0  = n0 + warp_n * 32 + mf * 16 + (lane >> 2);
            int col = warp_f * 32 + nf * 8 + (lane & 3) * 2;
            #pragma unroll
            for (int hh2 = 0; hh2 < 2; ++hh2) {
                int r = r0 + hh2 * 8;
                float c0 = sum[mf][nf][hh2 * 2], c1 = sum[mf][nf][hh2 * 2 + 1];
                if (FINAL) {
                    float2 v = { fmaxf(c0, 0.0f), fmaxf(c1, 0.0f) };
                    *(float2*)(outf + ((size_t)b * N_ + r) * DOUT + col) = v;
                } else {
                    c0 *= 0.125f; c1 *= 0.125f;
                    __half h0 = __float2half(c0), h1 = __float2half(c1);
                    *(__half2*)(outh + ((size_t)b * N_ + r) * DOUT + col) =
                        __halves2half2(h0, h1);
                    *(__half2*)(outl + ((size_t)b * N_ + r) * DOUT + col) =
                        __halves2half2(__float2half(c0 - __half2float(h0)),
                                       __float2half(c1 - __half2float(h1)));
                }
            }
        }
}

// ---------------- launch ----------------
extern "C" void kernel_launch(void* const* d_in, const int* in_sizes, int n_in,
                              void* d_out, int out_size)
{
    const float* x    = (const float*)d_in[0];
    const int*   adj  = (const int*)  d_in[1];
    const float* W0   = (const float*)d_in[2];
    const float* a1_0 = (const float*)d_in[3];
    const float* a2_0 = (const float*)d_in[4];
    const float* Wo   = (const float*)d_in[5];
    const float* a1_o = (const float*)d_in[6];
    const float* a2_o = (const float*)d_in[7];
    float* out = (float*)d_out;

    __half *xh, *xl, *w0h, *w0l, *Whh, *Whl, *hmh, *hml, *woh, *wol, *W2h, *W2l;
    float *eu1, *ev1, *eu2, *ev2, *din, *eu1b, *ev1b, *eu2b, *ev2b, *dinb;
    uint32_t* mask;
    cudaGetSymbolAddress((void**)&xh,  g_xh);
    cudaGetSymbolAddress((void**)&xl,  g_xl);
    cudaGetSymbolAddress((void**)&w0h, g_w0h);
    cudaGetSymbolAddress((void**)&w0l, g_w0l);
    cudaGetSymbolAddress((void**)&Whh, g_Whh);
    cudaGetSymbolAddress((void**)&Whl, g_Whl);
    cudaGetSymbolAddress((void**)&mask, g_mask);
    cudaGetSymbolAddress((void**)&eu1, g_eu1);
    cudaGetSymbolAddress((void**)&ev1, g_ev1);
    cudaGetSymbolAddress((void**)&eu2, g_eu2);
    cudaGetSymbolAddress((void**)&ev2, g_ev2);
    cudaGetSymbolAddress((void**)&din, g_din);
    cudaGetSymbolAddress((void**)&hmh, g_hmh);
    cudaGetSymbolAddress((void**)&hml, g_hml);
    cudaGetSymbolAddress((void**)&woh, g_woh);
    cudaGetSymbolAddress((void**)&wol, g_wol);
    cudaGetSymbolAddress((void**)&W2h, g_W2h);
    cudaGetSymbolAddress((void**)&W2l, g_W2l);
    cudaGetSymbolAddress((void**)&eu1b, g_eu1b);
    cudaGetSymbolAddress((void**)&ev1b, g_ev1b);
    cudaGetSymbolAddress((void**)&eu2b, g_eu2b);
    cudaGetSymbolAddress((void**)&ev2b, g_ev2b);
    cudaGetSymbolAddress((void**)&dinb, g_dinb);

    cudaFuncSetAttribute(gemm_mma_kernel,
        cudaFuncAttributeMaxDynamicSharedMemorySize, GEMM_SMEM);
    cudaFuncSetAttribute(attn_mma_kernel<H_, false>,
        cudaFuncAttributeMaxDynamicSharedMemorySize, ATTN_SMEM);
    cudaFuncSetAttribute(attn_mma_kernel<1, true>,
        cudaFuncAttributeMaxDynamicSharedMemorySize, ATTN_SMEM);

    // ---- layer 1 ----
    packadj_kernel<<<(B_ * N_) / 8, 256>>>(adj, mask);
    split_kernel<<<(M_ * DIN / 4 + 255) / 256, 256>>>(x, xh, xl, M_ * DIN / 4);
    wsplit_kernel<<<dim3((DIN * DOUT + 255) / 256, 1, H_), 256>>>(W0, w0h, w0l, DIN, DOUT);
    gemm_mma_kernel<<<dim3(M_ / 128, DOUT / 128, H_), 256, GEMM_SMEM>>>(
        xh, xl, w0h, w0l, Whh, Whl, DIN, DOUT);
    f12_kernel<<<(H_ * M_) / 8, 256>>>(Whh, Whl, a1_0, a2_0,
                                       eu1, ev1, eu2, ev2, H_ * M_, M_);
    dstats_kernel<<<(B_ * N_) / 8, 256>>>(eu1, ev1, eu2, ev2, mask, din, H_);
    attn_mma_kernel<H_, false><<<dim3(N_ / 64, B_), 512, ATTN_SMEM>>>(
        Whh, Whl, eu1, ev1, eu2, ev2, din, mask, hmh, hml, nullptr);

    // ---- layer 2 ----
    wsplit_kernel<<<dim3((DOUT * DOUT + 255) / 256, 1, 1), 256>>>(Wo, woh, wol, DOUT, DOUT);
    gemm_mma_kernel<<<dim3(M_ / 128, DOUT / 128, 1), 256, GEMM_SMEM>>>(
        hmh, hml, woh, wol, W2h, W2l, DOUT, DOUT);
    f12_kernel<<<M_ / 8, 256>>>(W2h, W2l, a1_o, a2_o,
                                eu1b, ev1b, eu2b, ev2b, M_, M_);
    dstats_kernel<<<(B_ * N_) / 8, 256>>>(eu1b, ev1b, eu2b, ev2b, mask, dinb, 1);
    attn_mma_kernel<1, true><<<dim3(N_ / 64, B_), 512, ATTN_SMEM>>>(
        W2h, W2l, eu1b, ev1b, eu2b, ev2b, dinb, mask, nullptr, nullptr, out);
}

// round 10
// speedup vs baseline: 2.0854x; 1.1505x over previous
#include <cuda_runtime.h>
#include <cuda_fp16.h>
#include <math.h>
#include <stdint.h>

#define B_  32
#define N_  512
#define DIN 768
#define DOUT 256
#define H_  8
#define M_  (B_ * N_)

// ---------------- device scratch ----------------
__device__ __half g_xh [(size_t)M_ * DIN];
__device__ __half g_w0h[(size_t)H_ * DOUT * DIN];
__device__ __half g_w0l[(size_t)H_ * DOUT * DIN];
__device__ __half g_Whh[(size_t)H_ * M_ * DOUT];
__device__ __half g_Whl[(size_t)H_ * M_ * DOUT];
__device__ uint32_t g_mask[(size_t)B_ * N_ * 16];
__device__ float  g_eu1[H_ * M_];
__device__ float  g_ev1[H_ * M_];
__device__ float  g_eu2[H_ * M_];
__device__ float  g_ev2[H_ * M_];
__device__ float  g_din[H_ * M_];
__device__ __half g_hmh[(size_t)M_ * DOUT];
__device__ __half g_woh[(size_t)DOUT * DOUT];
__device__ __half g_wol[(size_t)DOUT * DOUT];
__device__ __half g_W2h[(size_t)M_ * DOUT];
__device__ __half g_W2l[(size_t)M_ * DOUT];
__device__ float  g_eu1b[M_];
__device__ float  g_ev1b[M_];
__device__ float  g_eu2b[M_];
__device__ float  g_ev2b[M_];
__device__ float  g_dinb[M_];

// ---------------- PTX helpers ----------------
__device__ __forceinline__ uint32_t smem_u32(const void* p) {
    uint32_t a;
    asm("{ .reg .u64 t; cvta.to.shared.u64 t, %1; cvt.u32.u64 %0, t; }" : "=r"(a) : "l"(p));
    return a;
}
__device__ __forceinline__ void cp16(uint32_t d, const void* s) {
    asm volatile("cp.async.cg.shared.global [%0], [%1], 16;" :: "r"(d), "l"(s));
}
#define CP_COMMIT() asm volatile("cp.async.commit_group;")
#define CP_WAIT(n)  asm volatile("cp.async.wait_group %0;" :: "n"(n))

#define LDM_X4(r, addr) \
    asm volatile("ldmatrix.sync.aligned.m8n8.x4.shared.b16 {%0,%1,%2,%3}, [%4];" \
        : "=r"((r)[0]), "=r"((r)[1]), "=r"((r)[2]), "=r"((r)[3]) : "r"(addr))
#define LDM_X2(r, addr) \
    asm volatile("ldmatrix.sync.aligned.m8n8.x2.shared.b16 {%0,%1}, [%2];" \
        : "=r"((r)[0]), "=r"((r)[1]) : "r"(addr))
#define LDM_X2T(r, addr) \
    asm volatile("ldmatrix.sync.aligned.m8n8.x2.trans.shared.b16 {%0,%1}, [%2];" \
        : "=r"((r)[0]), "=r"((r)[1]) : "r"(addr))

__device__ __forceinline__ void mma_f16(float* c, const uint32_t* a, const uint32_t* b) {
    asm volatile("mma.sync.aligned.m16n8k16.row.col.f32.f16.f16.f32 "
        "{%0,%1,%2,%3}, {%4,%5,%6,%7}, {%8,%9}, {%0,%1,%2,%3};"
        : "+f"(c[0]), "+f"(c[1]), "+f"(c[2]), "+f"(c[3])
        : "r"(a[0]), "r"(a[1]), "r"(a[2]), "r"(a[3]), "r"(b[0]), "r"(b[1]));
}

// ---------------- conversion kernels ----------------
__global__ __launch_bounds__(256) void hi_kernel(
    const float* __restrict__ src, __half* __restrict__ hi, int n4)
{
    int i = blockIdx.x * 256 + threadIdx.x;
    if (i >= n4) return;
    float4 v = ((const float4*)src)[i];
    ((__half2*)hi)[2 * i]     = __halves2half2(__float2half(v.x), __float2half(v.y));
    ((__half2*)hi)[2 * i + 1] = __halves2half2(__float2half(v.z), __float2half(v.w));
}

__global__ __launch_bounds__(256) void wsplit_kernel(
    const float* __restrict__ W, __half* __restrict__ bh,
    __half* __restrict__ bl, int Kd, int Nd)
{
    int z = blockIdx.z;
    int i = blockIdx.x * 256 + threadIdx.x;
    if (i >= Kd * Nd) return;
    int n = i / Kd, k = i % Kd;
    float v = W[(size_t)z * Kd * Nd + (size_t)k * Nd + n];
    __half h = __float2half(v);
    bh[(size_t)z * Kd * Nd + i] = h;
    bl[(size_t)z * Kd * Nd + i] = __float2half(v - __half2float(h));
}

// ---------------- pack adjacency ----------------
__global__ __launch_bounds__(256) void packadj_kernel(
    const int* __restrict__ adj, uint32_t* __restrict__ mask)
{
    int row  = (blockIdx.x * 256 + threadIdx.x) >> 5;
    int lane = threadIdx.x & 31;
    if (row >= B_ * N_) return;
    const int* ar = adj + (size_t)row * N_;
    #pragma unroll
    for (int q = 0; q < 16; ++q) {
        uint32_t w = __ballot_sync(0xffffffffu, ar[q * 32 + lane] > 0);
        if (lane == q) mask[row * 16 + q] = w;
    }
}

// ================= HMMA 2-term GEMM: C = Ah @ (Bh+Bl)^T =================
// smem: 3 tiles [128][40] half per stage; stage 30720B, 2 stages 61440B.
#define GEMM_SMEM (2 * 30720)

__global__ __launch_bounds__(256, 2) void gemm_mma_kernel(
    const __half* __restrict__ Ah,
    const __half* __restrict__ Bh, const __half* __restrict__ Bl,
    __half* __restrict__ Chh, __half* __restrict__ Chl, int K, int Nt)
{
    extern __shared__ __align__(128) char sm[];
    const uint32_t sb = smem_u32(sm);
    const int t = threadIdx.x, lane = t & 31, wid = t >> 5;
    const int m0 = blockIdx.x * 128, f0 = blockIdx.y * 128, z = blockIdx.z;
    const int warp_m = wid & 1, warp_n = wid >> 1;

    const __half* As_h = Ah + (size_t)m0 * K;
    const __half* Bs_h = Bh + (size_t)z * Nt * K + (size_t)f0 * K;
    const __half* Bs_l = Bl + (size_t)z * Nt * K + (size_t)f0 * K;
    __half* Ch = Chh + (size_t)z * M_ * Nt;
    __half* Cl = Chl + (size_t)z * M_ * Nt;

    float acc[4][4][4];
    #pragma unroll
    for (int a = 0; a < 4; ++a)
        #pragma unroll
        for (int b = 0; b < 4; ++b)
            #pragma unroll
            for (int c = 0; c < 4; ++c) acc[a][b][c] = 0.0f;

    const int row = t >> 1, half = t & 1;
    auto prefetch = [&](int c, int s) {
        const int kc = c * 32;
        const __half* srcs[3] = { As_h + kc, Bs_h + kc, Bs_l + kc };
        #pragma unroll
        for (int tile = 0; tile < 3; ++tile) {
            uint32_t dst = sb + s * 30720 + tile * 10240 + row * 80 + half * 32;
            const __half* src = srcs[tile] + (size_t)row * K + half * 16;
            cp16(dst, src);
            cp16(dst + 16, src + 8);
        }
        CP_COMMIT();
    };

    const int NC = K >> 5;
    prefetch(0, 0);
    for (int c = 0; c < NC; ++c) {
        const int s = c & 1;
        if (c + 1 < NC) { prefetch(c + 1, s ^ 1); CP_WAIT(1); }
        else CP_WAIT(0);
        __syncthreads();

        const uint32_t bAh = sb + s * 30720;
        const uint32_t bBh = bAh + 10240;
        const uint32_t bBl = bAh + 20480;
        #pragma unroll
        for (int k16 = 0; k16 < 2; ++k16) {
            const int kc = k16 * 16;
            uint32_t ah[4][4];
            #pragma unroll
            for (int mf = 0; mf < 4; ++mf) {
                uint32_t off = (uint32_t)((warp_m * 64 + mf * 16 + (lane & 15)) * 80
                                          + (kc + ((lane >> 4) << 3)) * 2);
                LDM_X4(ah[mf], bAh + off);
            }
            #pragma unroll
            for (int nf = 0; nf < 4; ++nf) {
                uint32_t boff = (uint32_t)((warp_n * 32 + nf * 8 + (lane & 7)) * 80
                                           + (kc + (((lane >> 3) & 1) << 3)) * 2);
                uint32_t bh[2], bl[2];
                LDM_X2(bh, bBh + boff);
                LDM_X2(bl, bBl + boff);
                #pragma unroll
                for (int mf = 0; mf < 4; ++mf) {
                    mma_f16(acc[mf][nf], ah[mf], bh);
                    mma_f16(acc[mf][nf], ah[mf], bl);
                }
            }
        }
        __syncthreads();
    }

    #pragma unroll
    for (int mf = 0; mf < 4; ++mf)
        #pragma unroll
        for (int nf = 0; nf < 4; ++nf) {
            int r0 = m0 + warp_m * 64 + mf * 16 + (lane >> 2);
            int col = f0 + warp_n * 32 + nf * 8 + (lane & 3) * 2;
            #pragma unroll
            for (int hh = 0; hh < 2; ++hh) {
                float c0 = acc[mf][nf][hh * 2], c1 = acc[mf][nf][hh * 2 + 1];
                int r = r0 + hh * 8;
                __half h0 = __float2half(c0), h1 = __float2half(c1);
                *(__half2*)(Ch + (size_t)r * Nt + col) = __halves2half2(h0, h1);
                *(__half2*)(Cl + (size_t)r * Nt + col) = __halves2half2(
                    __float2half(c0 - __half2float(h0)),
                    __float2half(c1 - __half2float(h1)));
            }
        }
}

// ---------------- f1/f2 -> factored exponentials ----------------
__global__ __launch_bounds__(256) void f12_kernel(
    const __half* __restrict__ Whh, const __half* __restrict__ Whl,
    const float* __restrict__ a1, const float* __restrict__ a2,
    float* __restrict__ eu1, float* __restrict__ ev1,
    float* __restrict__ eu2, float* __restrict__ ev2,
    int rows, int Mper)
{
    int warp = (blockIdx.x * blockDim.x + threadIdx.x) >> 5;
    int lane = threadIdx.x & 31;
    if (warp >= rows) return;
    int h = warp / Mper;
    const __half* rh = Whh + (size_t)warp * DOUT;
    const __half* rl = Whl + (size_t)warp * DOUT;
    const float* a1h = a1 + h * DOUT;
    const float* a2h = a2 + h * DOUT;
    float s1 = 0.0f, s2 = 0.0f;
    #pragma unroll
    for (int f = lane; f < DOUT; f += 32) {
        float v = __half2float(rh[f]) + __half2float(rl[f]);
        s1 = fmaf(v, a1h[f], s1);
        s2 = fmaf(v, a2h[f], s2);
    }
    #pragma unroll
    for (int off = 16; off; off >>= 1) {
        s1 += __shfl_xor_sync(0xffffffffu, s1, off);
        s2 += __shfl_xor_sync(0xffffffffu, s2, off);
    }
    if (lane == 0) {
        eu1[warp] = __expf(s1);
        ev1[warp] = __expf(0.2f * s1);
        eu2[warp] = __expf(s2);
        ev2[warp] = __expf(0.2f * s2);
    }
}

// ---------------- denominator ----------------
__global__ __launch_bounds__(256) void dstats_kernel(
    const float* __restrict__ eu1, const float* __restrict__ ev1,
    const float* __restrict__ eu2, const float* __restrict__ ev2,
    const uint32_t* __restrict__ mask, float* __restrict__ dinv, int NH)
{
    int row  = (blockIdx.x * 256 + threadIdx.x) >> 5;
    int lane = threadIdx.x & 31;
    if (row >= B_ * N_) return;
    int b = row >> 9;
    uint32_t myw = (lane < 16) ? mask[row * 16 + lane] : 0u;

    for (int h = 0; h < NH; ++h) {
        size_t hb = (size_t)h * B_ + b;
        size_t r  = hb * N_ + (row & (N_ - 1));
        float u1 = eu1[r], v1 = ev1[r];
        const float* euh = eu2 + hb * N_;
        const float* evh = ev2 + hb * N_;
        float s = 0.0f;
        #pragma unroll
        for (int q = 0; q < 16; ++q) {
            uint32_t w = __shfl_sync(0xffffffffu, myw, q);
            int m = q * 32 + lane;
            float tt = u1 * euh[m];
            float t2 = v1 * evh[m];
            float E = tt >= 1.0f ? tt : t2;
            s += ((w >> lane) & 1u) ? E : 0.0f;
        }
        #pragma unroll
        for (int off = 16; off; off >>= 1)
            s += __shfl_xor_sync(0xffffffffu, s, off);
        if (lane == 0) dinv[r] = s > 0.0f ? 1.0f / s : 0.0f;
    }
}

// ================= HMMA attention: on-the-fly P, 2 MMAs =================
#define ATTN_SMEM (19456 + 67584)

template<int NHEADS, bool FINAL>
__global__ __launch_bounds__(512, 1) void attn_mma_kernel(
    const __half* __restrict__ Whh, const __half* __restrict__ Whl,
    const float* __restrict__ eu1, const float* __restrict__ ev1,
    const float* __restrict__ eu2, const float* __restrict__ ev2,
    const float* __restrict__ dinv, const uint32_t* __restrict__ gmask,
    __half* __restrict__ outh, float* __restrict__ outf)
{
    extern __shared__ __align__(128) char sm[];
    const uint32_t sb = smem_u32(sm);
    uint32_t* sadj = (uint32_t*)sm;
    float* seu  = (float*)(sm + 4096);
    float* sev  = (float*)(sm + 6144);
    float* su1  = (float*)(sm + 8192);
    float* sv1  = (float*)(sm + 8448);
    float* sinv = (float*)(sm + 8704);
    const uint32_t smP = sb + 9216;
    const uint32_t smW = sb + 19456;

    const int t = threadIdx.x, lane = t & 31, wid = t >> 5;
    const int n0 = blockIdx.x * 64;
    const int b  = blockIdx.y;
    const int warp_n = wid & 1, warp_f = wid >> 1;

    {
        int i0 = t;
        sadj[i0] = gmask[((size_t)b * N_ + n0 + (i0 >> 4)) * 16 + (i0 & 15)];
        int i1 = t + 512;
        sadj[i1] = gmask[((size_t)b * N_ + n0 + (i1 >> 4)) * 16 + (i1 & 15)];
    }

    const int pi  = t >> 3;
    const int pk4 = (t & 7) * 4;
    const int hl   = t >> 8;
    const int idx  = t & 255;
    const int wrow = idx >> 3, wseg = idx & 7;

    float sum[2][4][4];
    #pragma unroll
    for (int a = 0; a < 2; ++a)
        #pragma unroll
        for (int c = 0; c < 4; ++c)
            #pragma unroll
            for (int d = 0; d < 4; ++d) sum[a][c][d] = 0.0f;

    for (int h = 0; h < NHEADS; ++h) {
        const size_t hb = (size_t)h * B_ + b;
        const __half* Wsh = Whh + hb * (size_t)N_ * DOUT;
        const __half* Wsl = Whl + hb * (size_t)N_ * DOUT;

        __syncthreads();
        seu[t & 511] = eu2[hb * N_ + (t & 511)];
        sev[t & 511] = ev2[hb * N_ + (t & 511)];
        if (t < 64) {
            su1[t]  = eu1[hb * N_ + n0 + t];
            sv1[t]  = ev1[hb * N_ + n0 + t];
            sinv[t] = dinv[hb * N_ + n0 + t];
        }
        __syncthreads();

        float acc[2][4][4];
        #pragma unroll
        for (int a = 0; a < 2; ++a)
            #pragma unroll
            for (int c = 0; c < 4; ++c)
                #pragma unroll
                for (int d = 0; d < 4; ++d) acc[a][c][d] = 0.0f;

        auto computeP = [&](int c, int st) {
            const int m0 = c * 32;
            float u1 = su1[pi], v1 = sv1[pi], inv = sinv[pi];
            uint32_t w = sadj[pi * 16 + c];
            __half hs[4];
            #pragma unroll
            for (int kk = 0; kk < 4; ++kk) {
                int mm = m0 + pk4 + kk;
                float tt = u1 * seu[mm];
                float t2 = v1 * sev[mm];
                float E  = tt >= 1.0f ? tt : t2;
                float p  = ((w >> (pk4 + kk)) & 1u) ? E * inv : 0.0f;
                hs[kk] = __float2half(p);
            }
            char* dh = sm + 9216 + st * 5120 + pi * 80 + pk4 * 2;
            ((__half2*)dh)[0] = __halves2half2(hs[0], hs[1]);
            ((__half2*)dh)[1] = __halves2half2(hs[2], hs[3]);
        };
        auto prefetchW = [&](int c, int st) {
            const int m0 = c * 32;
            const __half* src = (hl ? Wsl : Wsh) + (size_t)(m0 + wrow) * DOUT;
            uint32_t dst = smW + st * 33792 + hl * 16896 + wrow * 528;
            #pragma unroll
            for (int j = 0; j < 4; ++j) {
                int s8 = wseg + j * 8;
                cp16(dst + s8 * 16, src + s8 * 8);
            }
            CP_COMMIT();
        };

        computeP(0, 0);
        prefetchW(0, 0);
        for (int c = 0; c < 16; ++c) {
            const int st = c & 1;
            if (c < 15) {
                prefetchW(c + 1, st ^ 1);
                computeP(c + 1, st ^ 1);
                CP_WAIT(1);
            } else CP_WAIT(0);
            __syncthreads();

            const uint32_t Phs = smP + st * 5120;
            const uint32_t Whs = smW + st * 33792;
            const uint32_t Wls = Whs + 16896;
            #pragma unroll
            for (int k16 = 0; k16 < 2; ++k16) {
                const int kc = k16 * 16;
                uint32_t ah[2][4];
                #pragma unroll
                for (int mf = 0; mf < 2; ++mf) {
                    uint32_t off = (uint32_t)((warp_n * 32 + mf * 16 + (lane & 15)) * 80
                                              + (kc + ((lane >> 4) << 3)) * 2);
                    LDM_X4(ah[mf], Phs + off);
                }
                #pragma unroll
                for (int nf = 0; nf < 4; ++nf) {
                    uint32_t woff = (uint32_t)((kc + (lane & 15)) * 528
                                               + (warp_f * 32 + nf * 8) * 2);
                    uint32_t bh[2], bl[2];
                    LDM_X2T(bh, Whs + woff);
                    LDM_X2T(bl, Wls + woff);
                    #pragma unroll
                    for (int mf = 0; mf < 2; ++mf) {
                        mma_f16(acc[mf][nf], ah[mf], bh);
                        mma_f16(acc[mf][nf], ah[mf], bl);
                    }
                }
            }
            __syncthreads();
        }

        if (FINAL) {
            #pragma unroll
            for (int a = 0; a < 2; ++a)
                #pragma unroll
                for (int c = 0; c < 4; ++c)
                    #pragma unroll
                    for (int d = 0; d < 4; ++d) sum[a][c][d] = acc[a][c][d];
        } else {
            #pragma unroll
            for (int a = 0; a < 2; ++a)
                #pragma unroll
                for (int c = 0; c < 4; ++c)
                    #pragma unroll
                    for (int d = 0; d < 4; ++d) {
                        float v = acc[a][c][d];
                        sum[a][c][d] += (v > 0.0f) ? v : expm1f(v);
                    }
        }
    }

    #pragma unroll
    for (int mf = 0; mf < 2; ++mf)
        #pragma unroll
        for (int nf = 0; nf < 4; ++nf) {
            int r0  = n0 + warp_n * 32 + mf * 16 + (lane >> 2);
            int col = warp_f * 32 + nf * 8 + (lane & 3) * 2;
            #pragma unroll
            for (int hh2 = 0; hh2 < 2; ++hh2) {
                int r = r0 + hh2 * 8;
                float c0 = sum[mf][nf][hh2 * 2], c1 = sum[mf][nf][hh2 * 2 + 1];
                if (FINAL) {
                    float2 v = { fmaxf(c0, 0.0f), fmaxf(c1, 0.0f) };
                    *(float2*)(outf + ((size_t)b * N_ + r) * DOUT + col) = v;
                } else {
                    c0 *= 0.125f; c1 *= 0.125f;
                    *(__half2*)(outh + ((size_t)b * N_ + r) * DOUT + col) =
                        __halves2half2(__float2half(c0), __float2half(c1));
                }
            }
        }
}

// ---------------- launch ----------------
extern "C" void kernel_launch(void* const* d_in, const int* in_sizes, int n_in,
                              void* d_out, int out_size)
{
    const float* x    = (const float*)d_in[0];
    const int*   adj  = (const int*)  d_in[1];
    const float* W0   = (const float*)d_in[2];
    const float* a1_0 = (const float*)d_in[3];
    const float* a2_0 = (const float*)d_in[4];
    const float* Wo   = (const float*)d_in[5];
    const float* a1_o = (const float*)d_in[6];
    const float* a2_o = (const float*)d_in[7];
    float* out = (float*)d_out;

    __half *xh, *w0h, *w0l, *Whh, *Whl, *hmh, *woh, *wol, *W2h, *W2l;
    float *eu1, *ev1, *eu2, *ev2, *din, *eu1b, *ev1b, *eu2b, *ev2b, *dinb;
    uint32_t* mask;
    cudaGetSymbolAddress((void**)&xh,  g_xh);
    cudaGetSymbolAddress((void**)&w0h, g_w0h);
    cudaGetSymbolAddress((void**)&w0l, g_w0l);
    cudaGetSymbolAddress((void**)&Whh, g_Whh);
    cudaGetSymbolAddress((void**)&Whl, g_Whl);
    cudaGetSymbolAddress((void**)&mask, g_mask);
    cudaGetSymbolAddress((void**)&eu1, g_eu1);
    cudaGetSymbolAddress((void**)&ev1, g_ev1);
    cudaGetSymbolAddress((void**)&eu2, g_eu2);
    cudaGetSymbolAddress((void**)&ev2, g_ev2);
    cudaGetSymbolAddress((void**)&din, g_din);
    cudaGetSymbolAddress((void**)&hmh, g_hmh);
    cudaGetSymbolAddress((void**)&woh, g_woh);
    cudaGetSymbolAddress((void**)&wol, g_wol);
    cudaGetSymbolAddress((void**)&W2h, g_W2h);
    cudaGetSymbolAddress((void**)&W2l, g_W2l);
    cudaGetSymbolAddress((void**)&eu1b, g_eu1b);
    cudaGetSymbolAddress((void**)&ev1b, g_ev1b);
    cudaGetSymbolAddress((void**)&eu2b, g_eu2b);
    cudaGetSymbolAddress((void**)&ev2b, g_ev2b);
    cudaGetSymbolAddress((void**)&dinb, g_dinb);

    cudaFuncSetAttribute(gemm_mma_kernel,
        cudaFuncAttributeMaxDynamicSharedMemorySize, GEMM_SMEM);
    cudaFuncSetAttribute(attn_mma_kernel<H_, false>,
        cudaFuncAttributeMaxDynamicSharedMemorySize, ATTN_SMEM);
    cudaFuncSetAttribute(attn_mma_kernel<1, true>,
        cudaFuncAttributeMaxDynamicSharedMemorySize, ATTN_SMEM);

    // ---- layer 1 ----
    packadj_kernel<<<(B_ * N_) / 8, 256>>>(adj, mask);
    hi_kernel<<<(M_ * DIN / 4 + 255) / 256, 256>>>(x, xh, M_ * DIN / 4);
    wsplit_kernel<<<dim3((DIN * DOUT + 255) / 256, 1, H_), 256>>>(W0, w0h, w0l, DIN, DOUT);
    gemm_mma_kernel<<<dim3(M_ / 128, DOUT / 128, H_), 256, GEMM_SMEM>>>(
        xh, w0h, w0l, Whh, Whl, DIN, DOUT);
    f12_kernel<<<(H_ * M_) / 8, 256>>>(Whh, Whl, a1_0, a2_0,
                                       eu1, ev1, eu2, ev2, H_ * M_, M_);
    dstats_kernel<<<(B_ * N_) / 8, 256>>>(eu1, ev1, eu2, ev2, mask, din, H_);
    attn_mma_kernel<H_, false><<<dim3(N_ / 64, B_), 512, ATTN_SMEM>>>(
        Whh, Whl, eu1, ev1, eu2, ev2, din, mask, hmh, nullptr);

    // ---- layer 2 ----
    wsplit_kernel<<<dim3((DOUT * DOUT + 255) / 256, 1, 1), 256>>>(Wo, woh, wol, DOUT, DOUT);
    gemm_mma_kernel<<<dim3(M_ / 128, DOUT / 128, 1), 256, GEMM_SMEM>>>(
        hmh, woh, wol, W2h, W2l, DOUT, DOUT);
    f12_kernel<<<M_ / 8, 256>>>(W2h, W2l, a1_o, a2_o,
                                eu1b, ev1b, eu2b, ev2b, M_, M_);
    dstats_kernel<<<(B_ * N_) / 8, 256>>>(eu1b, ev1b, eu2b, ev2b, mask, dinb, 1);
    attn_mma_kernel<1, true><<<dim3(N_ / 64, B_), 512, ATTN_SMEM>>>(
        W2h, W2l, eu1b, ev1b, eu2b, ev2b, dinb, mask, nullptr, out);
}

// round 11
// speedup vs baseline: 2.4143x; 1.1577x over previous
#include <cuda_runtime.h>
#include <cuda_fp16.h>
#include <math.h>
#include <stdint.h>

#define B_  32
#define N_  512
#define DIN 768
#define DOUT 256
#define H_  8
#define M_  (B_ * N_)

// ---------------- device scratch ----------------
__device__ __half g_xh [(size_t)M_ * DIN];
__device__ __half g_w0h[(size_t)H_ * DOUT * DIN];
__device__ __half g_w0l[(size_t)H_ * DOUT * DIN];
__device__ __half g_Whh[(size_t)H_ * M_ * DOUT];
__device__ __half g_Whl[(size_t)H_ * M_ * DOUT];
__device__ uint32_t g_mask[(size_t)B_ * N_ * 16];
__device__ float  g_eu1[H_ * M_];
__device__ float  g_ev1[H_ * M_];
__device__ float  g_eu2[H_ * M_];
__device__ float  g_ev2[H_ * M_];
__device__ float  g_din[H_ * M_];
__device__ __half g_hmh[(size_t)M_ * DOUT];
__device__ __half g_woh[(size_t)DOUT * DOUT];
__device__ __half g_wol[(size_t)DOUT * DOUT];
__device__ __half g_W2h[(size_t)M_ * DOUT];
__device__ __half g_W2l[(size_t)M_ * DOUT];
__device__ float  g_eu1b[M_];
__device__ float  g_ev1b[M_];
__device__ float  g_eu2b[M_];
__device__ float  g_ev2b[M_];
__device__ float  g_dinb[M_];

// ---------------- PTX helpers ----------------
__device__ __forceinline__ uint32_t smem_u32(const void* p) {
    uint32_t a;
    asm("{ .reg .u64 t; cvta.to.shared.u64 t, %1; cvt.u32.u64 %0, t; }" : "=r"(a) : "l"(p));
    return a;
}
__device__ __forceinline__ void cp16(uint32_t d, const void* s) {
    asm volatile("cp.async.cg.shared.global [%0], [%1], 16;" :: "r"(d), "l"(s));
}
#define CP_COMMIT() asm volatile("cp.async.commit_group;")
#define CP_WAIT(n)  asm volatile("cp.async.wait_group %0;" :: "n"(n))

#define LDM_X4(r, addr) \
    asm volatile("ldmatrix.sync.aligned.m8n8.x4.shared.b16 {%0,%1,%2,%3}, [%4];" \
        : "=r"((r)[0]), "=r"((r)[1]), "=r"((r)[2]), "=r"((r)[3]) : "r"(addr))
#define LDM_X2(r, addr) \
    asm volatile("ldmatrix.sync.aligned.m8n8.x2.shared.b16 {%0,%1}, [%2];" \
        : "=r"((r)[0]), "=r"((r)[1]) : "r"(addr))
#define LDM_X2T(r, addr) \
    asm volatile("ldmatrix.sync.aligned.m8n8.x2.trans.shared.b16 {%0,%1}, [%2];" \
        : "=r"((r)[0]), "=r"((r)[1]) : "r"(addr))

__device__ __forceinline__ void mma_f16(float* c, const uint32_t* a, const uint32_t* b) {
    asm volatile("mma.sync.aligned.m16n8k16.row.col.f32.f16.f16.f32 "
        "{%0,%1,%2,%3}, {%4,%5,%6,%7}, {%8,%9}, {%0,%1,%2,%3};"
        : "+f"(c[0]), "+f"(c[1]), "+f"(c[2]), "+f"(c[3])
        : "r"(a[0]), "r"(a[1]), "r"(a[2]), "r"(a[3]), "r"(b[0]), "r"(b[1]));
}

// ---------------- conversion kernels ----------------
__global__ __launch_bounds__(256) void hi_kernel(
    const float* __restrict__ src, __half* __restrict__ hi, int n4)
{
    int i = blockIdx.x * 256 + threadIdx.x;
    if (i >= n4) return;
    float4 v = ((const float4*)src)[i];
    ((__half2*)hi)[2 * i]     = __halves2half2(__float2half(v.x), __float2half(v.y));
    ((__half2*)hi)[2 * i + 1] = __halves2half2(__float2half(v.z), __float2half(v.w));
}

__global__ __launch_bounds__(256) void wsplit_kernel(
    const float* __restrict__ W, __half* __restrict__ bh,
    __half* __restrict__ bl, int Kd, int Nd)
{
    int z = blockIdx.z;
    int i = blockIdx.x * 256 + threadIdx.x;
    if (i >= Kd * Nd) return;
    int n = i / Kd, k = i % Kd;
    float v = W[(size_t)z * Kd * Nd + (size_t)k * Nd + n];
    __half h = __float2half(v);
    bh[(size_t)z * Kd * Nd + i] = h;
    bl[(size_t)z * Kd * Nd + i] = __float2half(v - __half2float(h));
}

// ---------------- pack adjacency ----------------
__global__ __launch_bounds__(256) void packadj_kernel(
    const int* __restrict__ adj, uint32_t* __restrict__ mask)
{
    int row  = (blockIdx.x * 256 + threadIdx.x) >> 5;
    int lane = threadIdx.x & 31;
    if (row >= B_ * N_) return;
    const int* ar = adj + (size_t)row * N_;
    #pragma unroll
    for (int q = 0; q < 16; ++q) {
        uint32_t w = __ballot_sync(0xffffffffu, ar[q * 32 + lane] > 0);
        if (lane == q) mask[row * 16 + q] = w;
    }
}

// ================= HMMA 2-term GEMM, 3-stage pipeline =================
// smem: 3 tiles [128][40] half per stage; stage 30720B, 3 stages 92160B.
#define GEMM_SMEM (3 * 30720)

__global__ __launch_bounds__(256, 2) void gemm_mma_kernel(
    const __half* __restrict__ Ah,
    const __half* __restrict__ Bh, const __half* __restrict__ Bl,
    __half* __restrict__ Chh, __half* __restrict__ Chl, int K, int Nt)
{
    extern __shared__ __align__(128) char sm[];
    const uint32_t sb = smem_u32(sm);
    const int t = threadIdx.x, lane = t & 31, wid = t >> 5;
    const int m0 = blockIdx.x * 128, f0 = blockIdx.y * 128, z = blockIdx.z;
    const int warp_m = wid & 1, warp_n = wid >> 1;

    const __half* As_h = Ah + (size_t)m0 * K;
    const __half* Bs_h = Bh + (size_t)z * Nt * K + (size_t)f0 * K;
    const __half* Bs_l = Bl + (size_t)z * Nt * K + (size_t)f0 * K;
    __half* Ch = Chh + (size_t)z * M_ * Nt;
    __half* Cl = Chl + (size_t)z * M_ * Nt;

    float acc[4][4][4];
    #pragma unroll
    for (int a = 0; a < 4; ++a)
        #pragma unroll
        for (int b = 0; b < 4; ++b)
            #pragma unroll
            for (int c = 0; c < 4; ++c) acc[a][b][c] = 0.0f;

    const int row = t >> 1, half = t & 1;
    auto prefetch = [&](int c, int s) {
        const int kc = c * 32;
        const __half* srcs[3] = { As_h + kc, Bs_h + kc, Bs_l + kc };
        #pragma unroll
        for (int tile = 0; tile < 3; ++tile) {
            uint32_t dst = sb + s * 30720 + tile * 10240 + row * 80 + half * 32;
            const __half* src = srcs[tile] + (size_t)row * K + half * 16;
            cp16(dst, src);
            cp16(dst + 16, src + 8);
        }
        CP_COMMIT();
    };

    const int NC = K >> 5;
    prefetch(0, 0);
    prefetch(1, 1);
    int st = 0;
    for (int c = 0; c < NC; ++c) {
        if (c + 2 < NC) {
            int s2 = st + 2; if (s2 >= 3) s2 -= 3;
            prefetch(c + 2, s2);
        } else CP_COMMIT();
        CP_WAIT(2);
        __syncthreads();

        const uint32_t bAh = sb + st * 30720;
        const uint32_t bBh = bAh + 10240;
        const uint32_t bBl = bAh + 20480;
        #pragma unroll
        for (int k16 = 0; k16 < 2; ++k16) {
            const int kc = k16 * 16;
            uint32_t ah[4][4];
            #pragma unroll
            for (int mf = 0; mf < 4; ++mf) {
                uint32_t off = (uint32_t)((warp_m * 64 + mf * 16 + (lane & 15)) * 80
                                          + (kc + ((lane >> 4) << 3)) * 2);
                LDM_X4(ah[mf], bAh + off);
            }
            #pragma unroll
            for (int nf = 0; nf < 4; ++nf) {
                uint32_t boff = (uint32_t)((warp_n * 32 + nf * 8 + (lane & 7)) * 80
                                           + (kc + (((lane >> 3) & 1) << 3)) * 2);
                uint32_t bh[2], bl[2];
                LDM_X2(bh, bBh + boff);
                LDM_X2(bl, bBl + boff);
                #pragma unroll
                for (int mf = 0; mf < 4; ++mf) {
                    mma_f16(acc[mf][nf], ah[mf], bh);
                    mma_f16(acc[mf][nf], ah[mf], bl);
                }
            }
        }
        __syncthreads();
        if (++st == 3) st = 0;
    }

    #pragma unroll
    for (int mf = 0; mf < 4; ++mf)
        #pragma unroll
        for (int nf = 0; nf < 4; ++nf) {
            int r0 = m0 + warp_m * 64 + mf * 16 + (lane >> 2);
            int col = f0 + warp_n * 32 + nf * 8 + (lane & 3) * 2;
            #pragma unroll
            for (int hh = 0; hh < 2; ++hh) {
                float c0 = acc[mf][nf][hh * 2], c1 = acc[mf][nf][hh * 2 + 1];
                int r = r0 + hh * 8;
                __half h0 = __float2half(c0), h1 = __float2half(c1);
                *(__half2*)(Ch + (size_t)r * Nt + col) = __halves2half2(h0, h1);
                *(__half2*)(Cl + (size_t)r * Nt + col) = __halves2half2(
                    __float2half(c0 - __half2float(h0)),
                    __float2half(c1 - __half2float(h1)));
            }
        }
}

// ---------------- f1/f2 -> factored exponentials ----------------
__global__ __launch_bounds__(256) void f12_kernel(
    const __half* __restrict__ Whh, const __half* __restrict__ Whl,
    const float* __restrict__ a1, const float* __restrict__ a2,
    float* __restrict__ eu1, float* __restrict__ ev1,
    float* __restrict__ eu2, float* __restrict__ ev2,
    int rows, int Mper)
{
    int warp = (blockIdx.x * blockDim.x + threadIdx.x) >> 5;
    int lane = threadIdx.x & 31;
    if (warp >= rows) return;
    int h = warp / Mper;
    const __half* rh = Whh + (size_t)warp * DOUT;
    const __half* rl = Whl + (size_t)warp * DOUT;
    const float* a1h = a1 + h * DOUT;
    const float* a2h = a2 + h * DOUT;
    float s1 = 0.0f, s2 = 0.0f;
    #pragma unroll
    for (int f = lane; f < DOUT; f += 32) {
        float v = __half2float(rh[f]) + __half2float(rl[f]);
        s1 = fmaf(v, a1h[f], s1);
        s2 = fmaf(v, a2h[f], s2);
    }
    #pragma unroll
    for (int off = 16; off; off >>= 1) {
        s1 += __shfl_xor_sync(0xffffffffu, s1, off);
        s2 += __shfl_xor_sync(0xffffffffu, s2, off);
    }
    if (lane == 0) {
        eu1[warp] = __expf(s1);
        ev1[warp] = __expf(0.2f * s1);
        eu2[warp] = __expf(s2);
        ev2[warp] = __expf(0.2f * s2);
    }
}

// ---------------- denominator ----------------
__global__ __launch_bounds__(256) void dstats_kernel(
    const float* __restrict__ eu1, const float* __restrict__ ev1,
    const float* __restrict__ eu2, const float* __restrict__ ev2,
    const uint32_t* __restrict__ mask, float* __restrict__ dinv, int NH)
{
    int row  = (blockIdx.x * 256 + threadIdx.x) >> 5;
    int lane = threadIdx.x & 31;
    if (row >= B_ * N_) return;
    int b = row >> 9;
    uint32_t myw = (lane < 16) ? mask[row * 16 + lane] : 0u;

    for (int h = 0; h < NH; ++h) {
        size_t hb = (size_t)h * B_ + b;
        size_t r  = hb * N_ + (row & (N_ - 1));
        float u1 = eu1[r], v1 = ev1[r];
        const float* euh = eu2 + hb * N_;
        const float* evh = ev2 + hb * N_;
        float s = 0.0f;
        #pragma unroll
        for (int q = 0; q < 16; ++q) {
            uint32_t w = __shfl_sync(0xffffffffu, myw, q);
            int m = q * 32 + lane;
            float tt = u1 * euh[m];
            float t2 = v1 * evh[m];
            float E = tt >= 1.0f ? tt : t2;
            s += ((w >> lane) & 1u) ? E : 0.0f;
        }
        #pragma unroll
        for (int off = 16; off; off >>= 1)
            s += __shfl_xor_sync(0xffffffffu, s, off);
        if (lane == 0) dinv[r] = s > 0.0f ? 1.0f / s : 0.0f;
    }
}

// ================= HMMA attention: on-the-fly P, Wh-hi only (1 MMA) =======
// smem: sadj 4096 | seu 2048 | sev 2048 | su1/sv1/sinv 3*256 | pad -> 9216
//       Ps [2 st][64][40]    = 10240   @ 9216
//       Whs [2 st][32][264]  = 33792   @ 19456
#define ATTN_SMEM (19456 + 33792)

template<int NHEADS, bool FINAL>
__global__ __launch_bounds__(512, 1) void attn_mma_kernel(
    const __half* __restrict__ Whh,
    const float* __restrict__ eu1, const float* __restrict__ ev1,
    const float* __restrict__ eu2, const float* __restrict__ ev2,
    const float* __restrict__ dinv, const uint32_t* __restrict__ gmask,
    __half* __restrict__ outh, float* __restrict__ outf)
{
    extern __shared__ __align__(128) char sm[];
    const uint32_t sb = smem_u32(sm);
    uint32_t* sadj = (uint32_t*)sm;
    float* seu  = (float*)(sm + 4096);
    float* sev  = (float*)(sm + 6144);
    float* su1  = (float*)(sm + 8192);
    float* sv1  = (float*)(sm + 8448);
    float* sinv = (float*)(sm + 8704);
    const uint32_t smP = sb + 9216;
    const uint32_t smW = sb + 19456;

    const int t = threadIdx.x, lane = t & 31, wid = t >> 5;
    const int n0 = blockIdx.x * 64;
    const int b  = blockIdx.y;
    const int warp_n = wid & 1, warp_f = wid >> 1;

    {
        int i0 = t;
        sadj[i0] = gmask[((size_t)b * N_ + n0 + (i0 >> 4)) * 16 + (i0 & 15)];
        int i1 = t + 512;
        sadj[i1] = gmask[((size_t)b * N_ + n0 + (i1 >> 4)) * 16 + (i1 & 15)];
    }

    const int pi  = t >> 3;          // 0..63
    const int pk4 = (t & 7) * 4;     // 0..28
    const int wrow = t >> 4;         // 0..31
    const int wseg = t & 15;         // 0..15

    float sum[2][4][4];
    #pragma unroll
    for (int a = 0; a < 2; ++a)
        #pragma unroll
        for (int c = 0; c < 4; ++c)
            #pragma unroll
            for (int d = 0; d < 4; ++d) sum[a][c][d] = 0.0f;

    for (int h = 0; h < NHEADS; ++h) {
        const size_t hb = (size_t)h * B_ + b;
        const __half* Wsh = Whh + hb * (size_t)N_ * DOUT;

        __syncthreads();
        seu[t & 511] = eu2[hb * N_ + (t & 511)];
        sev[t & 511] = ev2[hb * N_ + (t & 511)];
        if (t < 64) {
            su1[t]  = eu1[hb * N_ + n0 + t];
            sv1[t]  = ev1[hb * N_ + n0 + t];
            sinv[t] = dinv[hb * N_ + n0 + t];
        }
        __syncthreads();

        float acc[2][4][4];
        #pragma unroll
        for (int a = 0; a < 2; ++a)
            #pragma unroll
            for (int c = 0; c < 4; ++c)
                #pragma unroll
                for (int d = 0; d < 4; ++d) acc[a][c][d] = 0.0f;

        auto computeP = [&](int c, int st) {
            const int m0 = c * 32;
            float u1 = su1[pi], v1 = sv1[pi], inv = sinv[pi];
            uint32_t w = sadj[pi * 16 + c];
            __half hs[4];
            #pragma unroll
            for (int kk = 0; kk < 4; ++kk) {
                int mm = m0 + pk4 + kk;
                float tt = u1 * seu[mm];
                float t2 = v1 * sev[mm];
                float E  = tt >= 1.0f ? tt : t2;
                float p  = ((w >> (pk4 + kk)) & 1u) ? E * inv : 0.0f;
                hs[kk] = __float2half(p);
            }
            char* dh = sm + 9216 + st * 5120 + pi * 80 + pk4 * 2;
            ((__half2*)dh)[0] = __halves2half2(hs[0], hs[1]);
            ((__half2*)dh)[1] = __halves2half2(hs[2], hs[3]);
        };
        auto prefetchW = [&](int c, int st) {
            const int m0 = c * 32;
            const __half* src = Wsh + (size_t)(m0 + wrow) * DOUT;
            uint32_t dst = smW + st * 16896 + wrow * 528;
            cp16(dst + wseg * 16, src + wseg * 8);
            cp16(dst + (wseg + 16) * 16, src + (wseg + 16) * 8);
            CP_COMMIT();
        };

        computeP(0, 0);
        prefetchW(0, 0);
        for (int c = 0; c < 16; ++c) {
            const int st = c & 1;
            if (c < 15) {
                prefetchW(c + 1, st ^ 1);
                computeP(c + 1, st ^ 1);
                CP_WAIT(1);
            } else CP_WAIT(0);
            __syncthreads();

            const uint32_t Phs = smP + st * 5120;
            const uint32_t Whs = smW + st * 16896;
            #pragma unroll
            for (int k16 = 0; k16 < 2; ++k16) {
                const int kc = k16 * 16;
                uint32_t ah[2][4];
                #pragma unroll
                for (int mf = 0; mf < 2; ++mf) {
                    uint32_t off = (uint32_t)((warp_n * 32 + mf * 16 + (lane & 15)) * 80
                                              + (kc + ((lane >> 4) << 3)) * 2);
                    LDM_X4(ah[mf], Phs + off);
                }
                #pragma unroll
                for (int nf = 0; nf < 4; ++nf) {
                    uint32_t woff = (uint32_t)((kc + (lane & 15)) * 528
                                               + (warp_f * 32 + nf * 8) * 2);
                    uint32_t bh[2];
                    LDM_X2T(bh, Whs + woff);
                    #pragma unroll
                    for (int mf = 0; mf < 2; ++mf)
                        mma_f16(acc[mf][nf], ah[mf], bh);
                }
            }
            __syncthreads();
        }

        if (FINAL) {
            #pragma unroll
            for (int a = 0; a < 2; ++a)
                #pragma unroll
                for (int c = 0; c < 4; ++c)
                    #pragma unroll
                    for (int d = 0; d < 4; ++d) sum[a][c][d] = acc[a][c][d];
        } else {
            #pragma unroll
            for (int a = 0; a < 2; ++a)
                #pragma unroll
                for (int c = 0; c < 4; ++c)
                    #pragma unroll
                    for (int d = 0; d < 4; ++d) {
                        float v = acc[a][c][d];
                        sum[a][c][d] += (v > 0.0f) ? v : expm1f(v);
                    }
        }
    }

    #pragma unroll
    for (int mf = 0; mf < 2; ++mf)
        #pragma unroll
        for (int nf = 0; nf < 4; ++nf) {
            int r0  = n0 + warp_n * 32 + mf * 16 + (lane >> 2);
            int col = warp_f * 32 + nf * 8 + (lane & 3) * 2;
            #pragma unroll
            for (int hh2 = 0; hh2 < 2; ++hh2) {
                int r = r0 + hh2 * 8;
                float c0 = sum[mf][nf][hh2 * 2], c1 = sum[mf][nf][hh2 * 2 + 1];
                if (FINAL) {
                    float2 v = { fmaxf(c0, 0.0f), fmaxf(c1, 0.0f) };
                    *(float2*)(outf + ((size_t)b * N_ + r) * DOUT + col) = v;
                } else {
                    c0 *= 0.125f; c1 *= 0.125f;
                    *(__half2*)(outh + ((size_t)b * N_ + r) * DOUT + col) =
                        __halves2half2(__float2half(c0), __float2half(c1));
                }
            }
        }
}

// ---------------- launch ----------------
extern "C" void kernel_launch(void* const* d_in, const int* in_sizes, int n_in,
                              void* d_out, int out_size)
{
    const float* x    = (const float*)d_in[0];
    const int*   adj  = (const int*)  d_in[1];
    const float* W0   = (const float*)d_in[2];
    const float* a1_0 = (const float*)d_in[3];
    const float* a2_0 = (const float*)d_in[4];
    const float* Wo   = (const float*)d_in[5];
    const float* a1_o = (const float*)d_in[6];
    const float* a2_o = (const float*)d_in[7];
    float* out = (float*)d_out;

    __half *xh, *w0h, *w0l, *Whh, *Whl, *hmh, *woh, *wol, *W2h, *W2l;
    float *eu1, *ev1, *eu2, *ev2, *din, *eu1b, *ev1b, *eu2b, *ev2b, *dinb;
    uint32_t* mask;
    cudaGetSymbolAddress((void**)&xh,  g_xh);
    cudaGetSymbolAddress((void**)&w0h, g_w0h);
    cudaGetSymbolAddress((void**)&w0l, g_w0l);
    cudaGetSymbolAddress((void**)&Whh, g_Whh);
    cudaGetSymbolAddress((void**)&Whl, g_Whl);
    cudaGetSymbolAddress((void**)&mask, g_mask);
    cudaGetSymbolAddress((void**)&eu1, g_eu1);
    cudaGetSymbolAddress((void**)&ev1, g_ev1);
    cudaGetSymbolAddress((void**)&eu2, g_eu2);
    cudaGetSymbolAddress((void**)&ev2, g_ev2);
    cudaGetSymbolAddress((void**)&din, g_din);
    cudaGetSymbolAddress((void**)&hmh, g_hmh);
    cudaGetSymbolAddress((void**)&woh, g_woh);
    cudaGetSymbolAddress((void**)&wol, g_wol);
    cudaGetSymbolAddress((void**)&W2h, g_W2h);
    cudaGetSymbolAddress((void**)&W2l, g_W2l);
    cudaGetSymbolAddress((void**)&eu1b, g_eu1b);
    cudaGetSymbolAddress((void**)&ev1b, g_ev1b);
    cudaGetSymbolAddress((void**)&eu2b, g_eu2b);
    cudaGetSymbolAddress((void**)&ev2b, g_ev2b);
    cudaGetSymbolAddress((void**)&dinb, g_dinb);

    cudaFuncSetAttribute(gemm_mma_kernel,
        cudaFuncAttributeMaxDynamicSharedMemorySize, GEMM_SMEM);
    cudaFuncSetAttribute(attn_mma_kernel<H_, false>,
        cudaFuncAttributeMaxDynamicSharedMemorySize, ATTN_SMEM);
    cudaFuncSetAttribute(attn_mma_kernel<1, true>,
        cudaFuncAttributeMaxDynamicSharedMemorySize, ATTN_SMEM);

    // ---- layer 1 ----
    packadj_kernel<<<(B_ * N_) / 8, 256>>>(adj, mask);
    hi_kernel<<<(M_ * DIN / 4 + 255) / 256, 256>>>(x, xh, M_ * DIN / 4);
    wsplit_kernel<<<dim3((DIN * DOUT + 255) / 256, 1, H_), 256>>>(W0, w0h, w0l, DIN, DOUT);
    gemm_mma_kernel<<<dim3(M_ / 128, DOUT / 128, H_), 256, GEMM_SMEM>>>(
        xh, w0h, w0l, Whh, Whl, DIN, DOUT);
    f12_kernel<<<(H_ * M_) / 8, 256>>>(Whh, Whl, a1_0, a2_0,
                                       eu1, ev1, eu2, ev2, H_ * M_, M_);
    dstats_kernel<<<(B_ * N_) / 8, 256>>>(eu1, ev1, eu2, ev2, mask, din, H_);
    attn_mma_kernel<H_, false><<<dim3(N_ / 64, B_), 512, ATTN_SMEM>>>(
        Whh, eu1, ev1, eu2, ev2, din, mask, hmh, nullptr);

    // ---- layer 2 ----
    wsplit_kernel<<<dim3((DOUT * DOUT + 255) / 256, 1, 1), 256>>>(Wo, woh, wol, DOUT, DOUT);
    gemm_mma_kernel<<<dim3(M_ / 128, DOUT / 128, 1), 256, GEMM_SMEM>>>(
        hmh, woh, wol, W2h, W2l, DOUT, DOUT);
    f12_kernel<<<M_ / 8, 256>>>(W2h, W2l, a1_o, a2_o,
                                eu1b, ev1b, eu2b, ev2b, M_, M_);
    dstats_kernel<<<(B_ * N_) / 8, 256>>>(eu1b, ev1b, eu2b, ev2b, mask, dinb, 1);
    attn_mma_kernel<1, true><<<dim3(N_ / 64, B_), 512, ATTN_SMEM>>>(
        W2h, eu1b, ev1b, eu2b, ev2b, dinb, mask, nullptr, out);
}

// round 12
// speedup vs baseline: 2.4353x; 1.0087x over previous
#include <cuda_runtime.h>
#include <cuda_fp16.h>
#include <math.h>
#include <stdint.h>

#define B_  32
#define N_  512
#define DIN 768
#define DOUT 256
#define H_  8
#define M_  (B_ * N_)

// ---------------- device scratch ----------------
__device__ __half g_xh [(size_t)M_ * DIN];
__device__ __half g_w0h[(size_t)H_ * DOUT * DIN];
__device__ __half g_w0l[(size_t)H_ * DOUT * DIN];
__device__ __half g_Whh[(size_t)H_ * M_ * DOUT];
__device__ uint32_t g_mask[(size_t)B_ * N_ * 16];
__device__ float  g_wa1[H_ * DIN];
__device__ float  g_wa2[H_ * DIN];
__device__ float  g_eu1[H_ * M_];
__device__ float  g_ev1[H_ * M_];
__device__ float  g_eu2[H_ * M_];
__device__ float  g_ev2[H_ * M_];
__device__ float  g_din[H_ * M_];
__device__ __half g_hmh[(size_t)M_ * DOUT];
__device__ __half g_woh[(size_t)DOUT * DOUT];
__device__ __half g_wol[(size_t)DOUT * DOUT];
__device__ __half g_W2h[(size_t)M_ * DOUT];
__device__ float  g_wao1[DOUT];
__device__ float  g_wao2[DOUT];
__device__ float  g_eu1b[M_];
__device__ float  g_ev1b[M_];
__device__ float  g_eu2b[M_];
__device__ float  g_ev2b[M_];
__device__ float  g_dinb[M_];

// ---------------- PTX helpers ----------------
__device__ __forceinline__ uint32_t smem_u32(const void* p) {
    uint32_t a;
    asm("{ .reg .u64 t; cvta.to.shared.u64 t, %1; cvt.u32.u64 %0, t; }" : "=r"(a) : "l"(p));
    return a;
}
__device__ __forceinline__ void cp16(uint32_t d, const void* s) {
    asm volatile("cp.async.cg.shared.global [%0], [%1], 16;" :: "r"(d), "l"(s));
}
#define CP_COMMIT() asm volatile("cp.async.commit_group;")
#define CP_WAIT(n)  asm volatile("cp.async.wait_group %0;" :: "n"(n))

#define LDM_X4(r, addr) \
    asm volatile("ldmatrix.sync.aligned.m8n8.x4.shared.b16 {%0,%1,%2,%3}, [%4];" \
        : "=r"((r)[0]), "=r"((r)[1]), "=r"((r)[2]), "=r"((r)[3]) : "r"(addr))
#define LDM_X2(r, addr) \
    asm volatile("ldmatrix.sync.aligned.m8n8.x2.shared.b16 {%0,%1}, [%2];" \
        : "=r"((r)[0]), "=r"((r)[1]) : "r"(addr))
#define LDM_X2T(r, addr) \
    asm volatile("ldmatrix.sync.aligned.m8n8.x2.trans.shared.b16 {%0,%1}, [%2];" \
        : "=r"((r)[0]), "=r"((r)[1]) : "r"(addr))

__device__ __forceinline__ void mma_f16(float* c, const uint32_t* a, const uint32_t* b) {
    asm volatile("mma.sync.aligned.m16n8k16.row.col.f32.f16.f16.f32 "
        "{%0,%1,%2,%3}, {%4,%5,%6,%7}, {%8,%9}, {%0,%1,%2,%3};"
        : "+f"(c[0]), "+f"(c[1]), "+f"(c[2]), "+f"(c[3])
        : "r"(a[0]), "r"(a[1]), "r"(a[2]), "r"(a[3]), "r"(b[0]), "r"(b[1]));
}

// ---------------- conversion kernels ----------------
__global__ __launch_bounds__(256) void hi_kernel(
    const float* __restrict__ src, __half* __restrict__ hi, int n4)
{
    int i = blockIdx.x * 256 + threadIdx.x;
    if (i >= n4) return;
    float4 v = ((const float4*)src)[i];
    ((__half2*)hi)[2 * i]     = __halves2half2(__float2half(v.x), __float2half(v.y));
    ((__half2*)hi)[2 * i + 1] = __halves2half2(__float2half(v.z), __float2half(v.w));
}

__global__ __launch_bounds__(256) void wsplit_kernel(
    const float* __restrict__ W, __half* __restrict__ bh,
    __half* __restrict__ bl, int Kd, int Nd)
{
    int z = blockIdx.z;
    int i = blockIdx.x * 256 + threadIdx.x;
    if (i >= Kd * Nd) return;
    int n = i / Kd, k = i % Kd;
    float v = W[(size_t)z * Kd * Nd + (size_t)k * Nd + n];
    __half h = __float2half(v);
    bh[(size_t)z * Kd * Nd + i] = h;
    bl[(size_t)z * Kd * Nd + i] = __float2half(v - __half2float(h));
}

// ---------------- pack adjacency ----------------
__global__ __launch_bounds__(256) void packadj_kernel(
    const int* __restrict__ adj, uint32_t* __restrict__ mask)
{
    int row  = (blockIdx.x * 256 + threadIdx.x) >> 5;
    int lane = threadIdx.x & 31;
    if (row >= B_ * N_) return;
    const int* ar = adj + (size_t)row * N_;
    #pragma unroll
    for (int q = 0; q < 16; ++q) {
        uint32_t w = __ballot_sync(0xffffffffu, ar[q * 32 + lane] > 0);
        if (lane == q) mask[row * 16 + q] = w;
    }
}

// ---------------- wa = W @ a (per head) ----------------
// W: [z][Kd][Nd], a: [z][Nd]; out wa[z][Kd]. One warp per (z,k).
__global__ __launch_bounds__(256) void wa_kernel(
    const float* __restrict__ W, const float* __restrict__ a1,
    const float* __restrict__ a2, float* __restrict__ wa1,
    float* __restrict__ wa2, int Kd, int Nd)
{
    int warp = (blockIdx.x * 256 + threadIdx.x) >> 5;
    int lane = threadIdx.x & 31;
    int z = warp / Kd, k = warp % Kd;
    const float* row = W + ((size_t)z * Kd + k) * Nd;
    const float* a1z = a1 + z * Nd;
    const float* a2z = a2 + z * Nd;
    float s1 = 0.0f, s2 = 0.0f;
    for (int f = lane; f < Nd; f += 32) {
        float w = row[f];
        s1 = fmaf(w, a1z[f], s1);
        s2 = fmaf(w, a2z[f], s2);
    }
    #pragma unroll
    for (int off = 16; off; off >>= 1) {
        s1 += __shfl_xor_sync(0xffffffffu, s1, off);
        s2 += __shfl_xor_sync(0xffffffffu, s2, off);
    }
    if (lane == 0) { wa1[warp] = s1; wa2[warp] = s2; }
}

// ---------------- fvec: f1/f2 from X and wa, emit factored exps ----------------
// X: [M][K] (T = float or half). out idx = h*M_ + r.
template<int NH, int K, typename T>
__global__ __launch_bounds__(256) void fvec_kernel(
    const T* __restrict__ X,
    const float* __restrict__ wa1, const float* __restrict__ wa2,
    float* __restrict__ eu1, float* __restrict__ ev1,
    float* __restrict__ eu2, float* __restrict__ ev2)
{
    extern __shared__ float swa[];          // [2][NH][K]
    float* swa1 = swa;
    float* swa2 = swa + NH * K;
    const int t = threadIdx.x, lane = t & 31, w = t >> 5;
    for (int i = t; i < NH * K; i += 256) { swa1[i] = wa1[i]; swa2[i] = wa2[i]; }
    __syncthreads();

    int r = blockIdx.x * 8 + w;
    float xv[K / 32];
    #pragma unroll
    for (int j = 0; j < K / 32; ++j)
        xv[j] = (float)X[(size_t)r * K + j * 32 + lane];

    float s1[NH], s2[NH];
    #pragma unroll
    for (int h = 0; h < NH; ++h) {
        float a = 0.0f, bsum = 0.0f;
        #pragma unroll
        for (int j = 0; j < K / 32; ++j) {
            int k = j * 32 + lane;
            a    = fmaf(xv[j], swa1[h * K + k], a);
            bsum = fmaf(xv[j], swa2[h * K + k], bsum);
        }
        #pragma unroll
        for (int off = 16; off; off >>= 1) {
            a    += __shfl_xor_sync(0xffffffffu, a, off);
            bsum += __shfl_xor_sync(0xffffffffu, bsum, off);
        }
        s1[h] = a; s2[h] = bsum;
    }
    if (lane < 2 * NH) {
        int h = lane >> 1;
        float s = (lane & 1) ? s2[h] : s1[h];
        float eu = __expf(s), ev = __expf(0.2f * s);
        size_t idx = (size_t)h * M_ + r;
        if (lane & 1) { eu2[idx] = eu; ev2[idx] = ev; }
        else          { eu1[idx] = eu; ev1[idx] = ev; }
    }
}

// ================= HMMA 2-term GEMM, 3-stage, reordered MMAs =================
#define GEMM_SMEM (3 * 30720)

__global__ __launch_bounds__(256, 2) void gemm_mma_kernel(
    const __half* __restrict__ Ah,
    const __half* __restrict__ Bh, const __half* __restrict__ Bl,
    __half* __restrict__ Chh, int K, int Nt)
{
    extern __shared__ __align__(128) char sm[];
    const uint32_t sb = smem_u32(sm);
    const int t = threadIdx.x, lane = t & 31, wid = t >> 5;
    const int m0 = blockIdx.x * 128, f0 = blockIdx.y * 128, z = blockIdx.z;
    const int warp_m = wid & 1, warp_n = wid >> 1;

    const __half* As_h = Ah + (size_t)m0 * K;
    const __half* Bs_h = Bh + (size_t)z * Nt * K + (size_t)f0 * K;
    const __half* Bs_l = Bl + (size_t)z * Nt * K + (size_t)f0 * K;
    __half* Ch = Chh + (size_t)z * M_ * Nt;

    float acc[4][4][4];
    #pragma unroll
    for (int a = 0; a < 4; ++a)
        #pragma unroll
        for (int b = 0; b < 4; ++b)
            #pragma unroll
            for (int c = 0; c < 4; ++c) acc[a][b][c] = 0.0f;

    const int row = t >> 1, half = t & 1;
    auto prefetch = [&](int c, int s) {
        const int kc = c * 32;
        const __half* srcs[3] = { As_h + kc, Bs_h + kc, Bs_l + kc };
        #pragma unroll
        for (int tile = 0; tile < 3; ++tile) {
            uint32_t dst = sb + s * 30720 + tile * 10240 + row * 80 + half * 32;
            const __half* src = srcs[tile] + (size_t)row * K + half * 16;
            cp16(dst, src);
            cp16(dst + 16, src + 8);
        }
        CP_COMMIT();
    };

    const int NC = K >> 5;
    prefetch(0, 0);
    prefetch(1, 1);
    int st = 0;
    for (int c = 0; c < NC; ++c) {
        if (c + 2 < NC) {
            int s2 = st + 2; if (s2 >= 3) s2 -= 3;
            prefetch(c + 2, s2);
        } else CP_COMMIT();
        CP_WAIT(2);
        __syncthreads();

        const uint32_t bAh = sb + st * 30720;
        const uint32_t bBh = bAh + 10240;
        const uint32_t bBl = bAh + 20480;
        #pragma unroll
        for (int k16 = 0; k16 < 2; ++k16) {
            const int kc = k16 * 16;
            uint32_t ah[4][4];
            #pragma unroll
            for (int mf = 0; mf < 4; ++mf) {
                uint32_t off = (uint32_t)((warp_m * 64 + mf * 16 + (lane & 15)) * 80
                                          + (kc + ((lane >> 4) << 3)) * 2);
                LDM_X4(ah[mf], bAh + off);
            }
            uint32_t bh[4][2], bl[4][2];
            #pragma unroll
            for (int nf = 0; nf < 4; ++nf) {
                uint32_t boff = (uint32_t)((warp_n * 32 + nf * 8 + (lane & 7)) * 80
                                           + (kc + (((lane >> 3) & 1) << 3)) * 2);
                LDM_X2(bh[nf], bBh + boff);
                LDM_X2(bl[nf], bBl + boff);
            }
            #pragma unroll
            for (int nf = 0; nf < 4; ++nf)
                #pragma unroll
                for (int mf = 0; mf < 4; ++mf)
                    mma_f16(acc[mf][nf], ah[mf], bh[nf]);
            #pragma unroll
            for (int nf = 0; nf < 4; ++nf)
                #pragma unroll
                for (int mf = 0; mf < 4; ++mf)
                    mma_f16(acc[mf][nf], ah[mf], bl[nf]);
        }
        __syncthreads();
        if (++st == 3) st = 0;
    }

    #pragma unroll
    for (int mf = 0; mf < 4; ++mf)
        #pragma unroll
        for (int nf = 0; nf < 4; ++nf) {
            int r0 = m0 + warp_m * 64 + mf * 16 + (lane >> 2);
            int col = f0 + warp_n * 32 + nf * 8 + (lane & 3) * 2;
            #pragma unroll
            for (int hh = 0; hh < 2; ++hh) {
                int r = r0 + hh * 8;
                *(__half2*)(Ch + (size_t)r * Nt + col) = __halves2half2(
                    __float2half(acc[mf][nf][hh * 2]),
                    __float2half(acc[mf][nf][hh * 2 + 1]));
            }
        }
}

// ---------------- denominator ----------------
__global__ __launch_bounds__(256) void dstats_kernel(
    const float* __restrict__ eu1, const float* __restrict__ ev1,
    const float* __restrict__ eu2, const float* __restrict__ ev2,
    const uint32_t* __restrict__ mask, float* __restrict__ dinv, int NH)
{
    int row  = (blockIdx.x * 256 + threadIdx.x) >> 5;
    int lane = threadIdx.x & 31;
    if (row >= B_ * N_) return;
    int b = row >> 9;
    uint32_t myw = (lane < 16) ? mask[row * 16 + lane] : 0u;

    for (int h = 0; h < NH; ++h) {
        size_t hb = (size_t)h * B_ + b;
        size_t r  = hb * N_ + (row & (N_ - 1));
        float u1 = eu1[r], v1 = ev1[r];
        const float* euh = eu2 + hb * N_;
        const float* evh = ev2 + hb * N_;
        float s = 0.0f;
        #pragma unroll
        for (int q = 0; q < 16; ++q) {
            uint32_t w = __shfl_sync(0xffffffffu, myw, q);
            int m = q * 32 + lane;
            float tt = u1 * euh[m];
            float t2 = v1 * evh[m];
            float E = tt >= 1.0f ? tt : t2;
            s += ((w >> lane) & 1u) ? E : 0.0f;
        }
        #pragma unroll
        for (int off = 16; off; off >>= 1)
            s += __shfl_xor_sync(0xffffffffu, s, off);
        if (lane == 0) dinv[r] = s > 0.0f ? 1.0f / s : 0.0f;
    }
}

// ================= HMMA attention: on-the-fly P, Wh-hi only =================
#define ATTN_SMEM (19456 + 33792)

template<int NHEADS, bool FINAL>
__global__ __launch_bounds__(512, 1) void attn_mma_kernel(
    const __half* __restrict__ Whh,
    const float* __restrict__ eu1, const float* __restrict__ ev1,
    const float* __restrict__ eu2, const float* __restrict__ ev2,
    const float* __restrict__ dinv, const uint32_t* __restrict__ gmask,
    __half* __restrict__ outh, float* __restrict__ outf)
{
    extern __shared__ __align__(128) char sm[];
    const uint32_t sb = smem_u32(sm);
    uint32_t* sadj = (uint32_t*)sm;
    float* seu  = (float*)(sm + 4096);
    float* sev  = (float*)(sm + 6144);
    float* su1  = (float*)(sm + 8192);
    float* sv1  = (float*)(sm + 8448);
    float* sinv = (float*)(sm + 8704);
    const uint32_t smP = sb + 9216;
    const uint32_t smW = sb + 19456;

    const int t = threadIdx.x, lane = t & 31, wid = t >> 5;
    const int n0 = blockIdx.x * 64;
    const int b  = blockIdx.y;
    const int warp_n = wid & 1, warp_f = wid >> 1;

    {
        int i0 = t;
        sadj[i0] = gmask[((size_t)b * N_ + n0 + (i0 >> 4)) * 16 + (i0 & 15)];
        int i1 = t + 512;
        sadj[i1] = gmask[((size_t)b * N_ + n0 + (i1 >> 4)) * 16 + (i1 & 15)];
    }

    const int pi  = t >> 3;
    const int pk4 = (t & 7) * 4;
    const int wrow = t >> 4;
    const int wseg = t & 15;

    float sum[2][4][4];
    #pragma unroll
    for (int a = 0; a < 2; ++a)
        #pragma unroll
        for (int c = 0; c < 4; ++c)
            #pragma unroll
            for (int d = 0; d < 4; ++d) sum[a][c][d] = 0.0f;

    for (int h = 0; h < NHEADS; ++h) {
        const size_t hb = (size_t)h * B_ + b;
        const __half* Wsh = Whh + hb * (size_t)N_ * DOUT;

        __syncthreads();
        seu[t & 511] = eu2[hb * N_ + (t & 511)];
        sev[t & 511] = ev2[hb * N_ + (t & 511)];
        if (t < 64) {
            su1[t]  = eu1[hb * N_ + n0 + t];
            sv1[t]  = ev1[hb * N_ + n0 + t];
            sinv[t] = dinv[hb * N_ + n0 + t];
        }
        __syncthreads();

        float acc[2][4][4];
        #pragma unroll
        for (int a = 0; a < 2; ++a)
            #pragma unroll
            for (int c = 0; c < 4; ++c)
                #pragma unroll
                for (int d = 0; d < 4; ++d) acc[a][c][d] = 0.0f;

        auto computeP = [&](int c, int st) {
            const int m0 = c * 32;
            float u1 = su1[pi], v1 = sv1[pi], inv = sinv[pi];
            uint32_t w = sadj[pi * 16 + c];
            __half hs[4];
            #pragma unroll
            for (int kk = 0; kk < 4; ++kk) {
                int mm = m0 + pk4 + kk;
                float tt = u1 * seu[mm];
                float t2 = v1 * sev[mm];
                float E  = tt >= 1.0f ? tt : t2;
                float p  = ((w >> (pk4 + kk)) & 1u) ? E * inv : 0.0f;
                hs[kk] = __float2half(p);
            }
            char* dh = sm + 9216 + st * 5120 + pi * 80 + pk4 * 2;
            ((__half2*)dh)[0] = __halves2half2(hs[0], hs[1]);
            ((__half2*)dh)[1] = __halves2half2(hs[2], hs[3]);
        };
        auto prefetchW = [&](int c, int st) {
            const int m0 = c * 32;
            const __half* src = Wsh + (size_t)(m0 + wrow) * DOUT;
            uint32_t dst = smW + st * 16896 + wrow * 528;
            cp16(dst + wseg * 16, src + wseg * 8);
            cp16(dst + (wseg + 16) * 16, src + (wseg + 16) * 8);
            CP_COMMIT();
        };

        computeP(0, 0);
        prefetchW(0, 0);
        for (int c = 0; c < 16; ++c) {
            const int st = c & 1;
            if (c < 15) {
                prefetchW(c + 1, st ^ 1);
                computeP(c + 1, st ^ 1);
                CP_WAIT(1);
            } else CP_WAIT(0);
            __syncthreads();

            const uint32_t Phs = smP + st * 5120;
            const uint32_t Whs = smW + st * 16896;
            #pragma unroll
            for (int k16 = 0; k16 < 2; ++k16) {
                const int kc = k16 * 16;
                uint32_t ah[2][4];
                #pragma unroll
                for (int mf = 0; mf < 2; ++mf) {
                    uint32_t off = (uint32_t)((warp_n * 32 + mf * 16 + (lane & 15)) * 80
                                              + (kc + ((lane >> 4) << 3)) * 2);
                    LDM_X4(ah[mf], Phs + off);
                }
                #pragma unroll
                for (int nf = 0; nf < 4; ++nf) {
                    uint32_t woff = (uint32_t)((kc + (lane & 15)) * 528
                                               + (warp_f * 32 + nf * 8) * 2);
                    uint32_t bh[2];
                    LDM_X2T(bh, Whs + woff);
                    #pragma unroll
                    for (int mf = 0; mf < 2; ++mf)
                        mma_f16(acc[mf][nf], ah[mf], bh);
                }
            }
            __syncthreads();
        }

        if (FINAL) {
            #pragma unroll
            for (int a = 0; a < 2; ++a)
                #pragma unroll
                for (int c = 0; c < 4; ++c)
                    #pragma unroll
                    for (int d = 0; d < 4; ++d) sum[a][c][d] = acc[a][c][d];
        } else {
            #pragma unroll
            for (int a = 0; a < 2; ++a)
                #pragma unroll
                for (int c = 0; c < 4; ++c)
                    #pragma unroll
                    for (int d = 0; d < 4; ++d) {
                        float v = acc[a][c][d];
                        sum[a][c][d] += (v > 0.0f) ? v : expm1f(v);
                    }
        }
    }

    #pragma unroll
    for (int mf = 0; mf < 2; ++mf)
        #pragma unroll
        for (int nf = 0; nf < 4; ++nf) {
            int r0  = n0 + warp_n * 32 + mf * 16 + (lane >> 2);
            int col = warp_f * 32 + nf * 8 + (lane & 3) * 2;
            #pragma unroll
            for (int hh2 = 0; hh2 < 2; ++hh2) {
                int r = r0 + hh2 * 8;
                float c0 = sum[mf][nf][hh2 * 2], c1 = sum[mf][nf][hh2 * 2 + 1];
                if (FINAL) {
                    float2 v = { fmaxf(c0, 0.0f), fmaxf(c1, 0.0f) };
                    *(float2*)(outf + ((size_t)b * N_ + r) * DOUT + col) = v;
                } else {
                    c0 *= 0.125f; c1 *= 0.125f;
                    *(__half2*)(outh + ((size_t)b * N_ + r) * DOUT + col) =
                        __halves2half2(__float2half(c0), __float2half(c1));
                }
            }
        }
}

// ---------------- launch ----------------
extern "C" void kernel_launch(void* const* d_in, const int* in_sizes, int n_in,
                              void* d_out, int out_size)
{
    const float* x    = (const float*)d_in[0];
    const int*   adj  = (const int*)  d_in[1];
    const float* W0   = (const float*)d_in[2];
    const float* a1_0 = (const float*)d_in[3];
    const float* a2_0 = (const float*)d_in[4];
    const float* Wo   = (const float*)d_in[5];
    const float* a1_o = (const float*)d_in[6];
    const float* a2_o = (const float*)d_in[7];
    float* out = (float*)d_out;

    __half *xh, *w0h, *w0l, *Whh, *hmh, *woh, *wol, *W2h;
    float *wa1, *wa2, *wao1, *wao2;
    float *eu1, *ev1, *eu2, *ev2, *din, *eu1b, *ev1b, *eu2b, *ev2b, *dinb;
    uint32_t* mask;
    cudaGetSymbolAddress((void**)&xh,  g_xh);
    cudaGetSymbolAddress((void**)&w0h, g_w0h);
    cudaGetSymbolAddress((void**)&w0l, g_w0l);
    cudaGetSymbolAddress((void**)&Whh, g_Whh);
    cudaGetSymbolAddress((void**)&mask, g_mask);
    cudaGetSymbolAddress((void**)&wa1, g_wa1);
    cudaGetSymbolAddress((void**)&wa2, g_wa2);
    cudaGetSymbolAddress((void**)&eu1, g_eu1);
    cudaGetSymbolAddress((void**)&ev1, g_ev1);
    cudaGetSymbolAddress((void**)&eu2, g_eu2);
    cudaGetSymbolAddress((void**)&ev2, g_ev2);
    cudaGetSymbolAddress((void**)&din, g_din);
    cudaGetSymbolAddress((void**)&hmh, g_hmh);
    cudaGetSymbolAddress((void**)&woh, g_woh);
    cudaGetSymbolAddress((void**)&wol, g_wol);
    cudaGetSymbolAddress((void**)&W2h, g_W2h);
    cudaGetSymbolAddress((void**)&wao1, g_wao1);
    cudaGetSymbolAddress((void**)&wao2, g_wao2);
    cudaGetSymbolAddress((void**)&eu1b, g_eu1b);
    cudaGetSymbolAddress((void**)&ev1b, g_ev1b);
    cudaGetSymbolAddress((void**)&eu2b, g_eu2b);
    cudaGetSymbolAddress((void**)&ev2b, g_ev2b);
    cudaGetSymbolAddress((void**)&dinb, g_dinb);

    cudaFuncSetAttribute(gemm_mma_kernel,
        cudaFuncAttributeMaxDynamicSharedMemorySize, GEMM_SMEM);
    cudaFuncSetAttribute(attn_mma_kernel<H_, false>,
        cudaFuncAttributeMaxDynamicSharedMemorySize, ATTN_SMEM);
    cudaFuncSetAttribute(attn_mma_kernel<1, true>,
        cudaFuncAttributeMaxDynamicSharedMemorySize, ATTN_SMEM);
    cudaFuncSetAttribute((const void*)fvec_kernel<H_, DIN, float>,
        cudaFuncAttributeMaxDynamicSharedMemorySize, 2 * H_ * DIN * 4);
    cudaFuncSetAttribute((const void*)fvec_kernel<1, DOUT, __half>,
        cudaFuncAttributeMaxDynamicSharedMemorySize, 2 * DOUT * 4);

    // ---- layer 1 ----
    packadj_kernel<<<(B_ * N_) / 8, 256>>>(adj, mask);
    hi_kernel<<<(M_ * DIN / 4 + 255) / 256, 256>>>(x, xh, M_ * DIN / 4);
    wsplit_kernel<<<dim3((DIN * DOUT + 255) / 256, 1, H_), 256>>>(W0, w0h, w0l, DIN, DOUT);
    wa_kernel<<<(H_ * DIN) / 8, 256>>>(W0, a1_0, a2_0, wa1, wa2, DIN, DOUT);
    fvec_kernel<H_, DIN, float><<<M_ / 8, 256, 2 * H_ * DIN * 4>>>(
        x, wa1, wa2, eu1, ev1, eu2, ev2);
    gemm_mma_kernel<<<dim3(M_ / 128, DOUT / 128, H_), 256, GEMM_SMEM>>>(
        xh, w0h, w0l, Whh, DIN, DOUT);
    dstats_kernel<<<(B_ * N_) / 8, 256>>>(eu1, ev1, eu2, ev2, mask, din, H_);
    attn_mma_kernel<H_, false><<<dim3(N_ / 64, B_), 512, ATTN_SMEM>>>(
        Whh, eu1, ev1, eu2, ev2, din, mask, hmh, nullptr);

    // ---- layer 2 ----
    wsplit_kernel<<<dim3((DOUT * DOUT + 255) / 256, 1, 1), 256>>>(Wo, woh, wol, DOUT, DOUT);
    wa_kernel<<<DOUT / 8, 256>>>(Wo, a1_o, a2_o, wao1, wao2, DOUT, DOUT);
    fvec_kernel<1, DOUT, __half><<<M_ / 8, 256, 2 * DOUT * 4>>>(
        hmh, wao1, wao2, eu1b, ev1b, eu2b, ev2b);
    gemm_mma_kernel<<<dim3(M_ / 128, DOUT / 128, 1), 256, GEMM_SMEM>>>(
        hmh, woh, wol, W2h, DOUT, DOUT);
    dstats_kernel<<<(B_ * N_) / 8, 256>>>(eu1b, ev1b, eu2b, ev2b, mask, dinb, 1);
    attn_mma_kernel<1, true><<<dim3(N_ / 64, B_), 512, ATTN_SMEM>>>(
        W2h, eu1b, ev1b, eu2b, ev2b, dinb, mask, nullptr, out);
}

// round 13
// speedup vs baseline: 2.8720x; 1.1793x over previous
#include <cuda_runtime.h>
#include <cuda_fp16.h>
#include <math.h>
#include <stdint.h>

#define B_  32
#define N_  512
#define DIN 768
#define DOUT 256
#define H_  8
#define M_  (B_ * N_)

// ---------------- device scratch ----------------
__device__ __half g_xh [(size_t)M_ * DIN];
__device__ __half g_w0h[(size_t)H_ * DOUT * DIN];
__device__ __half g_Whh[(size_t)H_ * M_ * DOUT];
__device__ uint32_t g_mask[(size_t)B_ * N_ * 16];
__device__ float  g_wa1[H_ * DIN];
__device__ float  g_wa2[H_ * DIN];
__device__ float  g_eu1[H_ * M_];
__device__ float  g_ev1[H_ * M_];
__device__ float  g_eu2[H_ * M_];
__device__ float  g_ev2[H_ * M_];
__device__ float  g_din[H_ * M_];
__device__ __half g_hmh[(size_t)M_ * DOUT];
__device__ __half g_woh[(size_t)DOUT * DOUT];
__device__ __half g_W2h[(size_t)M_ * DOUT];
__device__ float  g_wao1[DOUT];
__device__ float  g_wao2[DOUT];
__device__ float  g_eu1b[M_];
__device__ float  g_ev1b[M_];
__device__ float  g_eu2b[M_];
__device__ float  g_ev2b[M_];
__device__ float  g_dinb[M_];

// ---------------- PTX helpers ----------------
__device__ __forceinline__ uint32_t smem_u32(const void* p) {
    uint32_t a;
    asm("{ .reg .u64 t; cvta.to.shared.u64 t, %1; cvt.u32.u64 %0, t; }" : "=r"(a) : "l"(p));
    return a;
}
__device__ __forceinline__ void cp16(uint32_t d, const void* s) {
    asm volatile("cp.async.cg.shared.global [%0], [%1], 16;" :: "r"(d), "l"(s));
}
#define CP_COMMIT() asm volatile("cp.async.commit_group;")
#define CP_WAIT(n)  asm volatile("cp.async.wait_group %0;" :: "n"(n))

#define LDM_X4(r, addr) \
    asm volatile("ldmatrix.sync.aligned.m8n8.x4.shared.b16 {%0,%1,%2,%3}, [%4];" \
        : "=r"((r)[0]), "=r"((r)[1]), "=r"((r)[2]), "=r"((r)[3]) : "r"(addr))
#define LDM_X2(r, addr) \
    asm volatile("ldmatrix.sync.aligned.m8n8.x2.shared.b16 {%0,%1}, [%2];" \
        : "=r"((r)[0]), "=r"((r)[1]) : "r"(addr))
#define LDM_X2T(r, addr) \
    asm volatile("ldmatrix.sync.aligned.m8n8.x2.trans.shared.b16 {%0,%1}, [%2];" \
        : "=r"((r)[0]), "=r"((r)[1]) : "r"(addr))

__device__ __forceinline__ void mma_f16(float* c, const uint32_t* a, const uint32_t* b) {
    asm volatile("mma.sync.aligned.m16n8k16.row.col.f32.f16.f16.f32 "
        "{%0,%1,%2,%3}, {%4,%5,%6,%7}, {%8,%9}, {%0,%1,%2,%3};"
        : "+f"(c[0]), "+f"(c[1]), "+f"(c[2]), "+f"(c[3])
        : "r"(a[0]), "r"(a[1]), "r"(a[2]), "r"(a[3]), "r"(b[0]), "r"(b[1]));
}

// ---------------- conversion kernels ----------------
__global__ __launch_bounds__(256) void hi_kernel(
    const float* __restrict__ src, __half* __restrict__ hi, int n4)
{
    int i = blockIdx.x * 256 + threadIdx.x;
    if (i >= n4) return;
    float4 v = ((const float4*)src)[i];
    ((__half2*)hi)[2 * i]     = __halves2half2(__float2half(v.x), __float2half(v.y));
    ((__half2*)hi)[2 * i + 1] = __halves2half2(__float2half(v.z), __float2half(v.w));
}

// W: [z][K][N] fp32 -> [z][N][K] fp16 (transpose, hi only)
__global__ __launch_bounds__(256) void whi_kernel(
    const float* __restrict__ W, __half* __restrict__ bh, int Kd, int Nd)
{
    int z = blockIdx.z;
    int i = blockIdx.x * 256 + threadIdx.x;
    if (i >= Kd * Nd) return;
    int n = i / Kd, k = i % Kd;
    bh[(size_t)z * Kd * Nd + i] =
        __float2half(W[(size_t)z * Kd * Nd + (size_t)k * Nd + n]);
}

// ---------------- pack adjacency ----------------
__global__ __launch_bounds__(256) void packadj_kernel(
    const int* __restrict__ adj, uint32_t* __restrict__ mask)
{
    int row  = (blockIdx.x * 256 + threadIdx.x) >> 5;
    int lane = threadIdx.x & 31;
    if (row >= B_ * N_) return;
    const int* ar = adj + (size_t)row * N_;
    #pragma unroll
    for (int q = 0; q < 16; ++q) {
        uint32_t w = __ballot_sync(0xffffffffu, ar[q * 32 + lane] > 0);
        if (lane == q) mask[row * 16 + q] = w;
    }
}

// ---------------- wa = W @ a (per head) ----------------
__global__ __launch_bounds__(256) void wa_kernel(
    const float* __restrict__ W, const float* __restrict__ a1,
    const float* __restrict__ a2, float* __restrict__ wa1,
    float* __restrict__ wa2, int Kd, int Nd)
{
    int warp = (blockIdx.x * 256 + threadIdx.x) >> 5;
    int lane = threadIdx.x & 31;
    int z = warp / Kd, k = warp % Kd;
    const float* row = W + ((size_t)z * Kd + k) * Nd;
    const float* a1z = a1 + z * Nd;
    const float* a2z = a2 + z * Nd;
    float s1 = 0.0f, s2 = 0.0f;
    for (int f = lane; f < Nd; f += 32) {
        float w = row[f];
        s1 = fmaf(w, a1z[f], s1);
        s2 = fmaf(w, a2z[f], s2);
    }
    #pragma unroll
    for (int off = 16; off; off >>= 1) {
        s1 += __shfl_xor_sync(0xffffffffu, s1, off);
        s2 += __shfl_xor_sync(0xffffffffu, s2, off);
    }
    if (lane == 0) { wa1[warp] = s1; wa2[warp] = s2; }
}

// ---------------- fvec: f1/f2 from X and wa, emit factored exps ----------------
template<int NH, int K, typename T>
__global__ __launch_bounds__(256) void fvec_kernel(
    const T* __restrict__ X,
    const float* __restrict__ wa1, const float* __restrict__ wa2,
    float* __restrict__ eu1, float* __restrict__ ev1,
    float* __restrict__ eu2, float* __restrict__ ev2)
{
    extern __shared__ float swa[];
    float* swa1 = swa;
    float* swa2 = swa + NH * K;
    const int t = threadIdx.x, lane = t & 31, w = t >> 5;
    for (int i = t; i < NH * K; i += 256) { swa1[i] = wa1[i]; swa2[i] = wa2[i]; }
    __syncthreads();

    int r = blockIdx.x * 8 + w;
    float xv[K / 32];
    #pragma unroll
    for (int j = 0; j < K / 32; ++j)
        xv[j] = (float)X[(size_t)r * K + j * 32 + lane];

    float s1[NH], s2[NH];
    #pragma unroll
    for (int h = 0; h < NH; ++h) {
        float a = 0.0f, bsum = 0.0f;
        #pragma unroll
        for (int j = 0; j < K / 32; ++j) {
            int k = j * 32 + lane;
            a    = fmaf(xv[j], swa1[h * K + k], a);
            bsum = fmaf(xv[j], swa2[h * K + k], bsum);
        }
        #pragma unroll
        for (int off = 16; off; off >>= 1) {
            a    += __shfl_xor_sync(0xffffffffu, a, off);
            bsum += __shfl_xor_sync(0xffffffffu, bsum, off);
        }
        s1[h] = a; s2[h] = bsum;
    }
    if (lane < 2 * NH) {
        int h = lane >> 1;
        float s = (lane & 1) ? s2[h] : s1[h];
        float eu = __expf(s), ev = __expf(0.2f * s);
        size_t idx = (size_t)h * M_ + r;
        if (lane & 1) { eu2[idx] = eu; ev2[idx] = ev; }
        else          { eu1[idx] = eu; ev1[idx] = ev; }
    }
}

// ================= HMMA fp16 GEMM (1-term), 3-stage =================
// smem: 2 tiles [128][40] half per stage; stage 20480B, 3 stages 61440B.
#define GEMM_SMEM (3 * 20480)

__global__ __launch_bounds__(256, 2) void gemm_mma_kernel(
    const __half* __restrict__ Ah, const __half* __restrict__ Bh,
    __half* __restrict__ Chh, int K, int Nt)
{
    extern __shared__ __align__(128) char sm[];
    const uint32_t sb = smem_u32(sm);
    const int t = threadIdx.x, lane = t & 31, wid = t >> 5;
    const int m0 = blockIdx.x * 128, f0 = blockIdx.y * 128, z = blockIdx.z;
    const int warp_m = wid & 1, warp_n = wid >> 1;

    const __half* As_h = Ah + (size_t)m0 * K;
    const __half* Bs_h = Bh + (size_t)z * Nt * K + (size_t)f0 * K;
    __half* Ch = Chh + (size_t)z * M_ * Nt;

    float acc[4][4][4];
    #pragma unroll
    for (int a = 0; a < 4; ++a)
        #pragma unroll
        for (int b = 0; b < 4; ++b)
            #pragma unroll
            for (int c = 0; c < 4; ++c) acc[a][b][c] = 0.0f;

    const int row = t >> 1, half = t & 1;
    auto prefetch = [&](int c, int s) {
        const int kc = c * 32;
        const __half* srcs[2] = { As_h + kc, Bs_h + kc };
        #pragma unroll
        for (int tile = 0; tile < 2; ++tile) {
            uint32_t dst = sb + s * 20480 + tile * 10240 + row * 80 + half * 32;
            const __half* src = srcs[tile] + (size_t)row * K + half * 16;
            cp16(dst, src);
            cp16(dst + 16, src + 8);
        }
        CP_COMMIT();
    };

    const int NC = K >> 5;
    prefetch(0, 0);
    prefetch(1, 1);
    int st = 0;
    for (int c = 0; c < NC; ++c) {
        if (c + 2 < NC) {
            int s2 = st + 2; if (s2 >= 3) s2 -= 3;
            prefetch(c + 2, s2);
        } else CP_COMMIT();
        CP_WAIT(2);
        __syncthreads();

        const uint32_t bAh = sb + st * 20480;
        const uint32_t bBh = bAh + 10240;
        #pragma unroll
        for (int k16 = 0; k16 < 2; ++k16) {
            const int kc = k16 * 16;
            uint32_t ah[4][4];
            #pragma unroll
            for (int mf = 0; mf < 4; ++mf) {
                uint32_t off = (uint32_t)((warp_m * 64 + mf * 16 + (lane & 15)) * 80
                                          + (kc + ((lane >> 4) << 3)) * 2);
                LDM_X4(ah[mf], bAh + off);
            }
            #pragma unroll
            for (int nf = 0; nf < 4; ++nf) {
                uint32_t boff = (uint32_t)((warp_n * 32 + nf * 8 + (lane & 7)) * 80
                                           + (kc + (((lane >> 3) & 1) << 3)) * 2);
                uint32_t bh[2];
                LDM_X2(bh, bBh + boff);
                #pragma unroll
                for (int mf = 0; mf < 4; ++mf)
                    mma_f16(acc[mf][nf], ah[mf], bh);
            }
        }
        __syncthreads();
        if (++st == 3) st = 0;
    }

    #pragma unroll
    for (int mf = 0; mf < 4; ++mf)
        #pragma unroll
        for (int nf = 0; nf < 4; ++nf) {
            int r0 = m0 + warp_m * 64 + mf * 16 + (lane >> 2);
            int col = f0 + warp_n * 32 + nf * 8 + (lane & 3) * 2;
            #pragma unroll
            for (int hh = 0; hh < 2; ++hh) {
                int r = r0 + hh * 8;
                *(__half2*)(Ch + (size_t)r * Nt + col) = __halves2half2(
                    __float2half(acc[mf][nf][hh * 2]),
                    __float2half(acc[mf][nf][hh * 2 + 1]));
            }
        }
}

// ---------------- denominator ----------------
__global__ __launch_bounds__(256) void dstats_kernel(
    const float* __restrict__ eu1, const float* __restrict__ ev1,
    const float* __restrict__ eu2, const float* __restrict__ ev2,
    const uint32_t* __restrict__ mask, float* __restrict__ dinv, int NH)
{
    int row  = (blockIdx.x * 256 + threadIdx.x) >> 5;
    int lane = threadIdx.x & 31;
    if (row >= B_ * N_) return;
    int b = row >> 9;
    uint32_t myw = (lane < 16) ? mask[row * 16 + lane] : 0u;

    for (int h = 0; h < NH; ++h) {
        size_t hb = (size_t)h * B_ + b;
        size_t r  = hb * N_ + (row & (N_ - 1));
        float u1 = eu1[r], v1 = ev1[r];
        const float* euh = eu2 + hb * N_;
        const float* evh = ev2 + hb * N_;
        float s = 0.0f;
        #pragma unroll
        for (int q = 0; q < 16; ++q) {
            uint32_t w = __shfl_sync(0xffffffffu, myw, q);
            int m = q * 32 + lane;
            float tt = u1 * euh[m];
            float t2 = v1 * evh[m];
            float E = tt >= 1.0f ? tt : t2;
            s += ((w >> lane) & 1u) ? E : 0.0f;
        }
        #pragma unroll
        for (int off = 16; off; off >>= 1)
            s += __shfl_xor_sync(0xffffffffu, s, off);
        if (lane == 0) dinv[r] = s > 0.0f ? 1.0f / s : 0.0f;
    }
}

// ================= HMMA attention: on-the-fly P, Wh-hi only =================
#define ATTN_SMEM (19456 + 33792)

template<int NHEADS, bool FINAL>
__global__ __launch_bounds__(512, 1) void attn_mma_kernel(
    const __half* __restrict__ Whh,
    const float* __restrict__ eu1, const float* __restrict__ ev1,
    const float* __restrict__ eu2, const float* __restrict__ ev2,
    const float* __restrict__ dinv, const uint32_t* __restrict__ gmask,
    __half* __restrict__ outh, float* __restrict__ outf)
{
    extern __shared__ __align__(128) char sm[];
    const uint32_t sb = smem_u32(sm);
    uint32_t* sadj = (uint32_t*)sm;
    float* seu  = (float*)(sm + 4096);
    float* sev  = (float*)(sm + 6144);
    float* su1  = (float*)(sm + 8192);
    float* sv1  = (float*)(sm + 8448);
    float* sinv = (float*)(sm + 8704);
    const uint32_t smP = sb + 9216;
    const uint32_t smW = sb + 19456;

    const int t = threadIdx.x, lane = t & 31, wid = t >> 5;
    const int n0 = blockIdx.x * 64;
    const int b  = blockIdx.y;
    const int warp_n = wid & 1, warp_f = wid >> 1;

    {
        int i0 = t;
        sadj[i0] = gmask[((size_t)b * N_ + n0 + (i0 >> 4)) * 16 + (i0 & 15)];
        int i1 = t + 512;
        sadj[i1] = gmask[((size_t)b * N_ + n0 + (i1 >> 4)) * 16 + (i1 & 15)];
    }

    const int pi  = t >> 3;
    const int pk4 = (t & 7) * 4;
    const int wrow = t >> 4;
    const int wseg = t & 15;

    float sum[2][4][4];
    #pragma unroll
    for (int a = 0; a < 2; ++a)
        #pragma unroll
        for (int c = 0; c < 4; ++c)
            #pragma unroll
            for (int d = 0; d < 4; ++d) sum[a][c][d] = 0.0f;

    for (int h = 0; h < NHEADS; ++h) {
        const size_t hb = (size_t)h * B_ + b;
        const __half* Wsh = Whh + hb * (size_t)N_ * DOUT;

        __syncthreads();
        seu[t & 511] = eu2[hb * N_ + (t & 511)];
        sev[t & 511] = ev2[hb * N_ + (t & 511)];
        if (t < 64) {
            su1[t]  = eu1[hb * N_ + n0 + t];
            sv1[t]  = ev1[hb * N_ + n0 + t];
            sinv[t] = dinv[hb * N_ + n0 + t];
        }
        __syncthreads();

        float acc[2][4][4];
        #pragma unroll
        for (int a = 0; a < 2; ++a)
            #pragma unroll
            for (int c = 0; c < 4; ++c)
                #pragma unroll
                for (int d = 0; d < 4; ++d) acc[a][c][d] = 0.0f;

        auto computeP = [&](int c, int st) {
            const int m0 = c * 32;
            float u1 = su1[pi], v1 = sv1[pi], inv = sinv[pi];
            uint32_t w = sadj[pi * 16 + c];
            __half hs[4];
            #pragma unroll
            for (int kk = 0; kk < 4; ++kk) {
                int mm = m0 + pk4 + kk;
                float tt = u1 * seu[mm];
                float t2 = v1 * sev[mm];
                float E  = tt >= 1.0f ? tt : t2;
                float p  = ((w >> (pk4 + kk)) & 1u) ? E * inv : 0.0f;
                hs[kk] = __float2half(p);
            }
            char* dh = sm + 9216 + st * 5120 + pi * 80 + pk4 * 2;
            ((__half2*)dh)[0] = __halves2half2(hs[0], hs[1]);
            ((__half2*)dh)[1] = __halves2half2(hs[2], hs[3]);
        };
        auto prefetchW = [&](int c, int st) {
            const int m0 = c * 32;
            const __half* src = Wsh + (size_t)(m0 + wrow) * DOUT;
            uint32_t dst = smW + st * 16896 + wrow * 528;
            cp16(dst + wseg * 16, src + wseg * 8);
            cp16(dst + (wseg + 16) * 16, src + (wseg + 16) * 8);
            CP_COMMIT();
        };

        computeP(0, 0);
        prefetchW(0, 0);
        for (int c = 0; c < 16; ++c) {
            const int st = c & 1;
            if (c < 15) {
                prefetchW(c + 1, st ^ 1);
                computeP(c + 1, st ^ 1);
                CP_WAIT(1);
            } else CP_WAIT(0);
            __syncthreads();

            const uint32_t Phs = smP + st * 5120;
            const uint32_t Whs = smW + st * 16896;
            #pragma unroll
            for (int k16 = 0; k16 < 2; ++k16) {
                const int kc = k16 * 16;
                uint32_t ah[2][4];
                #pragma unroll
                for (int mf = 0; mf < 2; ++mf) {
                    uint32_t off = (uint32_t)((warp_n * 32 + mf * 16 + (lane & 15)) * 80
                                              + (kc + ((lane >> 4) << 3)) * 2);
                    LDM_X4(ah[mf], Phs + off);
                }
                #pragma unroll
                for (int nf = 0; nf < 4; ++nf) {
                    uint32_t woff = (uint32_t)((kc + (lane & 15)) * 528
                                               + (warp_f * 32 + nf * 8) * 2);
                    uint32_t bh[2];
                    LDM_X2T(bh, Whs + woff);
                    #pragma unroll
                    for (int mf = 0; mf < 2; ++mf)
                        mma_f16(acc[mf][nf], ah[mf], bh);
                }
            }
            __syncthreads();
        }

        if (FINAL) {
            #pragma unroll
            for (int a = 0; a < 2; ++a)
                #pragma unroll
                for (int c = 0; c < 4; ++c)
                    #pragma unroll
                    for (int d = 0; d < 4; ++d) sum[a][c][d] = acc[a][c][d];
        } else {
            #pragma unroll
            for (int a = 0; a < 2; ++a)
                #pragma unroll
                for (int c = 0; c < 4; ++c)
                    #pragma unroll
                    for (int d = 0; d < 4; ++d) {
                        float v = acc[a][c][d];
                        sum[a][c][d] += (v > 0.0f) ? v : expm1f(v);
                    }
        }
    }

    #pragma unroll
    for (int mf = 0; mf < 2; ++mf)
        #pragma unroll
        for (int nf = 0; nf < 4; ++nf) {
            int r0  = n0 + warp_n * 32 + mf * 16 + (lane >> 2);
            int col = warp_f * 32 + nf * 8 + (lane & 3) * 2;
            #pragma unroll
            for (int hh2 = 0; hh2 < 2; ++hh2) {
                int r = r0 + hh2 * 8;
                float c0 = sum[mf][nf][hh2 * 2], c1 = sum[mf][nf][hh2 * 2 + 1];
                if (FINAL) {
                    float2 v = { fmaxf(c0, 0.0f), fmaxf(c1, 0.0f) };
                    *(float2*)(outf + ((size_t)b * N_ + r) * DOUT + col) = v;
                } else {
                    c0 *= 0.125f; c1 *= 0.125f;
                    *(__half2*)(outh + ((size_t)b * N_ + r) * DOUT + col) =
                        __halves2half2(__float2half(c0), __float2half(c1));
                }
            }
        }
}

// ---------------- launch ----------------
extern "C" void kernel_launch(void* const* d_in, const int* in_sizes, int n_in,
                              void* d_out, int out_size)
{
    const float* x    = (const float*)d_in[0];
    const int*   adj  = (const int*)  d_in[1];
    const float* W0   = (const float*)d_in[2];
    const float* a1_0 = (const float*)d_in[3];
    const float* a2_0 = (const float*)d_in[4];
    const float* Wo   = (const float*)d_in[5];
    const float* a1_o = (const float*)d_in[6];
    const float* a2_o = (const float*)d_in[7];
    float* out = (float*)d_out;

    __half *xh, *w0h, *Whh, *hmh, *woh, *W2h;
    float *wa1, *wa2, *wao1, *wao2;
    float *eu1, *ev1, *eu2, *ev2, *din, *eu1b, *ev1b, *eu2b, *ev2b, *dinb;
    uint32_t* mask;
    cudaGetSymbolAddress((void**)&xh,  g_xh);
    cudaGetSymbolAddress((void**)&w0h, g_w0h);
    cudaGetSymbolAddress((void**)&Whh, g_Whh);
    cudaGetSymbolAddress((void**)&mask, g_mask);
    cudaGetSymbolAddress((void**)&wa1, g_wa1);
    cudaGetSymbolAddress((void**)&wa2, g_wa2);
    cudaGetSymbolAddress((void**)&eu1, g_eu1);
    cudaGetSymbolAddress((void**)&ev1, g_ev1);
    cudaGetSymbolAddress((void**)&eu2, g_eu2);
    cudaGetSymbolAddress((void**)&ev2, g_ev2);
    cudaGetSymbolAddress((void**)&din, g_din);
    cudaGetSymbolAddress((void**)&hmh, g_hmh);
    cudaGetSymbolAddress((void**)&woh, g_woh);
    cudaGetSymbolAddress((void**)&W2h, g_W2h);
    cudaGetSymbolAddress((void**)&wao1, g_wao1);
    cudaGetSymbolAddress((void**)&wao2, g_wao2);
    cudaGetSymbolAddress((void**)&eu1b, g_eu1b);
    cudaGetSymbolAddress((void**)&ev1b, g_ev1b);
    cudaGetSymbolAddress((void**)&eu2b, g_eu2b);
    cudaGetSymbolAddress((void**)&ev2b, g_ev2b);
    cudaGetSymbolAddress((void**)&dinb, g_dinb);

    cudaFuncSetAttribute(gemm_mma_kernel,
        cudaFuncAttributeMaxDynamicSharedMemorySize, GEMM_SMEM);
    cudaFuncSetAttribute(attn_mma_kernel<H_, false>,
        cudaFuncAttributeMaxDynamicSharedMemorySize, ATTN_SMEM);
    cudaFuncSetAttribute(attn_mma_kernel<1, true>,
        cudaFuncAttributeMaxDynamicSharedMemorySize, ATTN_SMEM);
    cudaFuncSetAttribute((const void*)fvec_kernel<H_, DIN, float>,
        cudaFuncAttributeMaxDynamicSharedMemorySize, 2 * H_ * DIN * 4);
    cudaFuncSetAttribute((const void*)fvec_kernel<1, DOUT, __half>,
        cudaFuncAttributeMaxDynamicSharedMemorySize, 2 * DOUT * 4);

    // ---- layer 1 ----
    packadj_kernel<<<(B_ * N_) / 8, 256>>>(adj, mask);
    hi_kernel<<<(M_ * DIN / 4 + 255) / 256, 256>>>(x, xh, M_ * DIN / 4);
    whi_kernel<<<dim3((DIN * DOUT + 255) / 256, 1, H_), 256>>>(W0, w0h, DIN, DOUT);
    wa_kernel<<<(H_ * DIN) / 8, 256>>>(W0, a1_0, a2_0, wa1, wa2, DIN, DOUT);
    fvec_kernel<H_, DIN, float><<<M_ / 8, 256, 2 * H_ * DIN * 4>>>(
        x, wa1, wa2, eu1, ev1, eu2, ev2);
    gemm_mma_kernel<<<dim3(M_ / 128, DOUT / 128, H_), 256, GEMM_SMEM>>>(
        xh, w0h, Whh, DIN, DOUT);
    dstats_kernel<<<(B_ * N_) / 8, 256>>>(eu1, ev1, eu2, ev2, mask, din, H_);
    attn_mma_kernel<H_, false><<<dim3(N_ / 64, B_), 512, ATTN_SMEM>>>(
        Whh, eu1, ev1, eu2, ev2, din, mask, hmh, nullptr);

    // ---- layer 2 ----
    whi_kernel<<<dim3((DOUT * DOUT + 255) / 256, 1, 1), 256>>>(Wo, woh, DOUT, DOUT);
    wa_kernel<<<DOUT / 8, 256>>>(Wo, a1_o, a2_o, wao1, wao2, DOUT, DOUT);
    fvec_kernel<1, DOUT, __half><<<M_ / 8, 256, 2 * DOUT * 4>>>(
        hmh, wao1, wao2, eu1b, ev1b, eu2b, ev2b);
    gemm_mma_kernel<<<dim3(M_ / 128, DOUT / 128, 1), 256, GEMM_SMEM>>>(
        hmh, woh, W2h, DOUT, DOUT);
    dstats_kernel<<<(B_ * N_) / 8, 256>>>(eu1b, ev1b, eu2b, ev2b, mask, dinb, 1);
    attn_mma_kernel<1, true><<<dim3(N_ / 64, B_), 512, ATTN_SMEM>>>(
        W2h, eu1b, ev1b, eu2b, ev2b, dinb, mask, nullptr, out);
}

// round 15
// speedup vs baseline: 2.9673x; 1.0332x over previous
#include <cuda_runtime.h>
#include <cuda_fp16.h>
#include <math.h>
#include <stdint.h>

#define B_  32
#define N_  512
#define DIN 768
#define DOUT 256
#define H_  8
#define M_  (B_ * N_)

// ---------------- device scratch ----------------
__device__ __half g_xh [(size_t)M_ * DIN];
__device__ __half g_w0h[(size_t)H_ * DOUT * DIN];
__device__ __half g_Whh[(size_t)H_ * M_ * DOUT];
__device__ uint32_t g_mask[(size_t)B_ * N_ * 16];
__device__ float  g_wa1[H_ * DIN];
__device__ float  g_wa2[H_ * DIN];
__device__ float  g_eu1[H_ * M_];
__device__ float  g_ev1[H_ * M_];
__device__ float  g_eu2[H_ * M_];
__device__ float  g_ev2[H_ * M_];
__device__ float  g_din[H_ * M_];
__device__ __half g_hmh[(size_t)M_ * DOUT];
__device__ __half g_woh[(size_t)DOUT * DOUT];
__device__ __half g_W2h[(size_t)M_ * DOUT];
__device__ float  g_wao1[DOUT];
__device__ float  g_wao2[DOUT];
__device__ float  g_eu1b[M_];
__device__ float  g_ev1b[M_];
__device__ float  g_eu2b[M_];
__device__ float  g_ev2b[M_];
__device__ float  g_dinb[M_];

// ---------------- PTX helpers ----------------
__device__ __forceinline__ uint32_t smem_u32(const void* p) {
    uint32_t a;
    asm("{ .reg .u64 t; cvta.to.shared.u64 t, %1; cvt.u32.u64 %0, t; }" : "=r"(a) : "l"(p));
    return a;
}
__device__ __forceinline__ void cp16(uint32_t d, const void* s) {
    asm volatile("cp.async.cg.shared.global [%0], [%1], 16;" :: "r"(d), "l"(s));
}
#define CP_COMMIT() asm volatile("cp.async.commit_group;")
#define CP_WAIT(n)  asm volatile("cp.async.wait_group %0;" :: "n"(n))

#define LDM_X4(r, addr) \
    asm volatile("ldmatrix.sync.aligned.m8n8.x4.shared.b16 {%0,%1,%2,%3}, [%4];" \
        : "=r"((r)[0]), "=r"((r)[1]), "=r"((r)[2]), "=r"((r)[3]) : "r"(addr))
#define LDM_X2(r, addr) \
    asm volatile("ldmatrix.sync.aligned.m8n8.x2.shared.b16 {%0,%1}, [%2];" \
        : "=r"((r)[0]), "=r"((r)[1]) : "r"(addr))
#define LDM_X2T(r, addr) \
    asm volatile("ldmatrix.sync.aligned.m8n8.x2.trans.shared.b16 {%0,%1}, [%2];" \
        : "=r"((r)[0]), "=r"((r)[1]) : "r"(addr))

__device__ __forceinline__ void mma_f16(float* c, const uint32_t* a, const uint32_t* b) {
    asm volatile("mma.sync.aligned.m16n8k16.row.col.f32.f16.f16.f32 "
        "{%0,%1,%2,%3}, {%4,%5,%6,%7}, {%8,%9}, {%0,%1,%2,%3};"
        : "+f"(c[0]), "+f"(c[1]), "+f"(c[2]), "+f"(c[3])
        : "r"(a[0]), "r"(a[1]), "r"(a[2]), "r"(a[3]), "r"(b[0]), "r"(b[1]));
}

// ---------------- conversion kernels ----------------
// W: [z][K][N] fp32 -> [z][N][K] fp16 (transpose, hi only)
__global__ __launch_bounds__(256) void whi_kernel(
    const float* __restrict__ W, __half* __restrict__ bh, int Kd, int Nd)
{
    int z = blockIdx.z;
    int i = blockIdx.x * 256 + threadIdx.x;
    if (i >= Kd * Nd) return;
    int n = i / Kd, k = i % Kd;
    bh[(size_t)z * Kd * Nd + i] =
        __float2half(W[(size_t)z * Kd * Nd + (size_t)k * Nd + n]);
}

// ---------------- pack adjacency ----------------
__global__ __launch_bounds__(256) void packadj_kernel(
    const int* __restrict__ adj, uint32_t* __restrict__ mask)
{
    int row  = (blockIdx.x * 256 + threadIdx.x) >> 5;
    int lane = threadIdx.x & 31;
    if (row >= B_ * N_) return;
    const int* ar = adj + (size_t)row * N_;
    #pragma unroll
    for (int q = 0; q < 16; ++q) {
        uint32_t w = __ballot_sync(0xffffffffu, ar[q * 32 + lane] > 0);
        if (lane == q) mask[row * 16 + q] = w;
    }
}

// ---------------- wa = W @ a (per head) ----------------
__global__ __launch_bounds__(256) void wa_kernel(
    const float* __restrict__ W, const float* __restrict__ a1,
    const float* __restrict__ a2, float* __restrict__ wa1,
    float* __restrict__ wa2, int Kd, int Nd)
{
    int warp = (blockIdx.x * 256 + threadIdx.x) >> 5;
    int lane = threadIdx.x & 31;
    int z = warp / Kd, k = warp % Kd;
    const float* row = W + ((size_t)z * Kd + k) * Nd;
    const float* a1z = a1 + z * Nd;
    const float* a2z = a2 + z * Nd;
    float s1 = 0.0f, s2 = 0.0f;
    for (int f = lane; f < Nd; f += 32) {
        float w = row[f];
        s1 = fmaf(w, a1z[f], s1);
        s2 = fmaf(w, a2z[f], s2);
    }
    #pragma unroll
    for (int off = 16; off; off >>= 1) {
        s1 += __shfl_xor_sync(0xffffffffu, s1, off);
        s2 += __shfl_xor_sync(0xffffffffu, s2, off);
    }
    if (lane == 0) { wa1[warp] = s1; wa2[warp] = s2; }
}

// ---------------- fvec: f1/f2 from X, emit factored exps (+ optional xh) ----
template<int NH, int K, typename T>
__global__ __launch_bounds__(256) void fvec_kernel(
    const T* __restrict__ X,
    const float* __restrict__ wa1, const float* __restrict__ wa2,
    float* __restrict__ eu1, float* __restrict__ ev1,
    float* __restrict__ eu2, float* __restrict__ ev2,
    __half* __restrict__ xh)
{
    extern __shared__ float swa[];
    float* swa1 = swa;
    float* swa2 = swa + NH * K;
    const int t = threadIdx.x, lane = t & 31, w = t >> 5;
    for (int i = t; i < NH * K; i += 256) { swa1[i] = wa1[i]; swa2[i] = wa2[i]; }
    __syncthreads();

    int r = blockIdx.x * 8 + w;
    float xv[K / 32];
    #pragma unroll
    for (int j = 0; j < K / 32; ++j)
        xv[j] = (float)X[(size_t)r * K + j * 32 + lane];

    if (xh) {
        #pragma unroll
        for (int j = 0; j < K / 32; ++j)
            xh[(size_t)r * K + j * 32 + lane] = __float2half(xv[j]);
    }

    float s1[NH], s2[NH];
    #pragma unroll
    for (int h = 0; h < NH; ++h) {
        float a = 0.0f, bsum = 0.0f;
        #pragma unroll
        for (int j = 0; j < K / 32; ++j) {
            int k = j * 32 + lane;
            a    = fmaf(xv[j], swa1[h * K + k], a);
            bsum = fmaf(xv[j], swa2[h * K + k], bsum);
        }
        #pragma unroll
        for (int off = 16; off; off >>= 1) {
            a    += __shfl_xor_sync(0xffffffffu, a, off);
            bsum += __shfl_xor_sync(0xffffffffu, bsum, off);
        }
        s1[h] = a; s2[h] = bsum;
    }
    if (lane < 2 * NH) {
        int h = lane >> 1;
        float s = (lane & 1) ? s2[h] : s1[h];
        float eu = __expf(s), ev = __expf(0.2f * s);
        size_t idx = (size_t)h * M_ + r;
        if (lane & 1) { eu2[idx] = eu; ev2[idx] = ev; }
        else          { eu1[idx] = eu; ev1[idx] = ev; }
    }
}

// ================= HMMA fp16 GEMM (1-term), 3-stage =================
#define GEMM_SMEM (3 * 20480)

__global__ __launch_bounds__(256, 2) void gemm_mma_kernel(
    const __half* __restrict__ Ah, const __half* __restrict__ Bh,
    __half* __restrict__ Chh, int K, int Nt)
{
    extern __shared__ __align__(128) char sm[];
    const uint32_t sb = smem_u32(sm);
    const int t = threadIdx.x, lane = t & 31, wid = t >> 5;
    const int m0 = blockIdx.x * 128, f0 = blockIdx.y * 128, z = blockIdx.z;
    const int warp_m = wid & 1, warp_n = wid >> 1;

    const __half* As_h = Ah + (size_t)m0 * K;
    const __half* Bs_h = Bh + (size_t)z * Nt * K + (size_t)f0 * K;
    __half* Ch = Chh + (size_t)z * M_ * Nt;

    float acc[4][4][4];
    #pragma unroll
    for (int a = 0; a < 4; ++a)
        #pragma unroll
        for (int b = 0; b < 4; ++b)
            #pragma unroll
            for (int c = 0; c < 4; ++c) acc[a][b][c] = 0.0f;

    const int row = t >> 1, half = t & 1;
    auto prefetch = [&](int c, int s) {
        const int kc = c * 32;
        const __half* srcs[2] = { As_h + kc, Bs_h + kc };
        #pragma unroll
        for (int tile = 0; tile < 2; ++tile) {
            uint32_t dst = sb + s * 20480 + tile * 10240 + row * 80 + half * 32;
            const __half* src = srcs[tile] + (size_t)row * K + half * 16;
            cp16(dst, src);
            cp16(dst + 16, src + 8);
        }
        CP_COMMIT();
    };

    const int NC = K >> 5;
    prefetch(0, 0);
    prefetch(1, 1);
    int st = 0;
    for (int c = 0; c < NC; ++c) {
        if (c + 2 < NC) {
            int s2 = st + 2; if (s2 >= 3) s2 -= 3;
            prefetch(c + 2, s2);
        } else CP_COMMIT();
        CP_WAIT(2);
        __syncthreads();

        const uint32_t bAh = sb + st * 20480;
        const uint32_t bBh = bAh + 10240;
        #pragma unroll
        for (int k16 = 0; k16 < 2; ++k16) {
            const int kc = k16 * 16;
            uint32_t ah[4][4];
            #pragma unroll
            for (int mf = 0; mf < 4; ++mf) {
                uint32_t off = (uint32_t)((warp_m * 64 + mf * 16 + (lane & 15)) * 80
                                          + (kc + ((lane >> 4) << 3)) * 2);
                LDM_X4(ah[mf], bAh + off);
            }
            #pragma unroll
            for (int nf = 0; nf < 4; ++nf) {
                uint32_t boff = (uint32_t)((warp_n * 32 + nf * 8 + (lane & 7)) * 80
                                           + (kc + (((lane >> 3) & 1) << 3)) * 2);
                uint32_t bh[2];
                LDM_X2(bh, bBh + boff);
                #pragma unroll
                for (int mf = 0; mf < 4; ++mf)
                    mma_f16(acc[mf][nf], ah[mf], bh);
            }
        }
        __syncthreads();
        if (++st == 3) st = 0;
    }

    #pragma unroll
    for (int mf = 0; mf < 4; ++mf)
        #pragma unroll
        for (int nf = 0; nf < 4; ++nf) {
            int r0 = m0 + warp_m * 64 + mf * 16 + (lane >> 2);
            int col = f0 + warp_n * 32 + nf * 8 + (lane & 3) * 2;
            #pragma unroll
            for (int hh = 0; hh < 2; ++hh) {
                int r = r0 + hh * 8;
                *(__half2*)(Ch + (size_t)r * Nt + col) = __halves2half2(
                    __float2half(acc[mf][nf][hh * 2]),
                    __float2half(acc[mf][nf][hh * 2 + 1]));
            }
        }
}

// ---------------- denominator ----------------
__global__ __launch_bounds__(256) void dstats_kernel(
    const float* __restrict__ eu1, const float* __restrict__ ev1,
    const float* __restrict__ eu2, const float* __restrict__ ev2,
    const uint32_t* __restrict__ mask, float* __restrict__ dinv, int NH)
{
    int row  = (blockIdx.x * 256 + threadIdx.x) >> 5;
    int lane = threadIdx.x & 31;
    if (row >= B_ * N_) return;
    int b = row >> 9;
    uint32_t myw = (lane < 16) ? mask[row * 16 + lane] : 0u;

    for (int h = 0; h < NH; ++h) {
        size_t hb = (size_t)h * B_ + b;
        size_t r  = hb * N_ + (row & (N_ - 1));
        float u1 = eu1[r], v1 = ev1[r];
        const float* euh = eu2 + hb * N_;
        const float* evh = ev2 + hb * N_;
        float s = 0.0f;
        #pragma unroll
        for (int q = 0; q < 16; ++q) {
            uint32_t w = __shfl_sync(0xffffffffu, myw, q);
            int m = q * 32 + lane;
            float tt = u1 * euh[m];
            float t2 = v1 * evh[m];
            float E = tt >= 1.0f ? tt : t2;
            s += ((w >> lane) & 1u) ? E : 0.0f;
        }
        #pragma unroll
        for (int off = 16; off; off >>= 1)
            s += __shfl_xor_sync(0xffffffffu, s, off);
        if (lane == 0) dinv[r] = s > 0.0f ? 1.0f / s : 0.0f;
    }
}

// ============ HMMA attention: on-the-fly P, m-chunk 64 (8 chunks/head) =====
// smem: sadj 4096 | seu 2048 | sev 2048 | su1/sv1/sinv 3*256 | pad -> 9216
//       Ps [2 st][64][72] half  = 18432  @ 9216   (row stride 144B)
//       Whs [2 st][64][264] half = 67584 @ 27648  (row stride 528B)
#define ATTN_SMEM (27648 + 67584)

template<int NHEADS, bool FINAL>
__global__ __launch_bounds__(512, 1) void attn_mma_kernel(
    const __half* __restrict__ Whh,
    const float* __restrict__ eu1, const float* __restrict__ ev1,
    const float* __restrict__ eu2, const float* __restrict__ ev2,
    const float* __restrict__ dinv, const uint32_t* __restrict__ gmask,
    __half* __restrict__ outh, float* __restrict__ outf)
{
    extern __shared__ __align__(128) char sm[];
    const uint32_t sb = smem_u32(sm);
    uint32_t* sadj = (uint32_t*)sm;
    float* seu  = (float*)(sm + 4096);
    float* sev  = (float*)(sm + 6144);
    float* su1  = (float*)(sm + 8192);
    float* sv1  = (float*)(sm + 8448);
    float* sinv = (float*)(sm + 8704);
    const uint32_t smP = sb + 9216;
    const uint32_t smW = sb + 27648;

    const int t = threadIdx.x, lane = t & 31, wid = t >> 5;
    const int n0 = blockIdx.x * 64;
    const int b  = blockIdx.y;
    const int warp_n = wid & 1, warp_f = wid >> 1;

    {
        int i0 = t;
        sadj[i0] = gmask[((size_t)b * N_ + n0 + (i0 >> 4)) * 16 + (i0 & 15)];
        int i1 = t + 512;
        sadj[i1] = gmask[((size_t)b * N_ + n0 + (i1 >> 4)) * 16 + (i1 & 15)];
    }

    const int pi  = t >> 3;          // 0..63 (n-local row)
    const int pk8 = (t & 7) * 8;     // 0..56 (m-local, 8 vals)
    const int wrow = t >> 3;         // 0..63
    const int wseg = t & 7;          // 0..7

    float sum[2][4][4];
    #pragma unroll
    for (int a = 0; a < 2; ++a)
        #pragma unroll
        for (int c = 0; c < 4; ++c)
            #pragma unroll
            for (int d = 0; d < 4; ++d) sum[a][c][d] = 0.0f;

    for (int h = 0; h < NHEADS; ++h) {
        const size_t hb = (size_t)h * B_ + b;
        const __half* Wsh = Whh + hb * (size_t)N_ * DOUT;

        __syncthreads();
        seu[t & 511] = eu2[hb * N_ + (t & 511)];
        sev[t & 511] = ev2[hb * N_ + (t & 511)];
        if (t < 64) {
            su1[t]  = eu1[hb * N_ + n0 + t];
            sv1[t]  = ev1[hb * N_ + n0 + t];
            sinv[t] = dinv[hb * N_ + n0 + t];
        }
        __syncthreads();

        float acc[2][4][4];
        #pragma unroll
        for (int a = 0; a < 2; ++a)
            #pragma unroll
            for (int c = 0; c < 4; ++c)
                #pragma unroll
                for (int d = 0; d < 4; ++d) acc[a][c][d] = 0.0f;

        auto computeP = [&](int c, int st) {
            const int m0 = c * 64;
            float u1 = su1[pi], v1 = sv1[pi], inv = sinv[pi];
            uint32_t w = sadj[pi * 16 + c * 2 + (pk8 >> 5)];
            const int bit0 = pk8 & 31;
            uint4 v;
            __half2* vh = (__half2*)&v;
            #pragma unroll
            for (int kk2 = 0; kk2 < 4; ++kk2) {
                float p0, p1;
                {
                    int kk = kk2 * 2;
                    int mm = m0 + pk8 + kk;
                    float tt = u1 * seu[mm];
                    float t2 = v1 * sev[mm];
                    float E  = tt >= 1.0f ? tt : t2;
                    p0 = ((w >> (bit0 + kk)) & 1u) ? E * inv : 0.0f;
                }
                {
                    int kk = kk2 * 2 + 1;
                    int mm = m0 + pk8 + kk;
                    float tt = u1 * seu[mm];
                    float t2 = v1 * sev[mm];
                    float E  = tt >= 1.0f ? tt : t2;
                    p1 = ((w >> (bit0 + kk)) & 1u) ? E * inv : 0.0f;
                }
                vh[kk2] = __halves2half2(__float2half(p0), __float2half(p1));
            }
            *(uint4*)(sm + 9216 + st * 9216 + pi * 144 + pk8 * 2) = v;
        };
        auto prefetchW = [&](int c, int st) {
            const int m0 = c * 64;
            const __half* src = Wsh + (size_t)(m0 + wrow) * DOUT;
            uint32_t dst = smW + st * 33792 + wrow * 528;
            #pragma unroll
            for (int j = 0; j < 4; ++j) {
                int s8 = wseg + j * 8;
                cp16(dst + s8 * 16, src + s8 * 8);
            }
            CP_COMMIT();
        };

        computeP(0, 0);
        prefetchW(0, 0);
        for (int c = 0; c < 8; ++c) {
            const int st = c & 1;
            if (c < 7) {
                prefetchW(c + 1, st ^ 1);
                computeP(c + 1, st ^ 1);
                CP_WAIT(1);
            } else CP_WAIT(0);
            __syncthreads();

            const uint32_t Phs = smP + st * 9216;
            const uint32_t Whs = smW + st * 33792;
            #pragma unroll
            for (int k16 = 0; k16 < 4; ++k16) {
                const int kc = k16 * 16;
                uint32_t ah[2][4];
                #pragma unroll
                for (int mf = 0; mf < 2; ++mf) {
                    uint32_t off = (uint32_t)((warp_n * 32 + mf * 16 + (lane & 15)) * 144
                                              + (kc + ((lane >> 4) << 3)) * 2);
                    LDM_X4(ah[mf], Phs + off);
                }
                #pragma unroll
                for (int nf = 0; nf < 4; ++nf) {
                    uint32_t woff = (uint32_t)((kc + (lane & 15)) * 528
                                               + (warp_f * 32 + nf * 8) * 2);
                    uint32_t bh[2];
                    LDM_X2T(bh, Whs + woff);
                    #pragma unroll
                    for (int mf = 0; mf < 2; ++mf)
                        mma_f16(acc[mf][nf], ah[mf], bh);
                }
            }
            __syncthreads();
        }

        if (FINAL) {
            #pragma unroll
            for (int a = 0; a < 2; ++a)
                #pragma unroll
                for (int c = 0; c < 4; ++c)
                    #pragma unroll
                    for (int d = 0; d < 4; ++d) sum[a][c][d] = acc[a][c][d];
        } else {
            #pragma unroll
            for (int a = 0; a < 2; ++a)
                #pragma unroll
                for (int c = 0; c < 4; ++c)
                    #pragma unroll
                    for (int d = 0; d < 4; ++d) {
                        float v = acc[a][c][d];
                        sum[a][c][d] += (v > 0.0f) ? v : expm1f(v);
                    }
        }
    }

    #pragma unroll
    for (int mf = 0; mf < 2; ++mf)
        #pragma unroll
        for (int nf = 0; nf < 4; ++nf) {
            int r0  = n0 + warp_n * 32 + mf * 16 + (lane >> 2);
            int col = warp_f * 32 + nf * 8 + (lane & 3) * 2;
            #pragma unroll
            for (int hh2 = 0; hh2 < 2; ++hh2) {
                int r = r0 + hh2 * 8;
                float c0 = sum[mf][nf][hh2 * 2], c1 = sum[mf][nf][hh2 * 2 + 1];
                if (FINAL) {
                    float2 v = { fmaxf(c0, 0.0f), fmaxf(c1, 0.0f) };
                    *(float2*)(outf + ((size_t)b * N_ + r) * DOUT + col) = v;
                } else {
                    c0 *= 0.125f; c1 *= 0.125f;
                    *(__half2*)(outh + ((size_t)b * N_ + r) * DOUT + col) =
                        __halves2half2(__float2half(c0), __float2half(c1));
                }
            }
        }
}

// ---------------- launch ----------------
extern "C" void kernel_launch(void* const* d_in, const int* in_sizes, int n_in,
                              void* d_out, int out_size)
{
    const float* x    = (const float*)d_in[0];
    const int*   adj  = (const int*)  d_in[1];
    const float* W0   = (const float*)d_in[2];
    const float* a1_0 = (const float*)d_in[3];
    const float* a2_0 = (const float*)d_in[4];
    const float* Wo   = (const float*)d_in[5];
    const float* a1_o = (const float*)d_in[6];
    const float* a2_o = (const float*)d_in[7];
    float* out = (float*)d_out;

    __half *xh, *w0h, *Whh, *hmh, *woh, *W2h;
    float *wa1, *wa2, *wao1, *wao2;
    float *eu1, *ev1, *eu2, *ev2, *din, *eu1b, *ev1b, *eu2b, *ev2b, *dinb;
    uint32_t* mask;
    cudaGetSymbolAddress((void**)&xh,  g_xh);
    cudaGetSymbolAddress((void**)&w0h, g_w0h);
    cudaGetSymbolAddress((void**)&Whh, g_Whh);
    cudaGetSymbolAddress((void**)&mask, g_mask);
    cudaGetSymbolAddress((void**)&wa1, g_wa1);
    cudaGetSymbolAddress((void**)&wa2, g_wa2);
    cudaGetSymbolAddress((void**)&eu1, g_eu1);
    cudaGetSymbolAddress((void**)&ev1, g_ev1);
    cudaGetSymbolAddress((void**)&eu2, g_eu2);
    cudaGetSymbolAddress((void**)&ev2, g_ev2);
    cudaGetSymbolAddress((void**)&din, g_din);
    cudaGetSymbolAddress((void**)&hmh, g_hmh);
    cudaGetSymbolAddress((void**)&woh, g_woh);
    cudaGetSymbolAddress((void**)&W2h, g_W2h);
    cudaGetSymbolAddress((void**)&wao1, g_wao1);
    cudaGetSymbolAddress((void**)&wao2, g_wao2);
    cudaGetSymbolAddress((void**)&eu1b, g_eu1b);
    cudaGetSymbolAddress((void**)&ev1b, g_ev1b);
    cudaGetSymbolAddress((void**)&eu2b, g_eu2b);
    cudaGetSymbolAddress((void**)&ev2b, g_ev2b);
    cudaGetSymbolAddress((void**)&dinb, g_dinb);

    cudaFuncSetAttribute(gemm_mma_kernel,
        cudaFuncAttributeMaxDynamicSharedMemorySize, GEMM_SMEM);
    cudaFuncSetAttribute(attn_mma_kernel<H_, false>,
        cudaFuncAttributeMaxDynamicSharedMemorySize, ATTN_SMEM);
    cudaFuncSetAttribute(attn_mma_kernel<1, true>,
        cudaFuncAttributeMaxDynamicSharedMemorySize, ATTN_SMEM);
    cudaFuncSetAttribute((const void*)fvec_kernel<H_, DIN, float>,
        cudaFuncAttributeMaxDynamicSharedMemorySize, 2 * H_ * DIN * 4);
    cudaFuncSetAttribute((const void*)fvec_kernel<1, DOUT, __half>,
        cudaFuncAttributeMaxDynamicSharedMemorySize, 2 * DOUT * 4);

    // ---- layer 1 ----
    packadj_kernel<<<(B_ * N_) / 8, 256>>>(adj, mask);
    whi_kernel<<<dim3((DIN * DOUT + 255) / 256, 1, H_), 256>>>(W0, w0h, DIN, DOUT);
    wa_kernel<<<(H_ * DIN) / 8, 256>>>(W0, a1_0, a2_0, wa1, wa2, DIN, DOUT);
    fvec_kernel<H_, DIN, float><<<M_ / 8, 256, 2 * H_ * DIN * 4>>>(
        x, wa1, wa2, eu1, ev1, eu2, ev2, xh);
    gemm_mma_kernel<<<dim3(M_ / 128, DOUT / 128, H_), 256, GEMM_SMEM>>>(
        xh, w0h, Whh, DIN, DOUT);
    dstats_kernel<<<(B_ * N_) / 8, 256>>>(eu1, ev1, eu2, ev2, mask, din, H_);
    attn_mma_kernel<H_, false><<<dim3(N_ / 64, B_), 512, ATTN_SMEM>>>(
        Whh, eu1, ev1, eu2, ev2, din, mask, hmh, nullptr);

    // ---- layer 2 ----
    whi_kernel<<<dim3((DOUT * DOUT + 255) / 256, 1, 1), 256>>>(Wo, woh, DOUT, DOUT);
    wa_kernel<<<DOUT / 8, 256>>>(Wo, a1_o, a2_o, wao1, wao2, DOUT, DOUT);
    fvec_kernel<1, DOUT, __half><<<M_ / 8, 256, 2 * DOUT * 4>>>(
        hmh, wao1, wao2, eu1b, ev1b, eu2b, ev2b, nullptr);
    gemm_mma_kernel<<<dim3(M_ / 128, DOUT / 128, 1), 256, GEMM_SMEM>>>(
        hmh, woh, W2h, DOUT, DOUT);
    dstats_kernel<<<(B_ * N_) / 8, 256>>>(eu1b, ev1b, eu2b, ev2b, mask, dinb, 1);
    attn_mma_kernel<1, true><<<dim3(N_ / 64, B_), 512, ATTN_SMEM>>>(
        W2h, eu1b, ev1b, eu2b, ev2b, dinb, mask, nullptr, out);
}

// round 16
// speedup vs baseline: 3.1310x; 1.0552x over previous
#include <cuda_runtime.h>
#include <cuda_fp16.h>
#include <math.h>
#include <stdint.h>

#define B_  32
#define N_  512
#define DIN 768
#define DOUT 256
#define H_  8
#define M_  (B_ * N_)

// ---------------- device scratch ----------------
__device__ __half g_xh [(size_t)M_ * DIN];
__device__ __half g_w0h[(size_t)H_ * DOUT * DIN];
__device__ __half g_Whh[(size_t)H_ * M_ * DOUT];
__device__ uint32_t g_mask[(size_t)B_ * N_ * 16];
__device__ float  g_wa1[H_ * DIN];
__device__ float  g_wa2[H_ * DIN];
__device__ float  g_eu1[H_ * M_];
__device__ float  g_ev1[H_ * M_];
__device__ float  g_eu2[H_ * M_];
__device__ float  g_ev2[H_ * M_];
__device__ float  g_din[H_ * M_];
__device__ __half g_hmh[(size_t)M_ * DOUT];
__device__ __half g_woh[(size_t)DOUT * DOUT];
__device__ __half g_W2h[(size_t)M_ * DOUT];
__device__ float  g_wao1[DOUT];
__device__ float  g_wao2[DOUT];
__device__ float  g_eu1b[M_];
__device__ float  g_ev1b[M_];
__device__ float  g_eu2b[M_];
__device__ float  g_ev2b[M_];
__device__ float  g_dinb[M_];

// ---------------- PTX helpers ----------------
__device__ __forceinline__ uint32_t smem_u32(const void* p) {
    uint32_t a;
    asm("{ .reg .u64 t; cvta.to.shared.u64 t, %1; cvt.u32.u64 %0, t; }" : "=r"(a) : "l"(p));
    return a;
}
__device__ __forceinline__ void cp16(uint32_t d, const void* s) {
    asm volatile("cp.async.cg.shared.global [%0], [%1], 16;" :: "r"(d), "l"(s));
}
#define CP_COMMIT() asm volatile("cp.async.commit_group;")
#define CP_WAIT(n)  asm volatile("cp.async.wait_group %0;" :: "n"(n))

#define LDM_X4(r, addr) \
    asm volatile("ldmatrix.sync.aligned.m8n8.x4.shared.b16 {%0,%1,%2,%3}, [%4];" \
        : "=r"((r)[0]), "=r"((r)[1]), "=r"((r)[2]), "=r"((r)[3]) : "r"(addr))
#define LDM_X2(r, addr) \
    asm volatile("ldmatrix.sync.aligned.m8n8.x2.shared.b16 {%0,%1}, [%2];" \
        : "=r"((r)[0]), "=r"((r)[1]) : "r"(addr))
#define LDM_X2T(r, addr) \
    asm volatile("ldmatrix.sync.aligned.m8n8.x2.trans.shared.b16 {%0,%1}, [%2];" \
        : "=r"((r)[0]), "=r"((r)[1]) : "r"(addr))

__device__ __forceinline__ void mma_f16(float* c, const uint32_t* a, const uint32_t* b) {
    asm volatile("mma.sync.aligned.m16n8k16.row.col.f32.f16.f16.f32 "
        "{%0,%1,%2,%3}, {%4,%5,%6,%7}, {%8,%9}, {%0,%1,%2,%3};"
        : "+f"(c[0]), "+f"(c[1]), "+f"(c[2]), "+f"(c[3])
        : "r"(a[0]), "r"(a[1]), "r"(a[2]), "r"(a[3]), "r"(b[0]), "r"(b[1]));
}

// ---------------- W transpose via 32x32 smem tile ----------------
// W: [z][Kd][Nd] fp32 -> bh: [z][Nd][Kd] fp16
__global__ __launch_bounds__(256) void whi_kernel(
    const float* __restrict__ W, __half* __restrict__ bh, int Kd, int Nd)
{
    __shared__ float tile[32][33];
    const int z = blockIdx.z;
    const int n0 = blockIdx.x * 32, k0 = blockIdx.y * 32;
    const int tx = threadIdx.x & 31, ty = threadIdx.x >> 5;
    const float* Wz = W + (size_t)z * Kd * Nd;
    __half* bz = bh + (size_t)z * Kd * Nd;
    #pragma unroll
    for (int i = 0; i < 4; ++i) {
        int k = ty + i * 8;
        tile[k][tx] = Wz[(size_t)(k0 + k) * Nd + n0 + tx];
    }
    __syncthreads();
    #pragma unroll
    for (int i = 0; i < 4; ++i) {
        int n = ty + i * 8;
        bz[(size_t)(n0 + n) * Kd + k0 + tx] = __float2half(tile[tx][n]);
    }
}

// ---------------- pack adjacency ----------------
__global__ __launch_bounds__(256) void packadj_kernel(
    const int* __restrict__ adj, uint32_t* __restrict__ mask)
{
    int row  = (blockIdx.x * 256 + threadIdx.x) >> 5;
    int lane = threadIdx.x & 31;
    if (row >= B_ * N_) return;
    const int* ar = adj + (size_t)row * N_;
    #pragma unroll
    for (int q = 0; q < 16; ++q) {
        uint32_t w = __ballot_sync(0xffffffffu, ar[q * 32 + lane] > 0);
        if (lane == q) mask[row * 16 + q] = w;
    }
}

// ---------------- wa = W @ a (per head) ----------------
__global__ __launch_bounds__(256) void wa_kernel(
    const float* __restrict__ W, const float* __restrict__ a1,
    const float* __restrict__ a2, float* __restrict__ wa1,
    float* __restrict__ wa2, int Kd, int Nd)
{
    int warp = (blockIdx.x * 256 + threadIdx.x) >> 5;
    int lane = threadIdx.x & 31;
    int z = warp / Kd, k = warp % Kd;
    const float* row = W + ((size_t)z * Kd + k) * Nd;
    const float* a1z = a1 + z * Nd;
    const float* a2z = a2 + z * Nd;
    float s1 = 0.0f, s2 = 0.0f;
    for (int f = lane; f < Nd; f += 32) {
        float w = row[f];
        s1 = fmaf(w, a1z[f], s1);
        s2 = fmaf(w, a2z[f], s2);
    }
    #pragma unroll
    for (int off = 16; off; off >>= 1) {
        s1 += __shfl_xor_sync(0xffffffffu, s1, off);
        s2 += __shfl_xor_sync(0xffffffffu, s2, off);
    }
    if (lane == 0) { wa1[warp] = s1; wa2[warp] = s2; }
}

// ---------------- fvec: 4 rows/warp, f1/f2 + factored exps (+ optional xh) --
template<int NH, int K, typename T>
__global__ __launch_bounds__(256) void fvec_kernel(
    const T* __restrict__ X,
    const float* __restrict__ wa1, const float* __restrict__ wa2,
    float* __restrict__ eu1, float* __restrict__ ev1,
    float* __restrict__ eu2, float* __restrict__ ev2,
    __half* __restrict__ xh)
{
    extern __shared__ float swa[];
    float* swa1 = swa;
    float* swa2 = swa + NH * K;
    const int t = threadIdx.x, lane = t & 31, w = t >> 5;
    for (int i = t; i < NH * K; i += 256) { swa1[i] = wa1[i]; swa2[i] = wa2[i]; }
    __syncthreads();

    const int rbase = blockIdx.x * 32 + w * 4;
    float xv[4][K / 32];
    #pragma unroll
    for (int r = 0; r < 4; ++r)
        #pragma unroll
        for (int j = 0; j < K / 32; ++j)
            xv[r][j] = (float)X[(size_t)(rbase + r) * K + j * 32 + lane];

    if (xh) {
        #pragma unroll
        for (int r = 0; r < 4; ++r)
            #pragma unroll
            for (int j = 0; j < K / 32; ++j)
                xh[(size_t)(rbase + r) * K + j * 32 + lane] = __float2half(xv[r][j]);
    }

    #pragma unroll
    for (int h = 0; h < NH; ++h) {
        float a[4] = {0, 0, 0, 0}, bs[4] = {0, 0, 0, 0};
        #pragma unroll
        for (int j = 0; j < K / 32; ++j) {
            float w1 = swa1[h * K + j * 32 + lane];
            float w2 = swa2[h * K + j * 32 + lane];
            #pragma unroll
            for (int r = 0; r < 4; ++r) {
                a[r]  = fmaf(xv[r][j], w1, a[r]);
                bs[r] = fmaf(xv[r][j], w2, bs[r]);
            }
        }
        #pragma unroll
        for (int off = 16; off; off >>= 1)
            #pragma unroll
            for (int r = 0; r < 4; ++r) {
                a[r]  += __shfl_xor_sync(0xffffffffu, a[r], off);
                bs[r] += __shfl_xor_sync(0xffffffffu, bs[r], off);
            }
        if (lane < 8) {
            int r = lane >> 1;
            float s = (lane & 1) ? bs[r] : a[r];
            float eu = __expf(s), ev = __expf(0.2f * s);
            size_t idx = (size_t)h * M_ + rbase + r;
            if (lane & 1) { eu2[idx] = eu; ev2[idx] = ev; }
            else          { eu1[idx] = eu; ev1[idx] = ev; }
        }
    }
}

// ================= HMMA fp16 GEMM (1-term), 3-stage =================
#define GEMM_SMEM (3 * 20480)

__global__ __launch_bounds__(256, 2) void gemm_mma_kernel(
    const __half* __restrict__ Ah, const __half* __restrict__ Bh,
    __half* __restrict__ Chh, int K, int Nt)
{
    extern __shared__ __align__(128) char sm[];
    const uint32_t sb = smem_u32(sm);
    const int t = threadIdx.x, lane = t & 31, wid = t >> 5;
    const int m0 = blockIdx.x * 128, f0 = blockIdx.y * 128, z = blockIdx.z;
    const int warp_m = wid & 1, warp_n = wid >> 1;

    const __half* As_h = Ah + (size_t)m0 * K;
    const __half* Bs_h = Bh + (size_t)z * Nt * K + (size_t)f0 * K;
    __half* Ch = Chh + (size_t)z * M_ * Nt;

    float acc[4][4][4];
    #pragma unroll
    for (int a = 0; a < 4; ++a)
        #pragma unroll
        for (int b = 0; b < 4; ++b)
            #pragma unroll
            for (int c = 0; c < 4; ++c) acc[a][b][c] = 0.0f;

    const int row = t >> 1, half = t & 1;
    auto prefetch = [&](int c, int s) {
        const int kc = c * 32;
        const __half* srcs[2] = { As_h + kc, Bs_h + kc };
        #pragma unroll
        for (int tile = 0; tile < 2; ++tile) {
            uint32_t dst = sb + s * 20480 + tile * 10240 + row * 80 + half * 32;
            const __half* src = srcs[tile] + (size_t)row * K + half * 16;
            cp16(dst, src);
            cp16(dst + 16, src + 8);
        }
        CP_COMMIT();
    };

    const int NC = K >> 5;
    prefetch(0, 0);
    prefetch(1, 1);
    int st = 0;
    for (int c = 0; c < NC; ++c) {
        if (c + 2 < NC) {
            int s2 = st + 2; if (s2 >= 3) s2 -= 3;
            prefetch(c + 2, s2);
        } else CP_COMMIT();
        CP_WAIT(2);
        __syncthreads();

        const uint32_t bAh = sb + st * 20480;
        const uint32_t bBh = bAh + 10240;
        #pragma unroll
        for (int k16 = 0; k16 < 2; ++k16) {
            const int kc = k16 * 16;
            uint32_t ah[4][4];
            #pragma unroll
            for (int mf = 0; mf < 4; ++mf) {
                uint32_t off = (uint32_t)((warp_m * 64 + mf * 16 + (lane & 15)) * 80
                                          + (kc + ((lane >> 4) << 3)) * 2);
                LDM_X4(ah[mf], bAh + off);
            }
            #pragma unroll
            for (int nf = 0; nf < 4; ++nf) {
                uint32_t boff = (uint32_t)((warp_n * 32 + nf * 8 + (lane & 7)) * 80
                                           + (kc + (((lane >> 3) & 1) << 3)) * 2);
                uint32_t bh[2];
                LDM_X2(bh, bBh + boff);
                #pragma unroll
                for (int mf = 0; mf < 4; ++mf)
                    mma_f16(acc[mf][nf], ah[mf], bh);
            }
        }
        __syncthreads();
        if (++st == 3) st = 0;
    }

    #pragma unroll
    for (int mf = 0; mf < 4; ++mf)
        #pragma unroll
        for (int nf = 0; nf < 4; ++nf) {
            int r0 = m0 + warp_m * 64 + mf * 16 + (lane >> 2);
            int col = f0 + warp_n * 32 + nf * 8 + (lane & 3) * 2;
            #pragma unroll
            for (int hh = 0; hh < 2; ++hh) {
                int r = r0 + hh * 8;
                *(__half2*)(Ch + (size_t)r * Nt + col) = __halves2half2(
                    __float2half(acc[mf][nf][hh * 2]),
                    __float2half(acc[mf][nf][hh * 2 + 1]));
            }
        }
}

// ---------------- denominator ----------------
__global__ __launch_bounds__(256) void dstats_kernel(
    const float* __restrict__ eu1, const float* __restrict__ ev1,
    const float* __restrict__ eu2, const float* __restrict__ ev2,
    const uint32_t* __restrict__ mask, float* __restrict__ dinv, int NH)
{
    int row  = (blockIdx.x * 256 + threadIdx.x) >> 5;
    int lane = threadIdx.x & 31;
    if (row >= B_ * N_) return;
    int b = row >> 9;
    uint32_t myw = (lane < 16) ? mask[row * 16 + lane] : 0u;

    for (int h = 0; h < NH; ++h) {
        size_t hb = (size_t)h * B_ + b;
        size_t r  = hb * N_ + (row & (N_ - 1));
        float u1 = eu1[r], v1 = ev1[r];
        const float* euh = eu2 + hb * N_;
        const float* evh = ev2 + hb * N_;
        float s = 0.0f;
        #pragma unroll
        for (int q = 0; q < 16; ++q) {
            uint32_t w = __shfl_sync(0xffffffffu, myw, q);
            int m = q * 32 + lane;
            float tt = u1 * euh[m];
            float t2 = v1 * evh[m];
            float E = tt >= 1.0f ? tt : t2;
            s += ((w >> lane) & 1u) ? E : 0.0f;
        }
        #pragma unroll
        for (int off = 16; off; off >>= 1)
            s += __shfl_xor_sync(0xffffffffu, s, off);
        if (lane == 0) dinv[r] = s > 0.0f ? 1.0f / s : 0.0f;
    }
}

// ============ HMMA attention: on-the-fly P, m-chunk 64 (8 chunks/head) =====
#define ATTN_SMEM (27648 + 67584)

template<int NHEADS, bool FINAL>
__global__ __launch_bounds__(512, 1) void attn_mma_kernel(
    const __half* __restrict__ Whh,
    const float* __restrict__ eu1, const float* __restrict__ ev1,
    const float* __restrict__ eu2, const float* __restrict__ ev2,
    const float* __restrict__ dinv, const uint32_t* __restrict__ gmask,
    __half* __restrict__ outh, float* __restrict__ outf)
{
    extern __shared__ __align__(128) char sm[];
    const uint32_t sb = smem_u32(sm);
    uint32_t* sadj = (uint32_t*)sm;
    float* seu  = (float*)(sm + 4096);
    float* sev  = (float*)(sm + 6144);
    float* su1  = (float*)(sm + 8192);
    float* sv1  = (float*)(sm + 8448);
    float* sinv = (float*)(sm + 8704);
    const uint32_t smP = sb + 9216;
    const uint32_t smW = sb + 27648;

    const int t = threadIdx.x, lane = t & 31, wid = t >> 5;
    const int n0 = blockIdx.x * 64;
    const int b  = blockIdx.y;
    const int warp_n = wid & 1, warp_f = wid >> 1;

    {
        int i0 = t;
        sadj[i0] = gmask[((size_t)b * N_ + n0 + (i0 >> 4)) * 16 + (i0 & 15)];
        int i1 = t + 512;
        sadj[i1] = gmask[((size_t)b * N_ + n0 + (i1 >> 4)) * 16 + (i1 & 15)];
    }

    const int pi  = t >> 3;
    const int pk8 = (t & 7) * 8;
    const int wrow = t >> 3;
    const int wseg = t & 7;

    float sum[2][4][4];
    #pragma unroll
    for (int a = 0; a < 2; ++a)
        #pragma unroll
        for (int c = 0; c < 4; ++c)
            #pragma unroll
            for (int d = 0; d < 4; ++d) sum[a][c][d] = 0.0f;

    for (int h = 0; h < NHEADS; ++h) {
        const size_t hb = (size_t)h * B_ + b;
        const __half* Wsh = Whh + hb * (size_t)N_ * DOUT;

        __syncthreads();
        seu[t & 511] = eu2[hb * N_ + (t & 511)];
        sev[t & 511] = ev2[hb * N_ + (t & 511)];
        if (t < 64) {
            su1[t]  = eu1[hb * N_ + n0 + t];
            sv1[t]  = ev1[hb * N_ + n0 + t];
            sinv[t] = dinv[hb * N_ + n0 + t];
        }
        __syncthreads();

        float acc[2][4][4];
        #pragma unroll
        for (int a = 0; a < 2; ++a)
            #pragma unroll
            for (int c = 0; c < 4; ++c)
                #pragma unroll
                for (int d = 0; d < 4; ++d) acc[a][c][d] = 0.0f;

        auto computeP = [&](int c, int st) {
            const int m0 = c * 64;
            float u1 = su1[pi], v1 = sv1[pi], inv = sinv[pi];
            uint32_t w = sadj[pi * 16 + c * 2 + (pk8 >> 5)];
            const int bit0 = pk8 & 31;
            uint4 v;
            __half2* vh = (__half2*)&v;
            #pragma unroll
            for (int kk2 = 0; kk2 < 4; ++kk2) {
                float p0, p1;
                {
                    int kk = kk2 * 2;
                    int mm = m0 + pk8 + kk;
                    float tt = u1 * seu[mm];
                    float t2 = v1 * sev[mm];
                    float E  = tt >= 1.0f ? tt : t2;
                    p0 = ((w >> (bit0 + kk)) & 1u) ? E * inv : 0.0f;
                }
                {
                    int kk = kk2 * 2 + 1;
                    int mm = m0 + pk8 + kk;
                    float tt = u1 * seu[mm];
                    float t2 = v1 * sev[mm];
                    float E  = tt >= 1.0f ? tt : t2;
                    p1 = ((w >> (bit0 + kk)) & 1u) ? E * inv : 0.0f;
                }
                vh[kk2] = __halves2half2(__float2half(p0), __float2half(p1));
            }
            *(uint4*)(sm + 9216 + st * 9216 + pi * 144 + pk8 * 2) = v;
        };
        auto prefetchW = [&](int c, int st) {
            const int m0 = c * 64;
            const __half* src = Wsh + (size_t)(m0 + wrow) * DOUT;
            uint32_t dst = smW + st * 33792 + wrow * 528;
            #pragma unroll
            for (int j = 0; j < 4; ++j) {
                int s8 = wseg + j * 8;
                cp16(dst + s8 * 16, src + s8 * 8);
            }
            CP_COMMIT();
        };

        computeP(0, 0);
        prefetchW(0, 0);
        for (int c = 0; c < 8; ++c) {
            const int st = c & 1;
            if (c < 7) {
                prefetchW(c + 1, st ^ 1);
                computeP(c + 1, st ^ 1);
                CP_WAIT(1);
            } else CP_WAIT(0);
            __syncthreads();

            const uint32_t Phs = smP + st * 9216;
            const uint32_t Whs = smW + st * 33792;
            #pragma unroll
            for (int k16 = 0; k16 < 4; ++k16) {
                const int kc = k16 * 16;
                uint32_t ah[2][4];
                #pragma unroll
                for (int mf = 0; mf < 2; ++mf) {
                    uint32_t off = (uint32_t)((warp_n * 32 + mf * 16 + (lane & 15)) * 144
                                              + (kc + ((lane >> 4) << 3)) * 2);
                    LDM_X4(ah[mf], Phs + off);
                }
                #pragma unroll
                for (int nf = 0; nf < 4; ++nf) {
                    uint32_t woff = (uint32_t)((kc + (lane & 15)) * 528
                                               + (warp_f * 32 + nf * 8) * 2);
                    uint32_t bh[2];
                    LDM_X2T(bh, Whs + woff);
                    #pragma unroll
                    for (int mf = 0; mf < 2; ++mf)
                        mma_f16(acc[mf][nf], ah[mf], bh);
                }
            }
            __syncthreads();
        }

        if (FINAL) {
            #pragma unroll
            for (int a = 0; a < 2; ++a)
                #pragma unroll
                for (int c = 0; c < 4; ++c)
                    #pragma unroll
                    for (int d = 0; d < 4; ++d) sum[a][c][d] = acc[a][c][d];
        } else {
            #pragma unroll
            for (int a = 0; a < 2; ++a)
                #pragma unroll
                for (int c = 0; c < 4; ++c)
                    #pragma unroll
                    for (int d = 0; d < 4; ++d) {
                        float v = acc[a][c][d];
                        sum[a][c][d] += (v > 0.0f) ? v : expm1f(v);
                    }
        }
    }

    #pragma unroll
    for (int mf = 0; mf < 2; ++mf)
        #pragma unroll
        for (int nf = 0; nf < 4; ++nf) {
            int r0  = n0 + warp_n * 32 + mf * 16 + (lane >> 2);
            int col = warp_f * 32 + nf * 8 + (lane & 3) * 2;
            #pragma unroll
            for (int hh2 = 0; hh2 < 2; ++hh2) {
                int r = r0 + hh2 * 8;
                float c0 = sum[mf][nf][hh2 * 2], c1 = sum[mf][nf][hh2 * 2 + 1];
                if (FINAL) {
                    float2 v = { fmaxf(c0, 0.0f), fmaxf(c1, 0.0f) };
                    *(float2*)(outf + ((size_t)b * N_ + r) * DOUT + col) = v;
                } else {
                    c0 *= 0.125f; c1 *= 0.125f;
                    *(__half2*)(outh + ((size_t)b * N_ + r) * DOUT + col) =
                        __halves2half2(__float2half(c0), __float2half(c1));
                }
            }
        }
}

// ---------------- launch ----------------
extern "C" void kernel_launch(void* const* d_in, const int* in_sizes, int n_in,
                              void* d_out, int out_size)
{
    const float* x    = (const float*)d_in[0];
    const int*   adj  = (const int*)  d_in[1];
    const float* W0   = (const float*)d_in[2];
    const float* a1_0 = (const float*)d_in[3];
    const float* a2_0 = (const float*)d_in[4];
    const float* Wo   = (const float*)d_in[5];
    const float* a1_o = (const float*)d_in[6];
    const float* a2_o = (const float*)d_in[7];
    float* out = (float*)d_out;

    __half *xh, *w0h, *Whh, *hmh, *woh, *W2h;
    float *wa1, *wa2, *wao1, *wao2;
    float *eu1, *ev1, *eu2, *ev2, *din, *eu1b, *ev1b, *eu2b, *ev2b, *dinb;
    uint32_t* mask;
    cudaGetSymbolAddress((void**)&xh,  g_xh);
    cudaGetSymbolAddress((void**)&w0h, g_w0h);
    cudaGetSymbolAddress((void**)&Whh, g_Whh);
    cudaGetSymbolAddress((void**)&mask, g_mask);
    cudaGetSymbolAddress((void**)&wa1, g_wa1);
    cudaGetSymbolAddress((void**)&wa2, g_wa2);
    cudaGetSymbolAddress((void**)&eu1, g_eu1);
    cudaGetSymbolAddress((void**)&ev1, g_ev1);
    cudaGetSymbolAddress((void**)&eu2, g_eu2);
    cudaGetSymbolAddress((void**)&ev2, g_ev2);
    cudaGetSymbolAddress((void**)&din, g_din);
    cudaGetSymbolAddress((void**)&hmh, g_hmh);
    cudaGetSymbolAddress((void**)&woh, g_woh);
    cudaGetSymbolAddress((void**)&W2h, g_W2h);
    cudaGetSymbolAddress((void**)&wao1, g_wao1);
    cudaGetSymbolAddress((void**)&wao2, g_wao2);
    cudaGetSymbolAddress((void**)&eu1b, g_eu1b);
    cudaGetSymbolAddress((void**)&ev1b, g_ev1b);
    cudaGetSymbolAddress((void**)&eu2b, g_eu2b);
    cudaGetSymbolAddress((void**)&ev2b, g_ev2b);
    cudaGetSymbolAddress((void**)&dinb, g_dinb);

    cudaFuncSetAttribute(gemm_mma_kernel,
        cudaFuncAttributeMaxDynamicSharedMemorySize, GEMM_SMEM);
    cudaFuncSetAttribute(attn_mma_kernel<H_, false>,
        cudaFuncAttributeMaxDynamicSharedMemorySize, ATTN_SMEM);
    cudaFuncSetAttribute(attn_mma_kernel<1, true>,
        cudaFuncAttributeMaxDynamicSharedMemorySize, ATTN_SMEM);
    cudaFuncSetAttribute((const void*)fvec_kernel<H_, DIN, float>,
        cudaFuncAttributeMaxDynamicSharedMemorySize, 2 * H_ * DIN * 4);
    cudaFuncSetAttribute((const void*)fvec_kernel<1, DOUT, __half>,
        cudaFuncAttributeMaxDynamicSharedMemorySize, 2 * DOUT * 4);

    // ---- layer 1 ----
    packadj_kernel<<<(B_ * N_) / 8, 256>>>(adj, mask);
    whi_kernel<<<dim3(DOUT / 32, DIN / 32, H_), 256>>>(W0, w0h, DIN, DOUT);
    wa_kernel<<<(H_ * DIN) / 8, 256>>>(W0, a1_0, a2_0, wa1, wa2, DIN, DOUT);
    fvec_kernel<H_, DIN, float><<<M_ / 32, 256, 2 * H_ * DIN * 4>>>(
        x, wa1, wa2, eu1, ev1, eu2, ev2, xh);
    gemm_mma_kernel<<<dim3(M_ / 128, DOUT / 128, H_), 256, GEMM_SMEM>>>(
        xh, w0h, Whh, DIN, DOUT);
    dstats_kernel<<<(B_ * N_) / 8, 256>>>(eu1, ev1, eu2, ev2, mask, din, H_);
    attn_mma_kernel<H_, false><<<dim3(N_ / 64, B_), 512, ATTN_SMEM>>>(
        Whh, eu1, ev1, eu2, ev2, din, mask, hmh, nullptr);

    // ---- layer 2 ----
    whi_kernel<<<dim3(DOUT / 32, DOUT / 32, 1), 256>>>(Wo, woh, DOUT, DOUT);
    wa_kernel<<<DOUT / 8, 256>>>(Wo, a1_o, a2_o, wao1, wao2, DOUT, DOUT);
    fvec_kernel<1, DOUT, __half><<<M_ / 32, 256, 2 * DOUT * 4>>>(
        hmh, wao1, wao2, eu1b, ev1b, eu2b, ev2b, nullptr);
    gemm_mma_kernel<<<dim3(M_ / 128, DOUT / 128, 1), 256, GEMM_SMEM>>>(
        hmh, woh, W2h, DOUT, DOUT);
    dstats_kernel<<<(B_ * N_) / 8, 256>>>(eu1b, ev1b, eu2b, ev2b, mask, dinb, 1);
    attn_mma_kernel<1, true><<<dim3(N_ / 64, B_), 512, ATTN_SMEM>>>(
        W2h, eu1b, ev1b, eu2b, ev2b, dinb, mask, nullptr, out);
}